// round 9
// baseline (speedup 1.0000x reference)
#include <cuda_runtime.h>
#include <cuda_fp16.h>
#include <cstdint>

#define N_NODES 50000
#define MPAD    50048
#define E_EDGES 1600000
#define HDIM    256
#define NBLK    196

typedef unsigned short u16;

// ---------------------------------------------------------------------------
// Static device scratch
// ---------------------------------------------------------------------------
__device__ int   g_degi[N_NODES];
__device__ int   g_cnt[N_NODES];
__device__ int   g_rowstart[N_NODES];
__device__ int   g_cursor[N_NODES];
__device__ float g_dis[N_NODES];
__device__ int   g_csr_src[E_EDGES];
__device__ float g_csr_w[E_EDGES];
__device__ int   g_bsum[256];
__device__ int   g_boff[256];

__device__ float g_h3[(size_t)MPAD * HDIM];

// fp16 activation pairs
__device__ u16 g_xhi[(size_t)MPAD * HDIM];
__device__ u16 g_xlo[(size_t)MPAD * HDIM];
__device__ u16 g_h1hi[(size_t)MPAD * HDIM];
__device__ u16 g_h1lo[(size_t)MPAD * HDIM];
__device__ u16 g_h2hi[(size_t)MPAD * HDIM];
__device__ u16 g_h2lo[(size_t)MPAD * HDIM];
__device__ u16 g_aghi[(size_t)MPAD * HDIM];
__device__ u16 g_aglo[(size_t)MPAD * HDIM];
__device__ u16 g_o1hi[(size_t)MPAD * HDIM];
__device__ u16 g_o1lo[(size_t)MPAD * HDIM];
__device__ u16 g_o2hi[(size_t)MPAD * HDIM];
__device__ u16 g_o2lo[(size_t)MPAD * HDIM];

// fp16 hi/lo weights: W1,W2,W3 (256 cols) + concat conv weights (512 cols)
__device__ u16 g_whi[3 * HDIM * HDIM];
__device__ u16 g_wlo[3 * HDIM * HDIM];
__device__ u16 g_wc1hi[HDIM * 512];
__device__ u16 g_wc1lo[HDIM * 512];
__device__ u16 g_wc2hi[HDIM * 512];
__device__ u16 g_wc2lo[HDIM * 512];

// ---------------------------------------------------------------------------
// helpers
// ---------------------------------------------------------------------------
__device__ __forceinline__ uint32_t pack_f16x2(float lo, float hi) {
    __half2 h = __floats2half2_rn(lo, hi);
    return *reinterpret_cast<uint32_t*>(&h);
}

__device__ __forceinline__ float2 f16x2_to_f2(uint32_t u) {
    __half2 h = *reinterpret_cast<__half2*>(&u);
    return __half22float2(h);
}

__device__ __forceinline__ void ldsm_x4(uint32_t& r0, uint32_t& r1,
                                        uint32_t& r2, uint32_t& r3, uint32_t addr) {
    asm volatile("ldmatrix.sync.aligned.m8n8.x4.shared.b16 {%0,%1,%2,%3}, [%4];"
                 : "=r"(r0), "=r"(r1), "=r"(r2), "=r"(r3) : "r"(addr));
}

__device__ __forceinline__ void mma_f16(float c[4], const uint32_t a[4],
                                        const uint32_t b[2]) {
    asm volatile(
        "mma.sync.aligned.m16n8k16.row.col.f32.f16.f16.f32 "
        "{%0,%1,%2,%3}, {%4,%5,%6,%7}, {%8,%9}, {%0,%1,%2,%3};"
        : "+f"(c[0]), "+f"(c[1]), "+f"(c[2]), "+f"(c[3])
        : "r"(a[0]), "r"(a[1]), "r"(a[2]), "r"(a[3]), "r"(b[0]), "r"(b[1]));
}

#define CP16(sm, gp) \
    asm volatile("cp.async.cg.shared.global [%0], [%1], 16;" :: "r"(sm), "l"(gp))
#define CPCOMMIT() asm volatile("cp.async.commit_group;")
#define CPWAIT0()  asm volatile("cp.async.wait_group 0;")

// ---------------------------------------------------------------------------
// splits
// ---------------------------------------------------------------------------
__global__ void split_kernel(const float* __restrict__ in, u16* __restrict__ hi,
                             u16* __restrict__ lo, int n4)
{
    int i = blockIdx.x * blockDim.x + threadIdx.x;
    if (i >= n4) return;
    float4 v = ((const float4*)in)[i];
    float hx = __half2float(__float2half_rn(v.x));
    float hy = __half2float(__float2half_rn(v.y));
    float hz = __half2float(__float2half_rn(v.z));
    float hw = __half2float(__float2half_rn(v.w));
    uint2 h = make_uint2(pack_f16x2(v.x, v.y), pack_f16x2(v.z, v.w));
    uint2 l = make_uint2(pack_f16x2(v.x - hx, v.y - hy),
                         pack_f16x2(v.z - hz, v.w - hw));
    ((uint2*)hi)[i] = h;
    ((uint2*)lo)[i] = l;
}

// hi/lo split into 512-col concat layout
__global__ void split_w512_kernel(const float* __restrict__ in, u16* __restrict__ hi,
                                  u16* __restrict__ lo, int colofs)
{
    int i = blockIdx.x * blockDim.x + threadIdx.x;
    if (i >= HDIM * HDIM / 4) return;
    int row = i >> 6;
    int col = (i & 63) * 4;
    float4 v = ((const float4*)in)[i];
    float hx = __half2float(__float2half_rn(v.x));
    float hy = __half2float(__float2half_rn(v.y));
    float hz = __half2float(__float2half_rn(v.z));
    float hw = __half2float(__float2half_rn(v.w));
    uint2 h = make_uint2(pack_f16x2(v.x, v.y), pack_f16x2(v.z, v.w));
    uint2 l = make_uint2(pack_f16x2(v.x - hx, v.y - hy),
                         pack_f16x2(v.z - hz, v.w - hw));
    size_t o = (size_t)row * 512 + colofs + col;
    *(uint2*)(hi + o) = h;
    *(uint2*)(lo + o) = l;
}

// ---------------------------------------------------------------------------
// GEMM: C[MPAD, colBase:+64] = (Ahi+Alo) @ (Whi+Wlo)[colBase:+64]^T
// 3-pass exact fp16 split (drops only a_lo*w_lo ~2^-22).
// Tile 128x64x32, 256 thr, warp tile 32x32, 3 CTAs/SM, 2-stage cp.async.
// ---------------------------------------------------------------------------
#define BM   128
#define KS   40
#define STG  30720
#define OA_HI 0
#define OA_LO 10240
#define OB_HI 20480
#define OB_LO 25600

template <int KCHUNKS, bool RELU, bool HAS_BIAS, bool OUTF32>
__global__ __launch_bounds__(256, 3)
void gemm_mma_kernel(const u16* __restrict__ Ahi, const u16* __restrict__ Alo,
                     const u16* __restrict__ A2hi, const u16* __restrict__ A2lo,
                     const u16* __restrict__ Whi, const u16* __restrict__ Wlo,
                     const float* __restrict__ bias,
                     float* __restrict__ C, u16* __restrict__ Chi,
                     u16* __restrict__ Clo)
{
    extern __shared__ char smem[];
    const uint32_t sb = (uint32_t)__cvta_generic_to_shared(smem);
    const int tid  = threadIdx.x;
    const int lane = tid & 31;
    const int wid  = tid >> 5;
    const int wm   = (wid & 3) * 32;    // warp M offset
    const int wn   = (wid >> 2) * 32;   // warp N offset (0/32)
    const int rowBase = blockIdx.x * BM;
    const int colBase = blockIdx.y * 64;
    const int KTOT = KCHUNKS * 32;

    float acc[2][4][4];
#pragma unroll
    for (int mi = 0; mi < 2; mi++)
#pragma unroll
        for (int ni = 0; ni < 4; ni++)
#pragma unroll
            for (int j = 0; j < 4; j++) acc[mi][ni][j] = 0.0f;

    const int aRow = wm + (lane & 15);
    const int aColSel = (lane >> 4) * 8;
    const int bRow = wn + lane;

    auto load_chunk = [&](int c, int s) {
        uint32_t base = sb + (uint32_t)s * STG;
        const u16* pah = (c < 8) ? Ahi : A2hi;
        const u16* pal = (c < 8) ? Alo : A2lo;
        int ko = (c & 7) * 32;
        int k0 = c * 32;
#pragma unroll
        for (int i = 0; i < 2; i++) {
            int f   = tid + i * 256;
            int row = f >> 2;
            int c8  = (f & 3) * 8;
            uint32_t so = (uint32_t)(row * 80 + c8 * 2);
            CP16(base + OA_HI + so, pah + (size_t)(rowBase + row) * 256 + ko + c8);
            CP16(base + OA_LO + so, pal + (size_t)(rowBase + row) * 256 + ko + c8);
        }
        {
            int row = tid >> 2;          // 0..63
            int c8  = (tid & 3) * 8;
            uint32_t so = (uint32_t)(row * 80 + c8 * 2);
            CP16(base + OB_HI + so, Whi + (size_t)(colBase + row) * KTOT + k0 + c8);
            CP16(base + OB_LO + so, Wlo + (size_t)(colBase + row) * KTOT + k0 + c8);
        }
    };

    load_chunk(0, 0);
    CPCOMMIT();

#pragma unroll 1
    for (int c = 0; c < KCHUNKS; ++c) {
        const int s = c & 1;
        CPWAIT0();
        __syncthreads();
        if (c + 1 < KCHUNKS) { load_chunk(c + 1, s ^ 1); CPCOMMIT(); }

        const uint32_t stgBase = sb + (uint32_t)s * STG;
#pragma unroll
        for (int kk = 0; kk < 32; kk += 16) {
            uint32_t ah[2][4], al[2][4];
#pragma unroll
            for (int mi = 0; mi < 2; mi++) {
                uint32_t ao = (uint32_t)(((aRow + mi * 16) * KS + kk + aColSel) * 2);
                ldsm_x4(ah[mi][0], ah[mi][1], ah[mi][2], ah[mi][3],
                        stgBase + OA_HI + ao);
                ldsm_x4(al[mi][0], al[mi][1], al[mi][2], al[mi][3],
                        stgBase + OA_LO + ao);
            }
            uint32_t b[4][2];
            // pass set 1+2: W_hi with a_hi and a_lo
            {
                uint32_t r0, r1, r2, r3;
                uint32_t addr = stgBase + OB_HI + (uint32_t)((bRow * KS + kk) * 2);
                ldsm_x4(r0, r1, r2, r3, addr);
                b[0][0] = r0; b[1][0] = r1; b[2][0] = r2; b[3][0] = r3;
                addr += 16;
                ldsm_x4(r0, r1, r2, r3, addr);
                b[0][1] = r0; b[1][1] = r1; b[2][1] = r2; b[3][1] = r3;
            }
#pragma unroll
            for (int mi = 0; mi < 2; mi++)
#pragma unroll
                for (int ni = 0; ni < 4; ni++)
                    mma_f16(acc[mi][ni], ah[mi], b[ni]);
#pragma unroll
            for (int mi = 0; mi < 2; mi++)
#pragma unroll
                for (int ni = 0; ni < 4; ni++)
                    mma_f16(acc[mi][ni], al[mi], b[ni]);
            // pass 3: W_lo with a_hi
            {
                uint32_t r0, r1, r2, r3;
                uint32_t addr = stgBase + OB_LO + (uint32_t)((bRow * KS + kk) * 2);
                ldsm_x4(r0, r1, r2, r3, addr);
                b[0][0] = r0; b[1][0] = r1; b[2][0] = r2; b[3][0] = r3;
                addr += 16;
                ldsm_x4(r0, r1, r2, r3, addr);
                b[0][1] = r0; b[1][1] = r1; b[2][1] = r2; b[3][1] = r3;
            }
#pragma unroll
            for (int mi = 0; mi < 2; mi++)
#pragma unroll
                for (int ni = 0; ni < 4; ni++)
                    mma_f16(acc[mi][ni], ah[mi], b[ni]);
        }
        __syncthreads();
    }

    // ---- epilogue ----
#pragma unroll
    for (int mi = 0; mi < 2; mi++) {
        int row0 = rowBase + wm + mi * 16 + (lane >> 2);
        int row1 = row0 + 8;
#pragma unroll
        for (int ni = 0; ni < 4; ni++) {
            int col = colBase + wn + ni * 8 + (lane & 3) * 2;
            float bx = 0.f, by = 0.f;
            if (HAS_BIAS) { bx = __ldg(bias + col); by = __ldg(bias + col + 1); }
            float2 o0 = make_float2(acc[mi][ni][0] + bx, acc[mi][ni][1] + by);
            float2 o1 = make_float2(acc[mi][ni][2] + bx, acc[mi][ni][3] + by);
            if (RELU) {
                o0.x = fmaxf(o0.x, 0.f); o0.y = fmaxf(o0.y, 0.f);
                o1.x = fmaxf(o1.x, 0.f); o1.y = fmaxf(o1.y, 0.f);
            }
            if (OUTF32) {
                *(float2*)(C + (size_t)row0 * 256 + col) = o0;
                *(float2*)(C + (size_t)row1 * 256 + col) = o1;
            } else {
                float hx = __half2float(__float2half_rn(o0.x));
                float hy = __half2float(__float2half_rn(o0.y));
                *(uint32_t*)(Chi + (size_t)row0 * 256 + col) = pack_f16x2(o0.x, o0.y);
                *(uint32_t*)(Clo + (size_t)row0 * 256 + col) =
                    pack_f16x2(o0.x - hx, o0.y - hy);
                hx = __half2float(__float2half_rn(o1.x));
                hy = __half2float(__float2half_rn(o1.y));
                *(uint32_t*)(Chi + (size_t)row1 * 256 + col) = pack_f16x2(o1.x, o1.y);
                *(uint32_t*)(Clo + (size_t)row1 * 256 + col) =
                    pack_f16x2(o1.x - hx, o1.y - hy);
            }
        }
    }
}

// ---------------------------------------------------------------------------
// CSR build
// ---------------------------------------------------------------------------
__global__ void zero_cnt_kernel() {
    int i = blockIdx.x * blockDim.x + threadIdx.x;
    if (i < N_NODES) { g_degi[i] = 0; g_cnt[i] = 0; }
}

__global__ void hist_kernel(const int* __restrict__ src, const int* __restrict__ dst) {
    int e = blockIdx.x * blockDim.x + threadIdx.x;
    if (e < E_EDGES) {
        atomicAdd(&g_degi[src[e]], 1);
        atomicAdd(&g_cnt[dst[e]], 1);
    }
}

__global__ void dis_kernel() {
    int i = blockIdx.x * blockDim.x + threadIdx.x;
    if (i < N_NODES) {
        int d = g_degi[i];
        g_dis[i] = (d > 0) ? rsqrtf((float)d) : 0.0f;
    }
}

__global__ void partial_kernel() {
    __shared__ int sh[256];
    int i = blockIdx.x * 256 + threadIdx.x;
    sh[threadIdx.x] = (i < N_NODES) ? g_cnt[i] : 0;
    __syncthreads();
#pragma unroll
    for (int o = 128; o > 0; o >>= 1) {
        if (threadIdx.x < o) sh[threadIdx.x] += sh[threadIdx.x + o];
        __syncthreads();
    }
    if (threadIdx.x == 0) g_bsum[blockIdx.x] = sh[0];
}

__global__ void scan_blocks_kernel() {
    __shared__ int sh[256];
    int tid = threadIdx.x;
    int v = (tid < NBLK) ? g_bsum[tid] : 0;
    sh[tid] = v;
    __syncthreads();
#pragma unroll
    for (int o = 1; o < 256; o <<= 1) {
        int t = (tid >= o) ? sh[tid - o] : 0;
        __syncthreads();
        sh[tid] += t;
        __syncthreads();
    }
    g_boff[tid] = sh[tid] - v;
}

__global__ void apply_kernel() {
    __shared__ int sh[256];
    int tid = threadIdx.x;
    int i = blockIdx.x * 256 + tid;
    int v = (i < N_NODES) ? g_cnt[i] : 0;
    sh[tid] = v;
    __syncthreads();
#pragma unroll
    for (int o = 1; o < 256; o <<= 1) {
        int t = (tid >= o) ? sh[tid - o] : 0;
        __syncthreads();
        sh[tid] += t;
        __syncthreads();
    }
    if (i < N_NODES) {
        int excl = sh[tid] - v + g_boff[blockIdx.x];
        g_rowstart[i] = excl;
        g_cursor[i]   = excl;
    }
}

__global__ void fill_kernel(const int* __restrict__ src, const int* __restrict__ dst) {
    int e = blockIdx.x * blockDim.x + threadIdx.x;
    if (e < E_EDGES) {
        int s = src[e], d = dst[e];
        int pos = atomicAdd(&g_cursor[d], 1);
        g_csr_src[pos] = s;
        g_csr_w[pos]   = -g_dis[s] * g_dis[d];
    }
}

// ---------------------------------------------------------------------------
// Gather: agg[n] = sum_e w_e * (hi+lo)[src_e]; writes fp16 pair (streamed).
// ---------------------------------------------------------------------------
__global__ __launch_bounds__(256)
void gather_kernel(const u16* __restrict__ hi, const u16* __restrict__ lo,
                   u16* __restrict__ outhi, u16* __restrict__ outlo)
{
    int node = (blockIdx.x * blockDim.x + threadIdx.x) >> 5;
    int lane = threadIdx.x & 31;
    if (node >= N_NODES) return;

    float a[8] = {0.f, 0.f, 0.f, 0.f, 0.f, 0.f, 0.f, 0.f};

    int p   = g_rowstart[node];
    int end = p + g_cnt[node];

#pragma unroll 1
    for (; p + 1 < end; p += 2) {
        int   s0 = __ldg(&g_csr_src[p]);
        int   s1 = __ldg(&g_csr_src[p + 1]);
        float w0 = __ldg(&g_csr_w[p]);
        float w1 = __ldg(&g_csr_w[p + 1]);
        uint4 h0 = *(const uint4*)(hi + (size_t)s0 * 256 + lane * 8);
        uint4 l0 = *(const uint4*)(lo + (size_t)s0 * 256 + lane * 8);
        uint4 h1 = *(const uint4*)(hi + (size_t)s1 * 256 + lane * 8);
        uint4 l1 = *(const uint4*)(lo + (size_t)s1 * 256 + lane * 8);
#pragma unroll
        for (int q = 0; q < 4; q++) {
            float2 fh0 = f16x2_to_f2((&h0.x)[q]), fl0 = f16x2_to_f2((&l0.x)[q]);
            float2 fh1 = f16x2_to_f2((&h1.x)[q]), fl1 = f16x2_to_f2((&l1.x)[q]);
            a[q*2]   = fmaf(w0, fh0.x + fl0.x, a[q*2]);
            a[q*2+1] = fmaf(w0, fh0.y + fl0.y, a[q*2+1]);
            a[q*2]   = fmaf(w1, fh1.x + fl1.x, a[q*2]);
            a[q*2+1] = fmaf(w1, fh1.y + fl1.y, a[q*2+1]);
        }
    }
    if (p < end) {
        int   s0 = __ldg(&g_csr_src[p]);
        float w0 = __ldg(&g_csr_w[p]);
        uint4 h0 = *(const uint4*)(hi + (size_t)s0 * 256 + lane * 8);
        uint4 l0 = *(const uint4*)(lo + (size_t)s0 * 256 + lane * 8);
#pragma unroll
        for (int q = 0; q < 4; q++) {
            float2 fh0 = f16x2_to_f2((&h0.x)[q]), fl0 = f16x2_to_f2((&l0.x)[q]);
            a[q*2]   = fmaf(w0, fh0.x + fl0.x, a[q*2]);
            a[q*2+1] = fmaf(w0, fh0.y + fl0.y, a[q*2+1]);
        }
    }

    uint4 hh, ll;
#pragma unroll
    for (int q = 0; q < 4; q++) {
        float x0 = a[q*2], x1 = a[q*2+1];
        float h0 = __half2float(__float2half_rn(x0));
        float h1 = __half2float(__float2half_rn(x1));
        (&hh.x)[q] = pack_f16x2(x0, x1);
        (&ll.x)[q] = pack_f16x2(x0 - h0, x1 - h1);
    }
    __stcs((uint4*)(outhi + (size_t)node * 256 + lane * 8), hh);
    __stcs((uint4*)(outlo + (size_t)node * 256 + lane * 8), ll);
}

// ---------------------------------------------------------------------------
// Head
// ---------------------------------------------------------------------------
__global__ __launch_bounds__(256)
void head_kernel(const float* __restrict__ h, const float* __restrict__ W4,
                 const float* __restrict__ b4, float* __restrict__ out)
{
    int warp = (blockIdx.x * blockDim.x + threadIdx.x) >> 5;
    int lane = threadIdx.x & 31;
    if (warp >= N_NODES) return;

    const float* hr = h + (size_t)warp * 256;
    float s0 = 0.f, s1 = 0.f;
#pragma unroll
    for (int i = 0; i < 8; i++) {
        int c = lane + i * 32;
        float v = hr[c];
        s0 = fmaf(v, W4[c],       s0);
        s1 = fmaf(v, W4[256 + c], s1);
    }
#pragma unroll
    for (int o = 16; o > 0; o >>= 1) {
        s0 += __shfl_down_sync(0xFFFFFFFFu, s0, o);
        s1 += __shfl_down_sync(0xFFFFFFFFu, s1, o);
    }
    if (lane == 0) {
        out[(size_t)warp * 2 + 0] = s0 + b4[0];
        out[(size_t)warp * 2 + 1] = s1 + b4[1];
    }
}

// ---------------------------------------------------------------------------
// Launch sequence
// ---------------------------------------------------------------------------
extern "C" void kernel_launch(void* const* d_in, const int* in_sizes, int n_in,
                              void* d_out, int out_size)
{
    const float* x    = (const float*)d_in[0];
    const int*   ei   = (const int*)  d_in[1];
    const float* W1   = (const float*)d_in[2];
    const float* b1   = (const float*)d_in[3];
    const float* W2   = (const float*)d_in[4];
    const float* b2   = (const float*)d_in[5];
    const float* W3   = (const float*)d_in[6];
    const float* b3   = (const float*)d_in[7];
    const float* W4   = (const float*)d_in[8];
    const float* b4   = (const float*)d_in[9];
    const float* T10  = (const float*)d_in[10];
    const float* T11  = (const float*)d_in[11];
    const float* cb1  = (const float*)d_in[12];
    const float* T20  = (const float*)d_in[13];
    const float* T21  = (const float*)d_in[14];
    const float* cb2  = (const float*)d_in[15];
    float* out = (float*)d_out;

    const int* src = ei;
    const int* dst = ei + E_EDGES;

    float *h3;
    u16 *xhi, *xlo, *h1hi, *h1lo, *h2hi, *h2lo, *aghi, *aglo;
    u16 *o1hi, *o1lo, *o2hi, *o2lo, *whi, *wlo;
    u16 *wc1hi, *wc1lo, *wc2hi, *wc2lo;
    cudaGetSymbolAddress((void**)&h3, g_h3);
    cudaGetSymbolAddress((void**)&xhi, g_xhi);
    cudaGetSymbolAddress((void**)&xlo, g_xlo);
    cudaGetSymbolAddress((void**)&h1hi, g_h1hi);
    cudaGetSymbolAddress((void**)&h1lo, g_h1lo);
    cudaGetSymbolAddress((void**)&h2hi, g_h2hi);
    cudaGetSymbolAddress((void**)&h2lo, g_h2lo);
    cudaGetSymbolAddress((void**)&aghi, g_aghi);
    cudaGetSymbolAddress((void**)&aglo, g_aglo);
    cudaGetSymbolAddress((void**)&o1hi, g_o1hi);
    cudaGetSymbolAddress((void**)&o1lo, g_o1lo);
    cudaGetSymbolAddress((void**)&o2hi, g_o2hi);
    cudaGetSymbolAddress((void**)&o2lo, g_o2lo);
    cudaGetSymbolAddress((void**)&whi, g_whi);
    cudaGetSymbolAddress((void**)&wlo, g_wlo);
    cudaGetSymbolAddress((void**)&wc1hi, g_wc1hi);
    cudaGetSymbolAddress((void**)&wc1lo, g_wc1lo);
    cudaGetSymbolAddress((void**)&wc2hi, g_wc2hi);
    cudaGetSymbolAddress((void**)&wc2lo, g_wc2lo);

    const int WSZ = HDIM * HDIM;
    const int SMEMSZ = 2 * STG;   // 61440

    cudaFuncSetAttribute(gemm_mma_kernel<8,  true,  true, false>,
                         cudaFuncAttributeMaxDynamicSharedMemorySize, SMEMSZ);
    cudaFuncSetAttribute(gemm_mma_kernel<16, false, true, false>,
                         cudaFuncAttributeMaxDynamicSharedMemorySize, SMEMSZ);
    cudaFuncSetAttribute(gemm_mma_kernel<8,  true,  true, true>,
                         cudaFuncAttributeMaxDynamicSharedMemorySize, SMEMSZ);

    dim3 ggrid(MPAD / BM, 4);    // (391, 4) — 64-col column blocks
    const int gthr  = (N_NODES * 32 + 255) / 256;
    const int wblk  = (WSZ / 4 + 255) / 256;

    // --- positions 1-5: splits + first two GEMMs (ncu capture lands here) ---
    split_kernel<<<(N_NODES * HDIM / 4 + 255) / 256, 256>>>(x, xhi, xlo,
                                                            N_NODES * HDIM / 4);
    split_kernel<<<wblk, 256>>>(W1, whi + 0 * WSZ, wlo + 0 * WSZ, WSZ / 4);
    split_kernel<<<wblk, 256>>>(W2, whi + 1 * WSZ, wlo + 1 * WSZ, WSZ / 4);
    gemm_mma_kernel<8, true, true, false><<<ggrid, 256, SMEMSZ>>>(
        xhi, xlo, nullptr, nullptr, whi + 0 * WSZ, wlo + 0 * WSZ, b1,
        nullptr, h1hi, h1lo);
    gemm_mma_kernel<8, true, true, false><<<ggrid, 256, SMEMSZ>>>(
        h1hi, h1lo, nullptr, nullptr, whi + 1 * WSZ, wlo + 1 * WSZ, b2,
        nullptr, h2hi, h2lo);

    // --- CSR + remaining weight prep ---
    zero_cnt_kernel<<<(N_NODES + 255) / 256, 256>>>();
    hist_kernel<<<(E_EDGES + 255) / 256, 256>>>(src, dst);
    dis_kernel<<<(N_NODES + 255) / 256, 256>>>();
    partial_kernel<<<NBLK, 256>>>();
    scan_blocks_kernel<<<1, 256>>>();
    apply_kernel<<<NBLK, 256>>>();
    fill_kernel<<<(E_EDGES + 255) / 256, 256>>>(src, dst);

    split_w512_kernel<<<wblk, 256>>>(T10, wc1hi, wc1lo, 0);
    split_w512_kernel<<<wblk, 256>>>(T11, wc1hi, wc1lo, 256);
    split_w512_kernel<<<wblk, 256>>>(T20, wc2hi, wc2lo, 0);
    split_w512_kernel<<<wblk, 256>>>(T21, wc2hi, wc2lo, 256);
    split_kernel<<<wblk, 256>>>(W3, whi + 2 * WSZ, wlo + 2 * WSZ, WSZ / 4);

    // --- conv 1: agg = S h2 ; out1 = [h2, agg] @ [T10;T11]^T + cb1 ---
    gather_kernel<<<gthr, 256>>>(h2hi, h2lo, aghi, aglo);
    gemm_mma_kernel<16, false, true, false><<<ggrid, 256, SMEMSZ>>>(
        h2hi, h2lo, aghi, aglo, wc1hi, wc1lo, cb1, nullptr, o1hi, o1lo);

    // --- conv 2: agg = S out1 ; out2 = [out1, agg] @ [T20;T21]^T + cb2 ---
    gather_kernel<<<gthr, 256>>>(o1hi, o1lo, aghi, aglo);
    gemm_mma_kernel<16, false, true, false><<<ggrid, 256, SMEMSZ>>>(
        o1hi, o1lo, aghi, aglo, wc2hi, wc2lo, cb2, nullptr, o2hi, o2lo);

    // --- h3 = relu(out2@W3^T + b3) ; out = h3@W4^T + b4 ---
    gemm_mma_kernel<8, true, true, true><<<ggrid, 256, SMEMSZ>>>(
        o2hi, o2lo, nullptr, nullptr, whi + 2 * WSZ, wlo + 2 * WSZ, b3,
        h3, nullptr, nullptr);
    head_kernel<<<gthr, 256>>>(h3, W4, b4, out);
}

// round 11
// speedup vs baseline: 1.1105x; 1.1105x over previous
#include <cuda_runtime.h>
#include <cuda_fp16.h>
#include <cstdint>

#define N_NODES 50000
#define MPAD    50048
#define E_EDGES 1600000
#define HDIM    256
#define NBLK    196

typedef unsigned short u16;

// ---------------------------------------------------------------------------
// Static device scratch
// ---------------------------------------------------------------------------
__device__ int   g_degi[N_NODES];
__device__ int   g_cnt[N_NODES];
__device__ int   g_rowstart[N_NODES];
__device__ int   g_cursor[N_NODES];
__device__ float g_dis[N_NODES];
__device__ int   g_csr_src[E_EDGES];
__device__ float g_csr_w[E_EDGES];
__device__ int   g_bsum[256];
__device__ int   g_boff[256];

__device__ float g_h3[(size_t)MPAD * HDIM];

// fp16 activation pairs
__device__ u16 g_xhi[(size_t)MPAD * HDIM];
__device__ u16 g_xlo[(size_t)MPAD * HDIM];
__device__ u16 g_h1hi[(size_t)MPAD * HDIM];
__device__ u16 g_h1lo[(size_t)MPAD * HDIM];
__device__ u16 g_h2hi[(size_t)MPAD * HDIM];
__device__ u16 g_h2lo[(size_t)MPAD * HDIM];
__device__ u16 g_aghi[(size_t)MPAD * HDIM];
__device__ u16 g_aglo[(size_t)MPAD * HDIM];
__device__ u16 g_o1hi[(size_t)MPAD * HDIM];
__device__ u16 g_o1lo[(size_t)MPAD * HDIM];
__device__ u16 g_o2hi[(size_t)MPAD * HDIM];
__device__ u16 g_o2lo[(size_t)MPAD * HDIM];

// fp16 hi/lo weights: W1,W2,W3 (256 cols) + concat conv weights (512 cols)
__device__ u16 g_whi[3 * HDIM * HDIM];
__device__ u16 g_wlo[3 * HDIM * HDIM];
__device__ u16 g_wc1hi[HDIM * 512];
__device__ u16 g_wc1lo[HDIM * 512];
__device__ u16 g_wc2hi[HDIM * 512];
__device__ u16 g_wc2lo[HDIM * 512];

// ---------------------------------------------------------------------------
// helpers
// ---------------------------------------------------------------------------
__device__ __forceinline__ uint32_t pack_f16x2(float lo, float hi) {
    __half2 h = __floats2half2_rn(lo, hi);
    return *reinterpret_cast<uint32_t*>(&h);
}

__device__ __forceinline__ float2 f16x2_to_f2(uint32_t u) {
    __half2 h = *reinterpret_cast<__half2*>(&u);
    return __half22float2(h);
}

__device__ __forceinline__ void ldsm_x4(uint32_t& r0, uint32_t& r1,
                                        uint32_t& r2, uint32_t& r3, uint32_t addr) {
    asm volatile("ldmatrix.sync.aligned.m8n8.x4.shared.b16 {%0,%1,%2,%3}, [%4];"
                 : "=r"(r0), "=r"(r1), "=r"(r2), "=r"(r3) : "r"(addr));
}

__device__ __forceinline__ void mma_f16(float c[4], const uint32_t a[4],
                                        const uint32_t b[2]) {
    asm volatile(
        "mma.sync.aligned.m16n8k16.row.col.f32.f16.f16.f32 "
        "{%0,%1,%2,%3}, {%4,%5,%6,%7}, {%8,%9}, {%0,%1,%2,%3};"
        : "+f"(c[0]), "+f"(c[1]), "+f"(c[2]), "+f"(c[3])
        : "r"(a[0]), "r"(a[1]), "r"(a[2]), "r"(a[3]), "r"(b[0]), "r"(b[1]));
}

#define CP16(sm, gp) \
    asm volatile("cp.async.cg.shared.global [%0], [%1], 16;" :: "r"(sm), "l"(gp))
#define CPCOMMIT() asm volatile("cp.async.commit_group;")
#define CPWAIT0()  asm volatile("cp.async.wait_group 0;")

// ---------------------------------------------------------------------------
// splits
// ---------------------------------------------------------------------------
__global__ void split_kernel(const float* __restrict__ in, u16* __restrict__ hi,
                             u16* __restrict__ lo, int n4)
{
    int i = blockIdx.x * blockDim.x + threadIdx.x;
    if (i >= n4) return;
    float4 v = ((const float4*)in)[i];
    float hx = __half2float(__float2half_rn(v.x));
    float hy = __half2float(__float2half_rn(v.y));
    float hz = __half2float(__float2half_rn(v.z));
    float hw = __half2float(__float2half_rn(v.w));
    uint2 h = make_uint2(pack_f16x2(v.x, v.y), pack_f16x2(v.z, v.w));
    uint2 l = make_uint2(pack_f16x2(v.x - hx, v.y - hy),
                         pack_f16x2(v.z - hz, v.w - hw));
    ((uint2*)hi)[i] = h;
    ((uint2*)lo)[i] = l;
}

// hi/lo split into 512-col concat layout
__global__ void split_w512_kernel(const float* __restrict__ in, u16* __restrict__ hi,
                                  u16* __restrict__ lo, int colofs)
{
    int i = blockIdx.x * blockDim.x + threadIdx.x;
    if (i >= HDIM * HDIM / 4) return;
    int row = i >> 6;
    int col = (i & 63) * 4;
    float4 v = ((const float4*)in)[i];
    float hx = __half2float(__float2half_rn(v.x));
    float hy = __half2float(__float2half_rn(v.y));
    float hz = __half2float(__float2half_rn(v.z));
    float hw = __half2float(__float2half_rn(v.w));
    uint2 h = make_uint2(pack_f16x2(v.x, v.y), pack_f16x2(v.z, v.w));
    uint2 l = make_uint2(pack_f16x2(v.x - hx, v.y - hy),
                         pack_f16x2(v.z - hz, v.w - hw));
    size_t o = (size_t)row * 512 + colofs + col;
    *(uint2*)(hi + o) = h;
    *(uint2*)(lo + o) = l;
}

// ---------------------------------------------------------------------------
// GEMM: C[MPAD, colBase:+64] = (Ahi+Alo) @ (Whi+Wlo)[colBase:+64]^T
// 3-pass exact fp16 split (drops only a_lo*w_lo ~2^-22).
// Tile 128x64x32, 256 thr, warp tile 32x32, 3 CTAs/SM, 2-stage cp.async.
// ---------------------------------------------------------------------------
#define BM   128
#define KS   40
#define STG  30720
#define OA_HI 0
#define OA_LO 10240
#define OB_HI 20480
#define OB_LO 25600

template <int KCHUNKS, bool RELU, bool HAS_BIAS, bool OUTF32>
__global__ __launch_bounds__(256, 3)
void gemm_mma_kernel(const u16* __restrict__ Ahi, const u16* __restrict__ Alo,
                     const u16* __restrict__ A2hi, const u16* __restrict__ A2lo,
                     const u16* __restrict__ Whi, const u16* __restrict__ Wlo,
                     const float* __restrict__ bias,
                     float* __restrict__ C, u16* __restrict__ Chi,
                     u16* __restrict__ Clo)
{
    extern __shared__ char smem[];
    const uint32_t sb = (uint32_t)__cvta_generic_to_shared(smem);
    const int tid  = threadIdx.x;
    const int lane = tid & 31;
    const int wid  = tid >> 5;
    const int wm   = (wid & 3) * 32;
    const int wn   = (wid >> 2) * 32;
    const int rowBase = blockIdx.x * BM;
    const int colBase = blockIdx.y * 64;
    const int KTOT = KCHUNKS * 32;

    float acc[2][4][4];
#pragma unroll
    for (int mi = 0; mi < 2; mi++)
#pragma unroll
        for (int ni = 0; ni < 4; ni++)
#pragma unroll
            for (int j = 0; j < 4; j++) acc[mi][ni][j] = 0.0f;

    const int aRow = wm + (lane & 15);
    const int aColSel = (lane >> 4) * 8;
    const int bRow = wn + lane;

    auto load_chunk = [&](int c, int s) {
        uint32_t base = sb + (uint32_t)s * STG;
        const u16* pah = (c < 8) ? Ahi : A2hi;
        const u16* pal = (c < 8) ? Alo : A2lo;
        int ko = (c & 7) * 32;
        int k0 = c * 32;
#pragma unroll
        for (int i = 0; i < 2; i++) {
            int f   = tid + i * 256;
            int row = f >> 2;
            int c8  = (f & 3) * 8;
            uint32_t so = (uint32_t)(row * 80 + c8 * 2);
            CP16(base + OA_HI + so, pah + (size_t)(rowBase + row) * 256 + ko + c8);
            CP16(base + OA_LO + so, pal + (size_t)(rowBase + row) * 256 + ko + c8);
        }
        {
            int row = tid >> 2;
            int c8  = (tid & 3) * 8;
            uint32_t so = (uint32_t)(row * 80 + c8 * 2);
            CP16(base + OB_HI + so, Whi + (size_t)(colBase + row) * KTOT + k0 + c8);
            CP16(base + OB_LO + so, Wlo + (size_t)(colBase + row) * KTOT + k0 + c8);
        }
    };

    load_chunk(0, 0);
    CPCOMMIT();

#pragma unroll 1
    for (int c = 0; c < KCHUNKS; ++c) {
        const int s = c & 1;
        CPWAIT0();
        __syncthreads();
        if (c + 1 < KCHUNKS) { load_chunk(c + 1, s ^ 1); CPCOMMIT(); }

        const uint32_t stgBase = sb + (uint32_t)s * STG;
#pragma unroll
        for (int kk = 0; kk < 32; kk += 16) {
            uint32_t ah[2][4], al[2][4];
#pragma unroll
            for (int mi = 0; mi < 2; mi++) {
                uint32_t ao = (uint32_t)(((aRow + mi * 16) * KS + kk + aColSel) * 2);
                ldsm_x4(ah[mi][0], ah[mi][1], ah[mi][2], ah[mi][3],
                        stgBase + OA_HI + ao);
                ldsm_x4(al[mi][0], al[mi][1], al[mi][2], al[mi][3],
                        stgBase + OA_LO + ao);
            }
            uint32_t b[4][2];
            // W_hi with a_hi and a_lo
            {
                uint32_t r0, r1, r2, r3;
                uint32_t addr = stgBase + OB_HI + (uint32_t)((bRow * KS + kk) * 2);
                ldsm_x4(r0, r1, r2, r3, addr);
                b[0][0] = r0; b[1][0] = r1; b[2][0] = r2; b[3][0] = r3;
                addr += 16;
                ldsm_x4(r0, r1, r2, r3, addr);
                b[0][1] = r0; b[1][1] = r1; b[2][1] = r2; b[3][1] = r3;
            }
#pragma unroll
            for (int mi = 0; mi < 2; mi++)
#pragma unroll
                for (int ni = 0; ni < 4; ni++)
                    mma_f16(acc[mi][ni], ah[mi], b[ni]);
#pragma unroll
            for (int mi = 0; mi < 2; mi++)
#pragma unroll
                for (int ni = 0; ni < 4; ni++)
                    mma_f16(acc[mi][ni], al[mi], b[ni]);
            // W_lo with a_hi
            {
                uint32_t r0, r1, r2, r3;
                uint32_t addr = stgBase + OB_LO + (uint32_t)((bRow * KS + kk) * 2);
                ldsm_x4(r0, r1, r2, r3, addr);
                b[0][0] = r0; b[1][0] = r1; b[2][0] = r2; b[3][0] = r3;
                addr += 16;
                ldsm_x4(r0, r1, r2, r3, addr);
                b[0][1] = r0; b[1][1] = r1; b[2][1] = r2; b[3][1] = r3;
            }
#pragma unroll
            for (int mi = 0; mi < 2; mi++)
#pragma unroll
                for (int ni = 0; ni < 4; ni++)
                    mma_f16(acc[mi][ni], ah[mi], b[ni]);
        }
        __syncthreads();
    }

    // ---- epilogue ----
#pragma unroll
    for (int mi = 0; mi < 2; mi++) {
        int row0 = rowBase + wm + mi * 16 + (lane >> 2);
        int row1 = row0 + 8;
#pragma unroll
        for (int ni = 0; ni < 4; ni++) {
            int col = colBase + wn + ni * 8 + (lane & 3) * 2;
            float bx = 0.f, by = 0.f;
            if (HAS_BIAS) { bx = __ldg(bias + col); by = __ldg(bias + col + 1); }
            float2 o0 = make_float2(acc[mi][ni][0] + bx, acc[mi][ni][1] + by);
            float2 o1 = make_float2(acc[mi][ni][2] + bx, acc[mi][ni][3] + by);
            if (RELU) {
                o0.x = fmaxf(o0.x, 0.f); o0.y = fmaxf(o0.y, 0.f);
                o1.x = fmaxf(o1.x, 0.f); o1.y = fmaxf(o1.y, 0.f);
            }
            if (OUTF32) {
                *(float2*)(C + (size_t)row0 * 256 + col) = o0;
                *(float2*)(C + (size_t)row1 * 256 + col) = o1;
            } else {
                float hx = __half2float(__float2half_rn(o0.x));
                float hy = __half2float(__float2half_rn(o0.y));
                *(uint32_t*)(Chi + (size_t)row0 * 256 + col) = pack_f16x2(o0.x, o0.y);
                *(uint32_t*)(Clo + (size_t)row0 * 256 + col) =
                    pack_f16x2(o0.x - hx, o0.y - hy);
                hx = __half2float(__float2half_rn(o1.x));
                hy = __half2float(__float2half_rn(o1.y));
                *(uint32_t*)(Chi + (size_t)row1 * 256 + col) = pack_f16x2(o1.x, o1.y);
                *(uint32_t*)(Clo + (size_t)row1 * 256 + col) =
                    pack_f16x2(o1.x - hx, o1.y - hy);
            }
        }
    }
}

// ---------------------------------------------------------------------------
// CSR build
// ---------------------------------------------------------------------------
__global__ void zero_cnt_kernel() {
    int i = blockIdx.x * blockDim.x + threadIdx.x;
    if (i < N_NODES) { g_degi[i] = 0; g_cnt[i] = 0; }
}

__global__ void hist_kernel(const int* __restrict__ src, const int* __restrict__ dst) {
    int e = blockIdx.x * blockDim.x + threadIdx.x;
    if (e < E_EDGES) {
        atomicAdd(&g_degi[src[e]], 1);
        atomicAdd(&g_cnt[dst[e]], 1);
    }
}

__global__ void dis_kernel() {
    int i = blockIdx.x * blockDim.x + threadIdx.x;
    if (i < N_NODES) {
        int d = g_degi[i];
        g_dis[i] = (d > 0) ? rsqrtf((float)d) : 0.0f;
    }
}

__global__ void partial_kernel() {
    __shared__ int sh[256];
    int i = blockIdx.x * 256 + threadIdx.x;
    sh[threadIdx.x] = (i < N_NODES) ? g_cnt[i] : 0;
    __syncthreads();
#pragma unroll
    for (int o = 128; o > 0; o >>= 1) {
        if (threadIdx.x < o) sh[threadIdx.x] += sh[threadIdx.x + o];
        __syncthreads();
    }
    if (threadIdx.x == 0) g_bsum[blockIdx.x] = sh[0];
}

__global__ void scan_blocks_kernel() {
    __shared__ int sh[256];
    int tid = threadIdx.x;
    int v = (tid < NBLK) ? g_bsum[tid] : 0;
    sh[tid] = v;
    __syncthreads();
#pragma unroll
    for (int o = 1; o < 256; o <<= 1) {
        int t = (tid >= o) ? sh[tid - o] : 0;
        __syncthreads();
        sh[tid] += t;
        __syncthreads();
    }
    g_boff[tid] = sh[tid] - v;
}

__global__ void apply_kernel() {
    __shared__ int sh[256];
    int tid = threadIdx.x;
    int i = blockIdx.x * 256 + tid;
    int v = (i < N_NODES) ? g_cnt[i] : 0;
    sh[tid] = v;
    __syncthreads();
#pragma unroll
    for (int o = 1; o < 256; o <<= 1) {
        int t = (tid >= o) ? sh[tid - o] : 0;
        __syncthreads();
        sh[tid] += t;
        __syncthreads();
    }
    if (i < N_NODES) {
        int excl = sh[tid] - v + g_boff[blockIdx.x];
        g_rowstart[i] = excl;
        g_cursor[i]   = excl;
    }
}

__global__ void fill_kernel(const int* __restrict__ src, const int* __restrict__ dst) {
    int e = blockIdx.x * blockDim.x + threadIdx.x;
    if (e < E_EDGES) {
        int s = src[e], d = dst[e];
        int pos = atomicAdd(&g_cursor[d], 1);
        g_csr_src[pos] = s;
        g_csr_w[pos]   = -g_dis[s] * g_dis[d];
    }
}

// ---------------------------------------------------------------------------
// Gather (hi-only input): agg[n] = sum_e w_e * hi[src_e]; halves L2 traffic.
// Output written as exact fp16 hi/lo split of the fp32 accumulator.
// ---------------------------------------------------------------------------
__global__ __launch_bounds__(256)
void gather_kernel(const u16* __restrict__ hi,
                   u16* __restrict__ outhi, u16* __restrict__ outlo)
{
    int node = (blockIdx.x * blockDim.x + threadIdx.x) >> 5;
    int lane = threadIdx.x & 31;
    if (node >= N_NODES) return;

    float a[8] = {0.f, 0.f, 0.f, 0.f, 0.f, 0.f, 0.f, 0.f};

    int p   = g_rowstart[node];
    int end = p + g_cnt[node];

#pragma unroll 1
    for (; p + 3 < end; p += 4) {
        int   s0 = __ldg(&g_csr_src[p]);
        int   s1 = __ldg(&g_csr_src[p + 1]);
        int   s2 = __ldg(&g_csr_src[p + 2]);
        int   s3 = __ldg(&g_csr_src[p + 3]);
        float w0 = __ldg(&g_csr_w[p]);
        float w1 = __ldg(&g_csr_w[p + 1]);
        float w2 = __ldg(&g_csr_w[p + 2]);
        float w3 = __ldg(&g_csr_w[p + 3]);
        uint4 h0 = *(const uint4*)(hi + (size_t)s0 * 256 + lane * 8);
        uint4 h1 = *(const uint4*)(hi + (size_t)s1 * 256 + lane * 8);
        uint4 h2 = *(const uint4*)(hi + (size_t)s2 * 256 + lane * 8);
        uint4 h3 = *(const uint4*)(hi + (size_t)s3 * 256 + lane * 8);
#pragma unroll
        for (int q = 0; q < 4; q++) {
            float2 f0 = f16x2_to_f2((&h0.x)[q]);
            float2 f1 = f16x2_to_f2((&h1.x)[q]);
            float2 f2 = f16x2_to_f2((&h2.x)[q]);
            float2 f3 = f16x2_to_f2((&h3.x)[q]);
            a[q*2]   = fmaf(w0, f0.x, a[q*2]);
            a[q*2+1] = fmaf(w0, f0.y, a[q*2+1]);
            a[q*2]   = fmaf(w1, f1.x, a[q*2]);
            a[q*2+1] = fmaf(w1, f1.y, a[q*2+1]);
            a[q*2]   = fmaf(w2, f2.x, a[q*2]);
            a[q*2+1] = fmaf(w2, f2.y, a[q*2+1]);
            a[q*2]   = fmaf(w3, f3.x, a[q*2]);
            a[q*2+1] = fmaf(w3, f3.y, a[q*2+1]);
        }
    }
#pragma unroll 1
    for (; p < end; ++p) {
        int   s0 = __ldg(&g_csr_src[p]);
        float w0 = __ldg(&g_csr_w[p]);
        uint4 h0 = *(const uint4*)(hi + (size_t)s0 * 256 + lane * 8);
#pragma unroll
        for (int q = 0; q < 4; q++) {
            float2 f0 = f16x2_to_f2((&h0.x)[q]);
            a[q*2]   = fmaf(w0, f0.x, a[q*2]);
            a[q*2+1] = fmaf(w0, f0.y, a[q*2+1]);
        }
    }

    uint4 hh, ll;
#pragma unroll
    for (int q = 0; q < 4; q++) {
        float x0 = a[q*2], x1 = a[q*2+1];
        float h0 = __half2float(__float2half_rn(x0));
        float h1 = __half2float(__float2half_rn(x1));
        (&hh.x)[q] = pack_f16x2(x0, x1);
        (&ll.x)[q] = pack_f16x2(x0 - h0, x1 - h1);
    }
    __stcs((uint4*)(outhi + (size_t)node * 256 + lane * 8), hh);
    __stcs((uint4*)(outlo + (size_t)node * 256 + lane * 8), ll);
}

// ---------------------------------------------------------------------------
// Head
// ---------------------------------------------------------------------------
__global__ __launch_bounds__(256)
void head_kernel(const float* __restrict__ h, const float* __restrict__ W4,
                 const float* __restrict__ b4, float* __restrict__ out)
{
    int warp = (blockIdx.x * blockDim.x + threadIdx.x) >> 5;
    int lane = threadIdx.x & 31;
    if (warp >= N_NODES) return;

    const float* hr = h + (size_t)warp * 256;
    float s0 = 0.f, s1 = 0.f;
#pragma unroll
    for (int i = 0; i < 8; i++) {
        int c = lane + i * 32;
        float v = hr[c];
        s0 = fmaf(v, W4[c],       s0);
        s1 = fmaf(v, W4[256 + c], s1);
    }
#pragma unroll
    for (int o = 16; o > 0; o >>= 1) {
        s0 += __shfl_down_sync(0xFFFFFFFFu, s0, o);
        s1 += __shfl_down_sync(0xFFFFFFFFu, s1, o);
    }
    if (lane == 0) {
        out[(size_t)warp * 2 + 0] = s0 + b4[0];
        out[(size_t)warp * 2 + 1] = s1 + b4[1];
    }
}

// ---------------------------------------------------------------------------
// Launch sequence (single stream — capture-safe)
// ---------------------------------------------------------------------------
extern "C" void kernel_launch(void* const* d_in, const int* in_sizes, int n_in,
                              void* d_out, int out_size)
{
    const float* x    = (const float*)d_in[0];
    const int*   ei   = (const int*)  d_in[1];
    const float* W1   = (const float*)d_in[2];
    const float* b1   = (const float*)d_in[3];
    const float* W2   = (const float*)d_in[4];
    const float* b2   = (const float*)d_in[5];
    const float* W3   = (const float*)d_in[6];
    const float* b3   = (const float*)d_in[7];
    const float* W4   = (const float*)d_in[8];
    const float* b4   = (const float*)d_in[9];
    const float* T10  = (const float*)d_in[10];
    const float* T11  = (const float*)d_in[11];
    const float* cb1  = (const float*)d_in[12];
    const float* T20  = (const float*)d_in[13];
    const float* T21  = (const float*)d_in[14];
    const float* cb2  = (const float*)d_in[15];
    float* out = (float*)d_out;

    const int* src = ei;
    const int* dst = ei + E_EDGES;

    float *h3;
    u16 *xhi, *xlo, *h1hi, *h1lo, *h2hi, *h2lo, *aghi, *aglo;
    u16 *o1hi, *o1lo, *o2hi, *o2lo, *whi, *wlo;
    u16 *wc1hi, *wc1lo, *wc2hi, *wc2lo;
    cudaGetSymbolAddress((void**)&h3, g_h3);
    cudaGetSymbolAddress((void**)&xhi, g_xhi);
    cudaGetSymbolAddress((void**)&xlo, g_xlo);
    cudaGetSymbolAddress((void**)&h1hi, g_h1hi);
    cudaGetSymbolAddress((void**)&h1lo, g_h1lo);
    cudaGetSymbolAddress((void**)&h2hi, g_h2hi);
    cudaGetSymbolAddress((void**)&h2lo, g_h2lo);
    cudaGetSymbolAddress((void**)&aghi, g_aghi);
    cudaGetSymbolAddress((void**)&aglo, g_aglo);
    cudaGetSymbolAddress((void**)&o1hi, g_o1hi);
    cudaGetSymbolAddress((void**)&o1lo, g_o1lo);
    cudaGetSymbolAddress((void**)&o2hi, g_o2hi);
    cudaGetSymbolAddress((void**)&o2lo, g_o2lo);
    cudaGetSymbolAddress((void**)&whi, g_whi);
    cudaGetSymbolAddress((void**)&wlo, g_wlo);
    cudaGetSymbolAddress((void**)&wc1hi, g_wc1hi);
    cudaGetSymbolAddress((void**)&wc1lo, g_wc1lo);
    cudaGetSymbolAddress((void**)&wc2hi, g_wc2hi);
    cudaGetSymbolAddress((void**)&wc2lo, g_wc2lo);

    const int WSZ = HDIM * HDIM;
    const int SMEMSZ = 2 * STG;   // 61440

    cudaFuncSetAttribute(gemm_mma_kernel<8,  true,  true, false>,
                         cudaFuncAttributeMaxDynamicSharedMemorySize, SMEMSZ);
    cudaFuncSetAttribute(gemm_mma_kernel<16, false, true, false>,
                         cudaFuncAttributeMaxDynamicSharedMemorySize, SMEMSZ);
    cudaFuncSetAttribute(gemm_mma_kernel<8,  true,  true, true>,
                         cudaFuncAttributeMaxDynamicSharedMemorySize, SMEMSZ);

    dim3 ggrid(MPAD / BM, 4);    // (391, 4)
    const int gthr  = (N_NODES * 32 + 255) / 256;
    const int wblk  = (WSZ / 4 + 255) / 256;

    // --- input splits + MLP GEMMs ---
    split_kernel<<<(N_NODES * HDIM / 4 + 255) / 256, 256>>>(x, xhi, xlo,
                                                            N_NODES * HDIM / 4);
    split_kernel<<<wblk, 256>>>(W1, whi + 0 * WSZ, wlo + 0 * WSZ, WSZ / 4);
    split_kernel<<<wblk, 256>>>(W2, whi + 1 * WSZ, wlo + 1 * WSZ, WSZ / 4);
    gemm_mma_kernel<8, true, true, false><<<ggrid, 256, SMEMSZ>>>(
        xhi, xlo, nullptr, nullptr, whi + 0 * WSZ, wlo + 0 * WSZ, b1,
        nullptr, h1hi, h1lo);
    gemm_mma_kernel<8, true, true, false><<<ggrid, 256, SMEMSZ>>>(
        h1hi, h1lo, nullptr, nullptr, whi + 1 * WSZ, wlo + 1 * WSZ, b2,
        nullptr, h2hi, h2lo);

    // --- CSR + remaining weight prep ---
    zero_cnt_kernel<<<(N_NODES + 255) / 256, 256>>>();
    hist_kernel<<<(E_EDGES + 255) / 256, 256>>>(src, dst);
    dis_kernel<<<(N_NODES + 255) / 256, 256>>>();
    partial_kernel<<<NBLK, 256>>>();
    scan_blocks_kernel<<<1, 256>>>();
    apply_kernel<<<NBLK, 256>>>();
    fill_kernel<<<(E_EDGES + 255) / 256, 256>>>(src, dst);

    split_w512_kernel<<<wblk, 256>>>(T10, wc1hi, wc1lo, 0);
    split_w512_kernel<<<wblk, 256>>>(T11, wc1hi, wc1lo, 256);
    split_w512_kernel<<<wblk, 256>>>(T20, wc2hi, wc2lo, 0);
    split_w512_kernel<<<wblk, 256>>>(T21, wc2hi, wc2lo, 256);
    split_kernel<<<wblk, 256>>>(W3, whi + 2 * WSZ, wlo + 2 * WSZ, WSZ / 4);

    // --- conv 1: agg = S h2 (hi-only) ; out1 = [h2, agg] @ [T10;T11]^T + cb1 ---
    gather_kernel<<<gthr, 256>>>(h2hi, aghi, aglo);
    gemm_mma_kernel<16, false, true, false><<<ggrid, 256, SMEMSZ>>>(
        h2hi, h2lo, aghi, aglo, wc1hi, wc1lo, cb1, nullptr, o1hi, o1lo);

    // --- conv 2: agg = S out1 (hi-only) ; out2 = [out1, agg] @ [T20;T21]^T + cb2 ---
    gather_kernel<<<gthr, 256>>>(o1hi, aghi, aglo);
    gemm_mma_kernel<16, false, true, false><<<ggrid, 256, SMEMSZ>>>(
        o1hi, o1lo, aghi, aglo, wc2hi, wc2lo, cb2, nullptr, o2hi, o2lo);

    // --- h3 = relu(out2@W3^T + b3) ; out = h3@W4^T + b4 ---
    gemm_mma_kernel<8, true, true, true><<<ggrid, 256, SMEMSZ>>>(
        o2hi, o2lo, nullptr, nullptr, whi + 2 * WSZ, wlo + 2 * WSZ, b3,
        h3, nullptr, nullptr);
    head_kernel<<<gthr, 256>>>(h3, W4, b4, out);
}

// round 12
// speedup vs baseline: 1.1671x; 1.0510x over previous
#include <cuda_runtime.h>
#include <cuda_fp16.h>
#include <cstdint>

#define N_NODES 50000
#define MPAD    50048
#define E_EDGES 1600000
#define HDIM    256
#define NBLK    196

typedef unsigned short u16;

// ---------------------------------------------------------------------------
// Static device scratch
// ---------------------------------------------------------------------------
__device__ int   g_degi[N_NODES];
__device__ int   g_cnt[N_NODES];
__device__ int   g_rowstart[N_NODES];
__device__ int   g_cursor[N_NODES];
__device__ float g_dis[N_NODES];
__device__ int   g_csr_src[E_EDGES];
__device__ float g_csr_w[E_EDGES];
__device__ int   g_bsum[256];
__device__ int   g_boff[256];

__device__ float g_h3[(size_t)MPAD * HDIM];

// fp16 activation pairs
__device__ u16 g_xhi[(size_t)MPAD * HDIM];
__device__ u16 g_xlo[(size_t)MPAD * HDIM];
__device__ u16 g_h1hi[(size_t)MPAD * HDIM];
__device__ u16 g_h1lo[(size_t)MPAD * HDIM];
__device__ u16 g_h2hi[(size_t)MPAD * HDIM];
__device__ u16 g_h2lo[(size_t)MPAD * HDIM];
__device__ u16 g_aghi[(size_t)MPAD * HDIM];
__device__ u16 g_aglo[(size_t)MPAD * HDIM];
__device__ u16 g_o1hi[(size_t)MPAD * HDIM];
__device__ u16 g_o1lo[(size_t)MPAD * HDIM];
__device__ u16 g_o2hi[(size_t)MPAD * HDIM];
__device__ u16 g_o2lo[(size_t)MPAD * HDIM];

// fp16 hi/lo weights: W1,W2,W3 (256 cols) + concat conv weights (512 cols)
__device__ u16 g_whi[3 * HDIM * HDIM];
__device__ u16 g_wlo[3 * HDIM * HDIM];
__device__ u16 g_wc1hi[HDIM * 512];
__device__ u16 g_wc1lo[HDIM * 512];
__device__ u16 g_wc2hi[HDIM * 512];
__device__ u16 g_wc2lo[HDIM * 512];

// ---------------------------------------------------------------------------
// helpers
// ---------------------------------------------------------------------------
__device__ __forceinline__ uint32_t pack_f16x2(float lo, float hi) {
    __half2 h = __floats2half2_rn(lo, hi);
    return *reinterpret_cast<uint32_t*>(&h);
}

__device__ __forceinline__ float2 f16x2_to_f2(uint32_t u) {
    __half2 h = *reinterpret_cast<__half2*>(&u);
    return __half22float2(h);
}

__device__ __forceinline__ void ldsm_x4(uint32_t& r0, uint32_t& r1,
                                        uint32_t& r2, uint32_t& r3, uint32_t addr) {
    asm volatile("ldmatrix.sync.aligned.m8n8.x4.shared.b16 {%0,%1,%2,%3}, [%4];"
                 : "=r"(r0), "=r"(r1), "=r"(r2), "=r"(r3) : "r"(addr));
}

__device__ __forceinline__ void mma_f16(float c[4], const uint32_t a[4],
                                        const uint32_t b[2]) {
    asm volatile(
        "mma.sync.aligned.m16n8k16.row.col.f32.f16.f16.f32 "
        "{%0,%1,%2,%3}, {%4,%5,%6,%7}, {%8,%9}, {%0,%1,%2,%3};"
        : "+f"(c[0]), "+f"(c[1]), "+f"(c[2]), "+f"(c[3])
        : "r"(a[0]), "r"(a[1]), "r"(a[2]), "r"(a[3]), "r"(b[0]), "r"(b[1]));
}

#define CP16(sm, gp) \
    asm volatile("cp.async.cg.shared.global [%0], [%1], 16;" :: "r"(sm), "l"(gp))
#define CPCOMMIT() asm volatile("cp.async.commit_group;")
#define CPWAIT0()  asm volatile("cp.async.wait_group 0;")

// ---------------------------------------------------------------------------
// splits
// ---------------------------------------------------------------------------
__global__ void split_kernel(const float* __restrict__ in, u16* __restrict__ hi,
                             u16* __restrict__ lo, int n4)
{
    int i = blockIdx.x * blockDim.x + threadIdx.x;
    if (i >= n4) return;
    float4 v = ((const float4*)in)[i];
    float hx = __half2float(__float2half_rn(v.x));
    float hy = __half2float(__float2half_rn(v.y));
    float hz = __half2float(__float2half_rn(v.z));
    float hw = __half2float(__float2half_rn(v.w));
    uint2 h = make_uint2(pack_f16x2(v.x, v.y), pack_f16x2(v.z, v.w));
    uint2 l = make_uint2(pack_f16x2(v.x - hx, v.y - hy),
                         pack_f16x2(v.z - hz, v.w - hw));
    ((uint2*)hi)[i] = h;
    ((uint2*)lo)[i] = l;
}

// hi/lo split into 512-col concat layout
__global__ void split_w512_kernel(const float* __restrict__ in, u16* __restrict__ hi,
                                  u16* __restrict__ lo, int colofs)
{
    int i = blockIdx.x * blockDim.x + threadIdx.x;
    if (i >= HDIM * HDIM / 4) return;
    int row = i >> 6;
    int col = (i & 63) * 4;
    float4 v = ((const float4*)in)[i];
    float hx = __half2float(__float2half_rn(v.x));
    float hy = __half2float(__float2half_rn(v.y));
    float hz = __half2float(__float2half_rn(v.z));
    float hw = __half2float(__float2half_rn(v.w));
    uint2 h = make_uint2(pack_f16x2(v.x, v.y), pack_f16x2(v.z, v.w));
    uint2 l = make_uint2(pack_f16x2(v.x - hx, v.y - hy),
                         pack_f16x2(v.z - hz, v.w - hw));
    size_t o = (size_t)row * 512 + colofs + col;
    *(uint2*)(hi + o) = h;
    *(uint2*)(lo + o) = l;
}

// ---------------------------------------------------------------------------
// GEMM: C[MPAD, colBase:+64] = (Ahi+Alo) @ (Whi+Wlo)[colBase:+64]^T
// 3-pass exact fp16 split. If AGGLO2: chunks >= 8 (the agg half of the concat)
// run 2-pass (skip a_lo*W_hi) — that operand already carries ~2^-12 gather
// error, so the dropped ~2^-11 term is below its noise floor.
// Tile 128x64x32, 256 thr, warp tile 32x32, 3 CTAs/SM, 2-stage cp.async.
// ---------------------------------------------------------------------------
#define BM   128
#define KS   40
#define STG  30720
#define OA_HI 0
#define OA_LO 10240
#define OB_HI 20480
#define OB_LO 25600

template <int KCHUNKS, bool RELU, bool HAS_BIAS, bool OUTF32, bool AGGLO2>
__global__ __launch_bounds__(256, 3)
void gemm_mma_kernel(const u16* __restrict__ Ahi, const u16* __restrict__ Alo,
                     const u16* __restrict__ A2hi, const u16* __restrict__ A2lo,
                     const u16* __restrict__ Whi, const u16* __restrict__ Wlo,
                     const float* __restrict__ bias,
                     float* __restrict__ C, u16* __restrict__ Chi,
                     u16* __restrict__ Clo)
{
    extern __shared__ char smem[];
    const uint32_t sb = (uint32_t)__cvta_generic_to_shared(smem);
    const int tid  = threadIdx.x;
    const int lane = tid & 31;
    const int wid  = tid >> 5;
    const int wm   = (wid & 3) * 32;
    const int wn   = (wid >> 2) * 32;
    const int rowBase = blockIdx.x * BM;
    const int colBase = blockIdx.y * 64;
    const int KTOT = KCHUNKS * 32;

    float acc[2][4][4];
#pragma unroll
    for (int mi = 0; mi < 2; mi++)
#pragma unroll
        for (int ni = 0; ni < 4; ni++)
#pragma unroll
            for (int j = 0; j < 4; j++) acc[mi][ni][j] = 0.0f;

    const int aRow = wm + (lane & 15);
    const int aColSel = (lane >> 4) * 8;
    const int bRow = wn + lane;

    auto load_chunk = [&](int c, int s) {
        uint32_t base = sb + (uint32_t)s * STG;
        const u16* pah = (c < 8) ? Ahi : A2hi;
        const u16* pal = (c < 8) ? Alo : A2lo;
        int ko = (c & 7) * 32;
        int k0 = c * 32;
        bool needLo = !(AGGLO2 && c >= 8);
#pragma unroll
        for (int i = 0; i < 2; i++) {
            int f   = tid + i * 256;
            int row = f >> 2;
            int c8  = (f & 3) * 8;
            uint32_t so = (uint32_t)(row * 80 + c8 * 2);
            CP16(base + OA_HI + so, pah + (size_t)(rowBase + row) * 256 + ko + c8);
            if (needLo)
                CP16(base + OA_LO + so, pal + (size_t)(rowBase + row) * 256 + ko + c8);
        }
        {
            int row = tid >> 2;
            int c8  = (tid & 3) * 8;
            uint32_t so = (uint32_t)(row * 80 + c8 * 2);
            CP16(base + OB_HI + so, Whi + (size_t)(colBase + row) * KTOT + k0 + c8);
            CP16(base + OB_LO + so, Wlo + (size_t)(colBase + row) * KTOT + k0 + c8);
        }
    };

    load_chunk(0, 0);
    CPCOMMIT();

#pragma unroll 1
    for (int c = 0; c < KCHUNKS; ++c) {
        const int s = c & 1;
        CPWAIT0();
        __syncthreads();
        if (c + 1 < KCHUNKS) { load_chunk(c + 1, s ^ 1); CPCOMMIT(); }

        const uint32_t stgBase = sb + (uint32_t)s * STG;
        const bool doLo = !(AGGLO2 && c >= 8);
#pragma unroll
        for (int kk = 0; kk < 32; kk += 16) {
            uint32_t ah[2][4], al[2][4];
#pragma unroll
            for (int mi = 0; mi < 2; mi++) {
                uint32_t ao = (uint32_t)(((aRow + mi * 16) * KS + kk + aColSel) * 2);
                ldsm_x4(ah[mi][0], ah[mi][1], ah[mi][2], ah[mi][3],
                        stgBase + OA_HI + ao);
                if (doLo)
                    ldsm_x4(al[mi][0], al[mi][1], al[mi][2], al[mi][3],
                            stgBase + OA_LO + ao);
            }
            uint32_t b[4][2];
            // W_hi with a_hi (and a_lo when enabled)
            {
                uint32_t r0, r1, r2, r3;
                uint32_t addr = stgBase + OB_HI + (uint32_t)((bRow * KS + kk) * 2);
                ldsm_x4(r0, r1, r2, r3, addr);
                b[0][0] = r0; b[1][0] = r1; b[2][0] = r2; b[3][0] = r3;
                addr += 16;
                ldsm_x4(r0, r1, r2, r3, addr);
                b[0][1] = r0; b[1][1] = r1; b[2][1] = r2; b[3][1] = r3;
            }
#pragma unroll
            for (int mi = 0; mi < 2; mi++)
#pragma unroll
                for (int ni = 0; ni < 4; ni++)
                    mma_f16(acc[mi][ni], ah[mi], b[ni]);
            if (doLo) {
#pragma unroll
                for (int mi = 0; mi < 2; mi++)
#pragma unroll
                    for (int ni = 0; ni < 4; ni++)
                        mma_f16(acc[mi][ni], al[mi], b[ni]);
            }
            // W_lo with a_hi
            {
                uint32_t r0, r1, r2, r3;
                uint32_t addr = stgBase + OB_LO + (uint32_t)((bRow * KS + kk) * 2);
                ldsm_x4(r0, r1, r2, r3, addr);
                b[0][0] = r0; b[1][0] = r1; b[2][0] = r2; b[3][0] = r3;
                addr += 16;
                ldsm_x4(r0, r1, r2, r3, addr);
                b[0][1] = r0; b[1][1] = r1; b[2][1] = r2; b[3][1] = r3;
            }
#pragma unroll
            for (int mi = 0; mi < 2; mi++)
#pragma unroll
                for (int ni = 0; ni < 4; ni++)
                    mma_f16(acc[mi][ni], ah[mi], b[ni]);
        }
        __syncthreads();
    }

    // ---- epilogue ----
#pragma unroll
    for (int mi = 0; mi < 2; mi++) {
        int row0 = rowBase + wm + mi * 16 + (lane >> 2);
        int row1 = row0 + 8;
#pragma unroll
        for (int ni = 0; ni < 4; ni++) {
            int col = colBase + wn + ni * 8 + (lane & 3) * 2;
            float bx = 0.f, by = 0.f;
            if (HAS_BIAS) { bx = __ldg(bias + col); by = __ldg(bias + col + 1); }
            float2 o0 = make_float2(acc[mi][ni][0] + bx, acc[mi][ni][1] + by);
            float2 o1 = make_float2(acc[mi][ni][2] + bx, acc[mi][ni][3] + by);
            if (RELU) {
                o0.x = fmaxf(o0.x, 0.f); o0.y = fmaxf(o0.y, 0.f);
                o1.x = fmaxf(o1.x, 0.f); o1.y = fmaxf(o1.y, 0.f);
            }
            if (OUTF32) {
                *(float2*)(C + (size_t)row0 * 256 + col) = o0;
                *(float2*)(C + (size_t)row1 * 256 + col) = o1;
            } else {
                float hx = __half2float(__float2half_rn(o0.x));
                float hy = __half2float(__float2half_rn(o0.y));
                *(uint32_t*)(Chi + (size_t)row0 * 256 + col) = pack_f16x2(o0.x, o0.y);
                *(uint32_t*)(Clo + (size_t)row0 * 256 + col) =
                    pack_f16x2(o0.x - hx, o0.y - hy);
                hx = __half2float(__float2half_rn(o1.x));
                hy = __half2float(__float2half_rn(o1.y));
                *(uint32_t*)(Chi + (size_t)row1 * 256 + col) = pack_f16x2(o1.x, o1.y);
                *(uint32_t*)(Clo + (size_t)row1 * 256 + col) =
                    pack_f16x2(o1.x - hx, o1.y - hy);
            }
        }
    }
}

// ---------------------------------------------------------------------------
// CSR build
// ---------------------------------------------------------------------------
__global__ void zero_cnt_kernel() {
    int i = blockIdx.x * blockDim.x + threadIdx.x;
    if (i < N_NODES) { g_degi[i] = 0; g_cnt[i] = 0; }
}

__global__ void hist_kernel(const int* __restrict__ src, const int* __restrict__ dst) {
    int e = blockIdx.x * blockDim.x + threadIdx.x;
    if (e < E_EDGES) {
        atomicAdd(&g_degi[src[e]], 1);
        atomicAdd(&g_cnt[dst[e]], 1);
    }
}

__global__ void dis_kernel() {
    int i = blockIdx.x * blockDim.x + threadIdx.x;
    if (i < N_NODES) {
        int d = g_degi[i];
        g_dis[i] = (d > 0) ? rsqrtf((float)d) : 0.0f;
    }
}

__global__ void partial_kernel() {
    __shared__ int sh[256];
    int i = blockIdx.x * 256 + threadIdx.x;
    sh[threadIdx.x] = (i < N_NODES) ? g_cnt[i] : 0;
    __syncthreads();
#pragma unroll
    for (int o = 128; o > 0; o >>= 1) {
        if (threadIdx.x < o) sh[threadIdx.x] += sh[threadIdx.x + o];
        __syncthreads();
    }
    if (threadIdx.x == 0) g_bsum[blockIdx.x] = sh[0];
}

__global__ void scan_blocks_kernel() {
    __shared__ int sh[256];
    int tid = threadIdx.x;
    int v = (tid < NBLK) ? g_bsum[tid] : 0;
    sh[tid] = v;
    __syncthreads();
#pragma unroll
    for (int o = 1; o < 256; o <<= 1) {
        int t = (tid >= o) ? sh[tid - o] : 0;
        __syncthreads();
        sh[tid] += t;
        __syncthreads();
    }
    g_boff[tid] = sh[tid] - v;
}

__global__ void apply_kernel() {
    __shared__ int sh[256];
    int tid = threadIdx.x;
    int i = blockIdx.x * 256 + tid;
    int v = (i < N_NODES) ? g_cnt[i] : 0;
    sh[tid] = v;
    __syncthreads();
#pragma unroll
    for (int o = 1; o < 256; o <<= 1) {
        int t = (tid >= o) ? sh[tid - o] : 0;
        __syncthreads();
        sh[tid] += t;
        __syncthreads();
    }
    if (i < N_NODES) {
        int excl = sh[tid] - v + g_boff[blockIdx.x];
        g_rowstart[i] = excl;
        g_cursor[i]   = excl;
    }
}

__global__ void fill_kernel(const int* __restrict__ src, const int* __restrict__ dst) {
    int e = blockIdx.x * blockDim.x + threadIdx.x;
    if (e < E_EDGES) {
        int s = src[e], d = dst[e];
        int pos = atomicAdd(&g_cursor[d], 1);
        g_csr_src[pos] = s;
        g_csr_w[pos]   = -g_dis[s] * g_dis[d];
    }
}

// ---------------------------------------------------------------------------
// Gather (hi-only input): agg[n] = sum_e w_e * hi[src_e].
// Output written as exact fp16 hi/lo split of the fp32 accumulator.
// ---------------------------------------------------------------------------
__global__ __launch_bounds__(256)
void gather_kernel(const u16* __restrict__ hi,
                   u16* __restrict__ outhi, u16* __restrict__ outlo)
{
    int node = (blockIdx.x * blockDim.x + threadIdx.x) >> 5;
    int lane = threadIdx.x & 31;
    if (node >= N_NODES) return;

    float a[8] = {0.f, 0.f, 0.f, 0.f, 0.f, 0.f, 0.f, 0.f};

    int p   = g_rowstart[node];
    int end = p + g_cnt[node];

#pragma unroll 1
    for (; p + 3 < end; p += 4) {
        int   s0 = __ldg(&g_csr_src[p]);
        int   s1 = __ldg(&g_csr_src[p + 1]);
        int   s2 = __ldg(&g_csr_src[p + 2]);
        int   s3 = __ldg(&g_csr_src[p + 3]);
        float w0 = __ldg(&g_csr_w[p]);
        float w1 = __ldg(&g_csr_w[p + 1]);
        float w2 = __ldg(&g_csr_w[p + 2]);
        float w3 = __ldg(&g_csr_w[p + 3]);
        uint4 h0 = *(const uint4*)(hi + (size_t)s0 * 256 + lane * 8);
        uint4 h1 = *(const uint4*)(hi + (size_t)s1 * 256 + lane * 8);
        uint4 h2 = *(const uint4*)(hi + (size_t)s2 * 256 + lane * 8);
        uint4 h3 = *(const uint4*)(hi + (size_t)s3 * 256 + lane * 8);
#pragma unroll
        for (int q = 0; q < 4; q++) {
            float2 f0 = f16x2_to_f2((&h0.x)[q]);
            float2 f1 = f16x2_to_f2((&h1.x)[q]);
            float2 f2 = f16x2_to_f2((&h2.x)[q]);
            float2 f3 = f16x2_to_f2((&h3.x)[q]);
            a[q*2]   = fmaf(w0, f0.x, a[q*2]);
            a[q*2+1] = fmaf(w0, f0.y, a[q*2+1]);
            a[q*2]   = fmaf(w1, f1.x, a[q*2]);
            a[q*2+1] = fmaf(w1, f1.y, a[q*2+1]);
            a[q*2]   = fmaf(w2, f2.x, a[q*2]);
            a[q*2+1] = fmaf(w2, f2.y, a[q*2+1]);
            a[q*2]   = fmaf(w3, f3.x, a[q*2]);
            a[q*2+1] = fmaf(w3, f3.y, a[q*2+1]);
        }
    }
#pragma unroll 1
    for (; p < end; ++p) {
        int   s0 = __ldg(&g_csr_src[p]);
        float w0 = __ldg(&g_csr_w[p]);
        uint4 h0 = *(const uint4*)(hi + (size_t)s0 * 256 + lane * 8);
#pragma unroll
        for (int q = 0; q < 4; q++) {
            float2 f0 = f16x2_to_f2((&h0.x)[q]);
            a[q*2]   = fmaf(w0, f0.x, a[q*2]);
            a[q*2+1] = fmaf(w0, f0.y, a[q*2+1]);
        }
    }

    uint4 hh, ll;
#pragma unroll
    for (int q = 0; q < 4; q++) {
        float x0 = a[q*2], x1 = a[q*2+1];
        float h0 = __half2float(__float2half_rn(x0));
        float h1 = __half2float(__float2half_rn(x1));
        (&hh.x)[q] = pack_f16x2(x0, x1);
        (&ll.x)[q] = pack_f16x2(x0 - h0, x1 - h1);
    }
    __stcs((uint4*)(outhi + (size_t)node * 256 + lane * 8), hh);
    __stcs((uint4*)(outlo + (size_t)node * 256 + lane * 8), ll);
}

// ---------------------------------------------------------------------------
// Head
// ---------------------------------------------------------------------------
__global__ __launch_bounds__(256)
void head_kernel(const float* __restrict__ h, const float* __restrict__ W4,
                 const float* __restrict__ b4, float* __restrict__ out)
{
    int warp = (blockIdx.x * blockDim.x + threadIdx.x) >> 5;
    int lane = threadIdx.x & 31;
    if (warp >= N_NODES) return;

    const float* hr = h + (size_t)warp * 256;
    float s0 = 0.f, s1 = 0.f;
#pragma unroll
    for (int i = 0; i < 8; i++) {
        int c = lane + i * 32;
        float v = hr[c];
        s0 = fmaf(v, W4[c],       s0);
        s1 = fmaf(v, W4[256 + c], s1);
    }
#pragma unroll
    for (int o = 16; o > 0; o >>= 1) {
        s0 += __shfl_down_sync(0xFFFFFFFFu, s0, o);
        s1 += __shfl_down_sync(0xFFFFFFFFu, s1, o);
    }
    if (lane == 0) {
        out[(size_t)warp * 2 + 0] = s0 + b4[0];
        out[(size_t)warp * 2 + 1] = s1 + b4[1];
    }
}

// ---------------------------------------------------------------------------
// Launch sequence (single stream — capture-safe)
// ---------------------------------------------------------------------------
extern "C" void kernel_launch(void* const* d_in, const int* in_sizes, int n_in,
                              void* d_out, int out_size)
{
    const float* x    = (const float*)d_in[0];
    const int*   ei   = (const int*)  d_in[1];
    const float* W1   = (const float*)d_in[2];
    const float* b1   = (const float*)d_in[3];
    const float* W2   = (const float*)d_in[4];
    const float* b2   = (const float*)d_in[5];
    const float* W3   = (const float*)d_in[6];
    const float* b3   = (const float*)d_in[7];
    const float* W4   = (const float*)d_in[8];
    const float* b4   = (const float*)d_in[9];
    const float* T10  = (const float*)d_in[10];
    const float* T11  = (const float*)d_in[11];
    const float* cb1  = (const float*)d_in[12];
    const float* T20  = (const float*)d_in[13];
    const float* T21  = (const float*)d_in[14];
    const float* cb2  = (const float*)d_in[15];
    float* out = (float*)d_out;

    const int* src = ei;
    const int* dst = ei + E_EDGES;

    float *h3;
    u16 *xhi, *xlo, *h1hi, *h1lo, *h2hi, *h2lo, *aghi, *aglo;
    u16 *o1hi, *o1lo, *o2hi, *o2lo, *whi, *wlo;
    u16 *wc1hi, *wc1lo, *wc2hi, *wc2lo;
    cudaGetSymbolAddress((void**)&h3, g_h3);
    cudaGetSymbolAddress((void**)&xhi, g_xhi);
    cudaGetSymbolAddress((void**)&xlo, g_xlo);
    cudaGetSymbolAddress((void**)&h1hi, g_h1hi);
    cudaGetSymbolAddress((void**)&h1lo, g_h1lo);
    cudaGetSymbolAddress((void**)&h2hi, g_h2hi);
    cudaGetSymbolAddress((void**)&h2lo, g_h2lo);
    cudaGetSymbolAddress((void**)&aghi, g_aghi);
    cudaGetSymbolAddress((void**)&aglo, g_aglo);
    cudaGetSymbolAddress((void**)&o1hi, g_o1hi);
    cudaGetSymbolAddress((void**)&o1lo, g_o1lo);
    cudaGetSymbolAddress((void**)&o2hi, g_o2hi);
    cudaGetSymbolAddress((void**)&o2lo, g_o2lo);
    cudaGetSymbolAddress((void**)&whi, g_whi);
    cudaGetSymbolAddress((void**)&wlo, g_wlo);
    cudaGetSymbolAddress((void**)&wc1hi, g_wc1hi);
    cudaGetSymbolAddress((void**)&wc1lo, g_wc1lo);
    cudaGetSymbolAddress((void**)&wc2hi, g_wc2hi);
    cudaGetSymbolAddress((void**)&wc2lo, g_wc2lo);

    const int WSZ = HDIM * HDIM;
    const int SMEMSZ = 2 * STG;   // 61440

    cudaFuncSetAttribute(gemm_mma_kernel<8,  true,  true, false, false>,
                         cudaFuncAttributeMaxDynamicSharedMemorySize, SMEMSZ);
    cudaFuncSetAttribute(gemm_mma_kernel<16, false, true, false, true>,
                         cudaFuncAttributeMaxDynamicSharedMemorySize, SMEMSZ);
    cudaFuncSetAttribute(gemm_mma_kernel<8,  true,  true, true, false>,
                         cudaFuncAttributeMaxDynamicSharedMemorySize, SMEMSZ);

    dim3 ggrid(MPAD / BM, 4);    // (391, 4)
    const int gthr  = (N_NODES * 32 + 255) / 256;
    const int wblk  = (WSZ / 4 + 255) / 256;

    // --- input splits + MLP GEMMs ---
    split_kernel<<<(N_NODES * HDIM / 4 + 255) / 256, 256>>>(x, xhi, xlo,
                                                            N_NODES * HDIM / 4);
    split_kernel<<<wblk, 256>>>(W1, whi + 0 * WSZ, wlo + 0 * WSZ, WSZ / 4);
    split_kernel<<<wblk, 256>>>(W2, whi + 1 * WSZ, wlo + 1 * WSZ, WSZ / 4);
    gemm_mma_kernel<8, true, true, false, false><<<ggrid, 256, SMEMSZ>>>(
        xhi, xlo, nullptr, nullptr, whi + 0 * WSZ, wlo + 0 * WSZ, b1,
        nullptr, h1hi, h1lo);
    gemm_mma_kernel<8, true, true, false, false><<<ggrid, 256, SMEMSZ>>>(
        h1hi, h1lo, nullptr, nullptr, whi + 1 * WSZ, wlo + 1 * WSZ, b2,
        nullptr, h2hi, h2lo);

    // --- CSR + remaining weight prep ---
    zero_cnt_kernel<<<(N_NODES + 255) / 256, 256>>>();
    hist_kernel<<<(E_EDGES + 255) / 256, 256>>>(src, dst);
    dis_kernel<<<(N_NODES + 255) / 256, 256>>>();
    partial_kernel<<<NBLK, 256>>>();
    scan_blocks_kernel<<<1, 256>>>();
    apply_kernel<<<NBLK, 256>>>();
    fill_kernel<<<(E_EDGES + 255) / 256, 256>>>(src, dst);

    split_w512_kernel<<<wblk, 256>>>(T10, wc1hi, wc1lo, 0);
    split_w512_kernel<<<wblk, 256>>>(T11, wc1hi, wc1lo, 256);
    split_w512_kernel<<<wblk, 256>>>(T20, wc2hi, wc2lo, 0);
    split_w512_kernel<<<wblk, 256>>>(T21, wc2hi, wc2lo, 256);
    split_kernel<<<wblk, 256>>>(W3, whi + 2 * WSZ, wlo + 2 * WSZ, WSZ / 4);

    // --- conv 1: agg = S h2 (hi-only) ; out1 = [h2, agg] @ [T10;T11]^T + cb1 ---
    gather_kernel<<<gthr, 256>>>(h2hi, aghi, aglo);
    gemm_mma_kernel<16, false, true, false, true><<<ggrid, 256, SMEMSZ>>>(
        h2hi, h2lo, aghi, aglo, wc1hi, wc1lo, cb1, nullptr, o1hi, o1lo);

    // --- conv 2: agg = S out1 (hi-only) ; out2 = [out1, agg] @ [T20;T21]^T + cb2 ---
    gather_kernel<<<gthr, 256>>>(o1hi, aghi, aglo);
    gemm_mma_kernel<16, false, true, false, true><<<ggrid, 256, SMEMSZ>>>(
        o1hi, o1lo, aghi, aglo, wc2hi, wc2lo, cb2, nullptr, o2hi, o2lo);

    // --- h3 = relu(out2@W3^T + b3) ; out = h3@W4^T + b4 ---
    gemm_mma_kernel<8, true, true, true, false><<<ggrid, 256, SMEMSZ>>>(
        o2hi, o2lo, nullptr, nullptr, whi + 2 * WSZ, wlo + 2 * WSZ, b3,
        h3, nullptr, nullptr);
    head_kernel<<<gthr, 256>>>(h3, W4, b4, out);
}

// round 13
// speedup vs baseline: 1.2164x; 1.0422x over previous
#include <cuda_runtime.h>
#include <cuda_fp16.h>
#include <cstdint>

#define N_NODES 50000
#define MPAD    50048
#define E_EDGES 1600000
#define HDIM    256
#define NBLK    196
#define WSZ     (HDIM * HDIM)

typedef unsigned short u16;

// ---------------------------------------------------------------------------
// Static device scratch
// ---------------------------------------------------------------------------
__device__ int   g_degi[N_NODES];
__device__ int   g_cnt[N_NODES];
__device__ int   g_rowstart[N_NODES];
__device__ int   g_cursor[N_NODES];
__device__ float g_dis[N_NODES];
__device__ int   g_csr_src[E_EDGES];
__device__ float g_csr_w[E_EDGES];
__device__ int   g_bsum[256];
__device__ int   g_boff[256];

// fp16 activation pairs
__device__ u16 g_xhi[(size_t)MPAD * HDIM];
__device__ u16 g_xlo[(size_t)MPAD * HDIM];
__device__ u16 g_h1hi[(size_t)MPAD * HDIM];
__device__ u16 g_h1lo[(size_t)MPAD * HDIM];
__device__ u16 g_h2hi[(size_t)MPAD * HDIM];
__device__ u16 g_h2lo[(size_t)MPAD * HDIM];
__device__ u16 g_aghi[(size_t)MPAD * HDIM];
__device__ u16 g_o1hi[(size_t)MPAD * HDIM];
__device__ u16 g_o1lo[(size_t)MPAD * HDIM];
__device__ u16 g_o2hi[(size_t)MPAD * HDIM];
__device__ u16 g_o2lo[(size_t)MPAD * HDIM];

// fp16 hi/lo weights: W1,W2,W3 (256 cols) + concat conv weights (512 cols)
__device__ u16 g_whi[3 * WSZ];
__device__ u16 g_wlo[3 * WSZ];
__device__ u16 g_wc1hi[HDIM * 512];
__device__ u16 g_wc1lo[HDIM * 512];
__device__ u16 g_wc2hi[HDIM * 512];
__device__ u16 g_wc2lo[HDIM * 512];

// ---------------------------------------------------------------------------
// helpers
// ---------------------------------------------------------------------------
__device__ __forceinline__ uint32_t pack_f16x2(float lo, float hi) {
    __half2 h = __floats2half2_rn(lo, hi);
    return *reinterpret_cast<uint32_t*>(&h);
}

__device__ __forceinline__ float2 f16x2_to_f2(uint32_t u) {
    __half2 h = *reinterpret_cast<__half2*>(&u);
    return __half22float2(h);
}

__device__ __forceinline__ void ldsm_x4(uint32_t& r0, uint32_t& r1,
                                        uint32_t& r2, uint32_t& r3, uint32_t addr) {
    asm volatile("ldmatrix.sync.aligned.m8n8.x4.shared.b16 {%0,%1,%2,%3}, [%4];"
                 : "=r"(r0), "=r"(r1), "=r"(r2), "=r"(r3) : "r"(addr));
}

__device__ __forceinline__ void mma_f16(float c[4], const uint32_t a[4],
                                        const uint32_t b[2]) {
    asm volatile(
        "mma.sync.aligned.m16n8k16.row.col.f32.f16.f16.f32 "
        "{%0,%1,%2,%3}, {%4,%5,%6,%7}, {%8,%9}, {%0,%1,%2,%3};"
        : "+f"(c[0]), "+f"(c[1]), "+f"(c[2]), "+f"(c[3])
        : "r"(a[0]), "r"(a[1]), "r"(a[2]), "r"(a[3]), "r"(b[0]), "r"(b[1]));
}

#define CP16(sm, gp) \
    asm volatile("cp.async.cg.shared.global [%0], [%1], 16;" :: "r"(sm), "l"(gp))
#define CPCOMMIT() asm volatile("cp.async.commit_group;")
#define CPWAIT0()  asm volatile("cp.async.wait_group 0;")

// ---------------------------------------------------------------------------
// splits
// ---------------------------------------------------------------------------
__global__ void split_kernel(const float* __restrict__ in, u16* __restrict__ hi,
                             u16* __restrict__ lo, int n4)
{
    int i = blockIdx.x * blockDim.x + threadIdx.x;
    if (i >= n4) return;
    float4 v = ((const float4*)in)[i];
    float hx = __half2float(__float2half_rn(v.x));
    float hy = __half2float(__float2half_rn(v.y));
    float hz = __half2float(__float2half_rn(v.z));
    float hw = __half2float(__float2half_rn(v.w));
    uint2 h = make_uint2(pack_f16x2(v.x, v.y), pack_f16x2(v.z, v.w));
    uint2 l = make_uint2(pack_f16x2(v.x - hx, v.y - hy),
                         pack_f16x2(v.z - hz, v.w - hw));
    ((uint2*)hi)[i] = h;
    ((uint2*)lo)[i] = l;
}

// One launch splits all 7 weight matrices. blockIdx.y selects the matrix:
// 0..2 -> W1,W2,W3 (contiguous 256-col), 3..6 -> T10,T11,T20,T21 (512-col concat).
__global__ void split_all_w_kernel(const float* __restrict__ W1,
                                   const float* __restrict__ W2,
                                   const float* __restrict__ W3,
                                   const float* __restrict__ T10,
                                   const float* __restrict__ T11,
                                   const float* __restrict__ T20,
                                   const float* __restrict__ T21)
{
    int i = blockIdx.x * blockDim.x + threadIdx.x;
    if (i >= WSZ / 4) return;
    int w = blockIdx.y;
    const float* src = (w == 0) ? W1 : (w == 1) ? W2 : (w == 2) ? W3 :
                       (w == 3) ? T10 : (w == 4) ? T11 : (w == 5) ? T20 : T21;
    float4 v = ((const float4*)src)[i];
    float hx = __half2float(__float2half_rn(v.x));
    float hy = __half2float(__float2half_rn(v.y));
    float hz = __half2float(__float2half_rn(v.z));
    float hw = __half2float(__float2half_rn(v.w));
    uint2 h = make_uint2(pack_f16x2(v.x, v.y), pack_f16x2(v.z, v.w));
    uint2 l = make_uint2(pack_f16x2(v.x - hx, v.y - hy),
                         pack_f16x2(v.z - hz, v.w - hw));
    if (w < 3) {
        ((uint2*)(g_whi + (size_t)w * WSZ))[i] = h;
        ((uint2*)(g_wlo + (size_t)w * WSZ))[i] = l;
    } else {
        int row = i >> 6;
        int col = (i & 63) * 4;
        int colofs = ((w - 3) & 1) * 256;
        u16* dhi = (w < 5) ? g_wc1hi : g_wc2hi;
        u16* dlo = (w < 5) ? g_wc1lo : g_wc2lo;
        size_t o = (size_t)row * 512 + colofs + col;
        *(uint2*)(dhi + o) = h;
        *(uint2*)(dlo + o) = l;
    }
}

// ---------------------------------------------------------------------------
// GEMM: C[MPAD, colBase:+64] = (Ahi+Alo) @ (Whi+Wlo)[colBase:+64]^T
// 3-pass exact fp16 split; AGGLO2: chunks >= 8 run 2-pass (skip a_lo*W_hi).
// OMODE 0: write fp16 hi/lo pair. OMODE 1: fused head — accumulate
// relu(acc+b3) . W4 partial dots and atomicAdd into out[row*2 + cls].
// Tile 128x64x32, 256 thr, warp tile 32x32, 3 CTAs/SM, 2-stage cp.async.
// ---------------------------------------------------------------------------
#define BM   128
#define KS   40
#define STG  30720
#define OA_HI 0
#define OA_LO 10240
#define OB_HI 20480
#define OB_LO 25600

template <int KCHUNKS, bool RELU, int OMODE, bool AGGLO2>
__global__ __launch_bounds__(256, 3)
void gemm_mma_kernel(const u16* __restrict__ Ahi, const u16* __restrict__ Alo,
                     const u16* __restrict__ A2hi, const u16* __restrict__ A2lo,
                     const u16* __restrict__ Whi, const u16* __restrict__ Wlo,
                     const float* __restrict__ bias,
                     u16* __restrict__ Chi, u16* __restrict__ Clo,
                     const float* __restrict__ W4v, float* __restrict__ outp)
{
    extern __shared__ char smem[];
    const uint32_t sb = (uint32_t)__cvta_generic_to_shared(smem);
    const int tid  = threadIdx.x;
    const int lane = tid & 31;
    const int wid  = tid >> 5;
    const int wm   = (wid & 3) * 32;
    const int wn   = (wid >> 2) * 32;
    const int rowBase = blockIdx.x * BM;
    const int colBase = blockIdx.y * 64;
    const int KTOT = KCHUNKS * 32;

    float acc[2][4][4];
#pragma unroll
    for (int mi = 0; mi < 2; mi++)
#pragma unroll
        for (int ni = 0; ni < 4; ni++)
#pragma unroll
            for (int j = 0; j < 4; j++) acc[mi][ni][j] = 0.0f;

    const int aRow = wm + (lane & 15);
    const int aColSel = (lane >> 4) * 8;
    const int bRow = wn + lane;

    auto load_chunk = [&](int c, int s) {
        uint32_t base = sb + (uint32_t)s * STG;
        const u16* pah = (c < 8) ? Ahi : A2hi;
        const u16* pal = (c < 8) ? Alo : A2lo;
        int ko = (c & 7) * 32;
        int k0 = c * 32;
        bool needLo = !(AGGLO2 && c >= 8);
#pragma unroll
        for (int i = 0; i < 2; i++) {
            int f   = tid + i * 256;
            int row = f >> 2;
            int c8  = (f & 3) * 8;
            uint32_t so = (uint32_t)(row * 80 + c8 * 2);
            CP16(base + OA_HI + so, pah + (size_t)(rowBase + row) * 256 + ko + c8);
            if (needLo)
                CP16(base + OA_LO + so, pal + (size_t)(rowBase + row) * 256 + ko + c8);
        }
        {
            int row = tid >> 2;
            int c8  = (tid & 3) * 8;
            uint32_t so = (uint32_t)(row * 80 + c8 * 2);
            CP16(base + OB_HI + so, Whi + (size_t)(colBase + row) * KTOT + k0 + c8);
            CP16(base + OB_LO + so, Wlo + (size_t)(colBase + row) * KTOT + k0 + c8);
        }
    };

    load_chunk(0, 0);
    CPCOMMIT();

#pragma unroll 1
    for (int c = 0; c < KCHUNKS; ++c) {
        const int s = c & 1;
        CPWAIT0();
        __syncthreads();
        if (c + 1 < KCHUNKS) { load_chunk(c + 1, s ^ 1); CPCOMMIT(); }

        const uint32_t stgBase = sb + (uint32_t)s * STG;
        const bool doLo = !(AGGLO2 && c >= 8);
#pragma unroll
        for (int kk = 0; kk < 32; kk += 16) {
            uint32_t ah[2][4], al[2][4];
#pragma unroll
            for (int mi = 0; mi < 2; mi++) {
                uint32_t ao = (uint32_t)(((aRow + mi * 16) * KS + kk + aColSel) * 2);
                ldsm_x4(ah[mi][0], ah[mi][1], ah[mi][2], ah[mi][3],
                        stgBase + OA_HI + ao);
                if (doLo)
                    ldsm_x4(al[mi][0], al[mi][1], al[mi][2], al[mi][3],
                            stgBase + OA_LO + ao);
            }
            uint32_t b[4][2];
            // W_hi with a_hi (and a_lo when enabled)
            {
                uint32_t r0, r1, r2, r3;
                uint32_t addr = stgBase + OB_HI + (uint32_t)((bRow * KS + kk) * 2);
                ldsm_x4(r0, r1, r2, r3, addr);
                b[0][0] = r0; b[1][0] = r1; b[2][0] = r2; b[3][0] = r3;
                addr += 16;
                ldsm_x4(r0, r1, r2, r3, addr);
                b[0][1] = r0; b[1][1] = r1; b[2][1] = r2; b[3][1] = r3;
            }
#pragma unroll
            for (int mi = 0; mi < 2; mi++)
#pragma unroll
                for (int ni = 0; ni < 4; ni++)
                    mma_f16(acc[mi][ni], ah[mi], b[ni]);
            if (doLo) {
#pragma unroll
                for (int mi = 0; mi < 2; mi++)
#pragma unroll
                    for (int ni = 0; ni < 4; ni++)
                        mma_f16(acc[mi][ni], al[mi], b[ni]);
            }
            // W_lo with a_hi
            {
                uint32_t r0, r1, r2, r3;
                uint32_t addr = stgBase + OB_LO + (uint32_t)((bRow * KS + kk) * 2);
                ldsm_x4(r0, r1, r2, r3, addr);
                b[0][0] = r0; b[1][0] = r1; b[2][0] = r2; b[3][0] = r3;
                addr += 16;
                ldsm_x4(r0, r1, r2, r3, addr);
                b[0][1] = r0; b[1][1] = r1; b[2][1] = r2; b[3][1] = r3;
            }
#pragma unroll
            for (int mi = 0; mi < 2; mi++)
#pragma unroll
                for (int ni = 0; ni < 4; ni++)
                    mma_f16(acc[mi][ni], ah[mi], b[ni]);
        }
        __syncthreads();
    }

    // ---- epilogue ----
#pragma unroll
    for (int mi = 0; mi < 2; mi++) {
        int row0 = rowBase + wm + mi * 16 + (lane >> 2);
        int row1 = row0 + 8;
        float p00 = 0.f, p01 = 0.f, p10 = 0.f, p11 = 0.f;
#pragma unroll
        for (int ni = 0; ni < 4; ni++) {
            int col = colBase + wn + ni * 8 + (lane & 3) * 2;
            float bx = __ldg(bias + col), by = __ldg(bias + col + 1);
            float2 o0 = make_float2(acc[mi][ni][0] + bx, acc[mi][ni][1] + by);
            float2 o1 = make_float2(acc[mi][ni][2] + bx, acc[mi][ni][3] + by);
            if (RELU) {
                o0.x = fmaxf(o0.x, 0.f); o0.y = fmaxf(o0.y, 0.f);
                o1.x = fmaxf(o1.x, 0.f); o1.y = fmaxf(o1.y, 0.f);
            }
            if (OMODE == 0) {
                float hx = __half2float(__float2half_rn(o0.x));
                float hy = __half2float(__float2half_rn(o0.y));
                *(uint32_t*)(Chi + (size_t)row0 * 256 + col) = pack_f16x2(o0.x, o0.y);
                *(uint32_t*)(Clo + (size_t)row0 * 256 + col) =
                    pack_f16x2(o0.x - hx, o0.y - hy);
                hx = __half2float(__float2half_rn(o1.x));
                hy = __half2float(__float2half_rn(o1.y));
                *(uint32_t*)(Chi + (size_t)row1 * 256 + col) = pack_f16x2(o1.x, o1.y);
                *(uint32_t*)(Clo + (size_t)row1 * 256 + col) =
                    pack_f16x2(o1.x - hx, o1.y - hy);
            } else {
                float wa = __ldg(W4v + col),       wb = __ldg(W4v + col + 1);
                float wc = __ldg(W4v + 256 + col), wd = __ldg(W4v + 256 + col + 1);
                p00 = fmaf(o0.x, wa, fmaf(o0.y, wb, p00));
                p01 = fmaf(o0.x, wc, fmaf(o0.y, wd, p01));
                p10 = fmaf(o1.x, wa, fmaf(o1.y, wb, p10));
                p11 = fmaf(o1.x, wc, fmaf(o1.y, wd, p11));
            }
        }
        if (OMODE == 1) {
            // reduce across the 4 lanes (lane&3) sharing the same rows
            p00 += __shfl_xor_sync(0xFFFFFFFFu, p00, 1);
            p00 += __shfl_xor_sync(0xFFFFFFFFu, p00, 2);
            p01 += __shfl_xor_sync(0xFFFFFFFFu, p01, 1);
            p01 += __shfl_xor_sync(0xFFFFFFFFu, p01, 2);
            p10 += __shfl_xor_sync(0xFFFFFFFFu, p10, 1);
            p10 += __shfl_xor_sync(0xFFFFFFFFu, p10, 2);
            p11 += __shfl_xor_sync(0xFFFFFFFFu, p11, 1);
            p11 += __shfl_xor_sync(0xFFFFFFFFu, p11, 2);
            if ((lane & 3) == 0) {
                if (row0 < N_NODES) {
                    atomicAdd(outp + (size_t)row0 * 2,     p00);
                    atomicAdd(outp + (size_t)row0 * 2 + 1, p01);
                }
                if (row1 < N_NODES) {
                    atomicAdd(outp + (size_t)row1 * 2,     p10);
                    atomicAdd(outp + (size_t)row1 * 2 + 1, p11);
                }
            }
        }
    }
}

// ---------------------------------------------------------------------------
// CSR build
// ---------------------------------------------------------------------------
__global__ void zero_cnt_kernel() {
    int i = blockIdx.x * blockDim.x + threadIdx.x;
    if (i < N_NODES) { g_degi[i] = 0; g_cnt[i] = 0; }
}

__global__ void hist_kernel(const int* __restrict__ src, const int* __restrict__ dst) {
    int e = blockIdx.x * blockDim.x + threadIdx.x;
    if (e < E_EDGES) {
        atomicAdd(&g_degi[src[e]], 1);
        atomicAdd(&g_cnt[dst[e]], 1);
    }
}

// fused: dis computation + per-block partial sums of g_cnt
__global__ void partial_dis_kernel() {
    __shared__ int sh[256];
    int i = blockIdx.x * 256 + threadIdx.x;
    if (i < N_NODES) {
        int d = g_degi[i];
        g_dis[i] = (d > 0) ? rsqrtf((float)d) : 0.0f;
    }
    sh[threadIdx.x] = (i < N_NODES) ? g_cnt[i] : 0;
    __syncthreads();
#pragma unroll
    for (int o = 128; o > 0; o >>= 1) {
        if (threadIdx.x < o) sh[threadIdx.x] += sh[threadIdx.x + o];
        __syncthreads();
    }
    if (threadIdx.x == 0) g_bsum[blockIdx.x] = sh[0];
}

__global__ void scan_blocks_kernel() {
    __shared__ int sh[256];
    int tid = threadIdx.x;
    int v = (tid < NBLK) ? g_bsum[tid] : 0;
    sh[tid] = v;
    __syncthreads();
#pragma unroll
    for (int o = 1; o < 256; o <<= 1) {
        int t = (tid >= o) ? sh[tid - o] : 0;
        __syncthreads();
        sh[tid] += t;
        __syncthreads();
    }
    g_boff[tid] = sh[tid] - v;
}

__global__ void apply_kernel() {
    __shared__ int sh[256];
    int tid = threadIdx.x;
    int i = blockIdx.x * 256 + tid;
    int v = (i < N_NODES) ? g_cnt[i] : 0;
    sh[tid] = v;
    __syncthreads();
#pragma unroll
    for (int o = 1; o < 256; o <<= 1) {
        int t = (tid >= o) ? sh[tid - o] : 0;
        __syncthreads();
        sh[tid] += t;
        __syncthreads();
    }
    if (i < N_NODES) {
        int excl = sh[tid] - v + g_boff[blockIdx.x];
        g_rowstart[i] = excl;
        g_cursor[i]   = excl;
    }
}

__global__ void fill_kernel(const int* __restrict__ src, const int* __restrict__ dst) {
    int e = blockIdx.x * blockDim.x + threadIdx.x;
    if (e < E_EDGES) {
        int s = src[e], d = dst[e];
        int pos = atomicAdd(&g_cursor[d], 1);
        g_csr_src[pos] = s;
        g_csr_w[pos]   = -g_dis[s] * g_dis[d];
    }
}

// ---------------------------------------------------------------------------
// Gather (hi-only input AND hi-only output; the lo half of agg is never
// consumed by the AGGLO2 conv GEMMs).
// ---------------------------------------------------------------------------
__global__ __launch_bounds__(256)
void gather_kernel(const u16* __restrict__ hi, u16* __restrict__ outhi)
{
    int node = (blockIdx.x * blockDim.x + threadIdx.x) >> 5;
    int lane = threadIdx.x & 31;
    if (node >= N_NODES) return;

    float a[8] = {0.f, 0.f, 0.f, 0.f, 0.f, 0.f, 0.f, 0.f};

    int p   = g_rowstart[node];
    int end = p + g_cnt[node];

#pragma unroll 1
    for (; p + 3 < end; p += 4) {
        int   s0 = __ldg(&g_csr_src[p]);
        int   s1 = __ldg(&g_csr_src[p + 1]);
        int   s2 = __ldg(&g_csr_src[p + 2]);
        int   s3 = __ldg(&g_csr_src[p + 3]);
        float w0 = __ldg(&g_csr_w[p]);
        float w1 = __ldg(&g_csr_w[p + 1]);
        float w2 = __ldg(&g_csr_w[p + 2]);
        float w3 = __ldg(&g_csr_w[p + 3]);
        uint4 h0 = *(const uint4*)(hi + (size_t)s0 * 256 + lane * 8);
        uint4 h1 = *(const uint4*)(hi + (size_t)s1 * 256 + lane * 8);
        uint4 h2 = *(const uint4*)(hi + (size_t)s2 * 256 + lane * 8);
        uint4 h3 = *(const uint4*)(hi + (size_t)s3 * 256 + lane * 8);
#pragma unroll
        for (int q = 0; q < 4; q++) {
            float2 f0 = f16x2_to_f2((&h0.x)[q]);
            float2 f1 = f16x2_to_f2((&h1.x)[q]);
            float2 f2 = f16x2_to_f2((&h2.x)[q]);
            float2 f3 = f16x2_to_f2((&h3.x)[q]);
            a[q*2]   = fmaf(w0, f0.x, a[q*2]);
            a[q*2+1] = fmaf(w0, f0.y, a[q*2+1]);
            a[q*2]   = fmaf(w1, f1.x, a[q*2]);
            a[q*2+1] = fmaf(w1, f1.y, a[q*2+1]);
            a[q*2]   = fmaf(w2, f2.x, a[q*2]);
            a[q*2+1] = fmaf(w2, f2.y, a[q*2+1]);
            a[q*2]   = fmaf(w3, f3.x, a[q*2]);
            a[q*2+1] = fmaf(w3, f3.y, a[q*2+1]);
        }
    }
#pragma unroll 1
    for (; p < end; ++p) {
        int   s0 = __ldg(&g_csr_src[p]);
        float w0 = __ldg(&g_csr_w[p]);
        uint4 h0 = *(const uint4*)(hi + (size_t)s0 * 256 + lane * 8);
#pragma unroll
        for (int q = 0; q < 4; q++) {
            float2 f0 = f16x2_to_f2((&h0.x)[q]);
            a[q*2]   = fmaf(w0, f0.x, a[q*2]);
            a[q*2+1] = fmaf(w0, f0.y, a[q*2+1]);
        }
    }

    uint4 hh;
#pragma unroll
    for (int q = 0; q < 4; q++)
        (&hh.x)[q] = pack_f16x2(a[q*2], a[q*2+1]);
    __stcs((uint4*)(outhi + (size_t)node * 256 + lane * 8), hh);
}

// out[i] = b4[i&1]  (base for the fused-head atomic accumulation)
__global__ void init_out_kernel(float* __restrict__ out,
                                const float* __restrict__ b4)
{
    int i = blockIdx.x * blockDim.x + threadIdx.x;
    if (i < N_NODES * 2) out[i] = __ldg(b4 + (i & 1));
}

// ---------------------------------------------------------------------------
// Launch sequence (single stream — capture-safe)
// ---------------------------------------------------------------------------
extern "C" void kernel_launch(void* const* d_in, const int* in_sizes, int n_in,
                              void* d_out, int out_size)
{
    const float* x    = (const float*)d_in[0];
    const int*   ei   = (const int*)  d_in[1];
    const float* W1   = (const float*)d_in[2];
    const float* b1   = (const float*)d_in[3];
    const float* W2   = (const float*)d_in[4];
    const float* b2   = (const float*)d_in[5];
    const float* W3   = (const float*)d_in[6];
    const float* b3   = (const float*)d_in[7];
    const float* W4   = (const float*)d_in[8];
    const float* b4   = (const float*)d_in[9];
    const float* T10  = (const float*)d_in[10];
    const float* T11  = (const float*)d_in[11];
    const float* cb1  = (const float*)d_in[12];
    const float* T20  = (const float*)d_in[13];
    const float* T21  = (const float*)d_in[14];
    const float* cb2  = (const float*)d_in[15];
    float* out = (float*)d_out;

    const int* src = ei;
    const int* dst = ei + E_EDGES;

    u16 *xhi, *xlo, *h1hi, *h1lo, *h2hi, *h2lo, *aghi;
    u16 *o1hi, *o1lo, *o2hi, *o2lo, *whi, *wlo;
    u16 *wc1hi, *wc1lo, *wc2hi, *wc2lo;
    cudaGetSymbolAddress((void**)&xhi, g_xhi);
    cudaGetSymbolAddress((void**)&xlo, g_xlo);
    cudaGetSymbolAddress((void**)&h1hi, g_h1hi);
    cudaGetSymbolAddress((void**)&h1lo, g_h1lo);
    cudaGetSymbolAddress((void**)&h2hi, g_h2hi);
    cudaGetSymbolAddress((void**)&h2lo, g_h2lo);
    cudaGetSymbolAddress((void**)&aghi, g_aghi);
    cudaGetSymbolAddress((void**)&o1hi, g_o1hi);
    cudaGetSymbolAddress((void**)&o1lo, g_o1lo);
    cudaGetSymbolAddress((void**)&o2hi, g_o2hi);
    cudaGetSymbolAddress((void**)&o2lo, g_o2lo);
    cudaGetSymbolAddress((void**)&whi, g_whi);
    cudaGetSymbolAddress((void**)&wlo, g_wlo);
    cudaGetSymbolAddress((void**)&wc1hi, g_wc1hi);
    cudaGetSymbolAddress((void**)&wc1lo, g_wc1lo);
    cudaGetSymbolAddress((void**)&wc2hi, g_wc2hi);
    cudaGetSymbolAddress((void**)&wc2lo, g_wc2lo);

    const int SMEMSZ = 2 * STG;   // 61440

    cudaFuncSetAttribute(gemm_mma_kernel<8,  true,  0, false>,
                         cudaFuncAttributeMaxDynamicSharedMemorySize, SMEMSZ);
    cudaFuncSetAttribute(gemm_mma_kernel<16, false, 0, true>,
                         cudaFuncAttributeMaxDynamicSharedMemorySize, SMEMSZ);
    cudaFuncSetAttribute(gemm_mma_kernel<8,  true,  1, false>,
                         cudaFuncAttributeMaxDynamicSharedMemorySize, SMEMSZ);

    dim3 ggrid(MPAD / BM, 4);    // (391, 4)
    const int gthr = (N_NODES * 32 + 255) / 256;
    const int wblk = (WSZ / 4 + 255) / 256;

    // --- input/weight splits + MLP GEMMs ---
    split_kernel<<<(N_NODES * HDIM / 4 + 255) / 256, 256>>>(x, xhi, xlo,
                                                            N_NODES * HDIM / 4);
    split_all_w_kernel<<<dim3(wblk, 7), 256>>>(W1, W2, W3, T10, T11, T20, T21);
    gemm_mma_kernel<8, true, 0, false><<<ggrid, 256, SMEMSZ>>>(
        xhi, xlo, nullptr, nullptr, whi + 0 * WSZ, wlo + 0 * WSZ, b1,
        h1hi, h1lo, nullptr, nullptr);
    gemm_mma_kernel<8, true, 0, false><<<ggrid, 256, SMEMSZ>>>(
        h1hi, h1lo, nullptr, nullptr, whi + 1 * WSZ, wlo + 1 * WSZ, b2,
        h2hi, h2lo, nullptr, nullptr);

    // --- CSR build ---
    zero_cnt_kernel<<<(N_NODES + 255) / 256, 256>>>();
    hist_kernel<<<(E_EDGES + 255) / 256, 256>>>(src, dst);
    partial_dis_kernel<<<NBLK, 256>>>();
    scan_blocks_kernel<<<1, 256>>>();
    apply_kernel<<<NBLK, 256>>>();
    fill_kernel<<<(E_EDGES + 255) / 256, 256>>>(src, dst);

    // --- conv 1: agg = S h2 (hi-only) ; out1 = [h2, agg] @ [T10;T11]^T + cb1 ---
    gather_kernel<<<gthr, 256>>>(h2hi, aghi);
    gemm_mma_kernel<16, false, 0, true><<<ggrid, 256, SMEMSZ>>>(
        h2hi, h2lo, aghi, nullptr, wc1hi, wc1lo, cb1,
        o1hi, o1lo, nullptr, nullptr);

    // --- conv 2: agg = S out1 (hi-only) ; out2 = [out1, agg] @ [T20;T21]^T + cb2 ---
    gather_kernel<<<gthr, 256>>>(o1hi, aghi);
    gemm_mma_kernel<16, false, 0, true><<<ggrid, 256, SMEMSZ>>>(
        o1hi, o1lo, aghi, nullptr, wc2hi, wc2lo, cb2,
        o2hi, o2lo, nullptr, nullptr);

    // --- fused: out = relu(out2@W3^T + b3) @ W4^T + b4 ---
    init_out_kernel<<<(N_NODES * 2 + 255) / 256, 256>>>(out, b4);
    gemm_mma_kernel<8, true, 1, false><<<ggrid, 256, SMEMSZ>>>(
        o2hi, o2lo, nullptr, nullptr, whi + 2 * WSZ, wlo + 2 * WSZ, b3,
        nullptr, nullptr, W4, out);
}

// round 14
// speedup vs baseline: 1.2674x; 1.0419x over previous
#include <cuda_runtime.h>
#include <cuda_fp16.h>
#include <cstdint>

#define N_NODES 50000
#define MPAD    50048
#define E_EDGES 1600000
#define HDIM    256
#define NBLK    196
#define WSZ     (HDIM * HDIM)

typedef unsigned short u16;

// ---------------------------------------------------------------------------
// Static device scratch
// ---------------------------------------------------------------------------
__device__ int   g_degi[N_NODES];
__device__ int   g_cnt[N_NODES];
__device__ int   g_rowstart[N_NODES];
__device__ int   g_cursor[N_NODES];
__device__ float g_dis[N_NODES];
__device__ int   g_csr_src[E_EDGES];
__device__ float g_csr_w[E_EDGES];
__device__ int   g_bsum[256];
__device__ int   g_boff[256];

// fp16 activation pairs
__device__ u16 g_xhi[(size_t)MPAD * HDIM];
__device__ u16 g_xlo[(size_t)MPAD * HDIM];
__device__ u16 g_h1hi[(size_t)MPAD * HDIM];
__device__ u16 g_h1lo[(size_t)MPAD * HDIM];
__device__ u16 g_h2hi[(size_t)MPAD * HDIM];
__device__ u16 g_h2lo[(size_t)MPAD * HDIM];
__device__ u16 g_aghi[(size_t)MPAD * HDIM];
__device__ u16 g_o1hi[(size_t)MPAD * HDIM];
__device__ u16 g_o1lo[(size_t)MPAD * HDIM];
__device__ u16 g_o2hi[(size_t)MPAD * HDIM];
__device__ u16 g_o2lo[(size_t)MPAD * HDIM];

// fp16 hi/lo weights: W1,W2,W3 (256 cols) + concat conv weights (512 cols)
__device__ u16 g_whi[3 * WSZ];
__device__ u16 g_wlo[3 * WSZ];
__device__ u16 g_wc1hi[HDIM * 512];
__device__ u16 g_wc1lo[HDIM * 512];
__device__ u16 g_wc2hi[HDIM * 512];
__device__ u16 g_wc2lo[HDIM * 512];

// ---------------------------------------------------------------------------
// helpers
// ---------------------------------------------------------------------------
__device__ __forceinline__ uint32_t pack_f16x2(float lo, float hi) {
    __half2 h = __floats2half2_rn(lo, hi);
    return *reinterpret_cast<uint32_t*>(&h);
}

__device__ __forceinline__ float2 f16x2_to_f2(uint32_t u) {
    __half2 h = *reinterpret_cast<__half2*>(&u);
    return __half22float2(h);
}

__device__ __forceinline__ void ldsm_x4(uint32_t& r0, uint32_t& r1,
                                        uint32_t& r2, uint32_t& r3, uint32_t addr) {
    asm volatile("ldmatrix.sync.aligned.m8n8.x4.shared.b16 {%0,%1,%2,%3}, [%4];"
                 : "=r"(r0), "=r"(r1), "=r"(r2), "=r"(r3) : "r"(addr));
}

__device__ __forceinline__ void mma_f16(float c[4], const uint32_t a[4],
                                        const uint32_t b[2]) {
    asm volatile(
        "mma.sync.aligned.m16n8k16.row.col.f32.f16.f16.f32 "
        "{%0,%1,%2,%3}, {%4,%5,%6,%7}, {%8,%9}, {%0,%1,%2,%3};"
        : "+f"(c[0]), "+f"(c[1]), "+f"(c[2]), "+f"(c[3])
        : "r"(a[0]), "r"(a[1]), "r"(a[2]), "r"(a[3]), "r"(b[0]), "r"(b[1]));
}

#define CP16(sm, gp) \
    asm volatile("cp.async.cg.shared.global [%0], [%1], 16;" :: "r"(sm), "l"(gp))
#define CPCOMMIT() asm volatile("cp.async.commit_group;")
#define CPWAIT0()  asm volatile("cp.async.wait_group 0;")

// ---------------------------------------------------------------------------
// splits
// ---------------------------------------------------------------------------
__global__ void split_kernel(const float* __restrict__ in, u16* __restrict__ hi,
                             u16* __restrict__ lo, int n4)
{
    int i = blockIdx.x * blockDim.x + threadIdx.x;
    if (i >= n4) return;
    float4 v = ((const float4*)in)[i];
    float hx = __half2float(__float2half_rn(v.x));
    float hy = __half2float(__float2half_rn(v.y));
    float hz = __half2float(__float2half_rn(v.z));
    float hw = __half2float(__float2half_rn(v.w));
    uint2 h = make_uint2(pack_f16x2(v.x, v.y), pack_f16x2(v.z, v.w));
    uint2 l = make_uint2(pack_f16x2(v.x - hx, v.y - hy),
                         pack_f16x2(v.z - hz, v.w - hw));
    ((uint2*)hi)[i] = h;
    ((uint2*)lo)[i] = l;
}

// One launch splits all 7 weight matrices. blockIdx.y selects the matrix:
// 0..2 -> W1,W2,W3 (contiguous 256-col), 3..6 -> T10,T11,T20,T21 (512-col concat).
__global__ void split_all_w_kernel(const float* __restrict__ W1,
                                   const float* __restrict__ W2,
                                   const float* __restrict__ W3,
                                   const float* __restrict__ T10,
                                   const float* __restrict__ T11,
                                   const float* __restrict__ T20,
                                   const float* __restrict__ T21)
{
    int i = blockIdx.x * blockDim.x + threadIdx.x;
    if (i >= WSZ / 4) return;
    int w = blockIdx.y;
    const float* src = (w == 0) ? W1 : (w == 1) ? W2 : (w == 2) ? W3 :
                       (w == 3) ? T10 : (w == 4) ? T11 : (w == 5) ? T20 : T21;
    float4 v = ((const float4*)src)[i];
    float hx = __half2float(__float2half_rn(v.x));
    float hy = __half2float(__float2half_rn(v.y));
    float hz = __half2float(__float2half_rn(v.z));
    float hw = __half2float(__float2half_rn(v.w));
    uint2 h = make_uint2(pack_f16x2(v.x, v.y), pack_f16x2(v.z, v.w));
    uint2 l = make_uint2(pack_f16x2(v.x - hx, v.y - hy),
                         pack_f16x2(v.z - hz, v.w - hw));
    if (w < 3) {
        ((uint2*)(g_whi + (size_t)w * WSZ))[i] = h;
        ((uint2*)(g_wlo + (size_t)w * WSZ))[i] = l;
    } else {
        int row = i >> 6;
        int col = (i & 63) * 4;
        int colofs = ((w - 3) & 1) * 256;
        u16* dhi = (w < 5) ? g_wc1hi : g_wc2hi;
        u16* dlo = (w < 5) ? g_wc1lo : g_wc2lo;
        size_t o = (size_t)row * 512 + colofs + col;
        *(uint2*)(dhi + o) = h;
        *(uint2*)(dlo + o) = l;
    }
}

// ---------------------------------------------------------------------------
// GEMM: C[MPAD, colBase:+64] = (Ahi+Alo) @ (Whi+Wlo)[colBase:+64]^T
// 3-pass exact fp16 split on chunks < 8. AGGP = passes for chunks >= 8 (the
// agg half of the conv concat): 3 = full exact; 1 = a_hi*W_hi only (that
// operand already carries ~2^-12 gather noise, so the dropped ~2^-11 terms
// are near its noise floor).
// OMODE 0: write fp16 hi/lo pair. OMODE 1: fused head — accumulate
// relu(acc+b3) . W4 partial dots and atomicAdd into out[row*2 + cls].
// Tile 128x64x32, 256 thr, warp tile 32x32, 3 CTAs/SM, 2-stage cp.async.
// ---------------------------------------------------------------------------
#define BM   128
#define KS   40
#define STG  30720
#define OA_HI 0
#define OA_LO 10240
#define OB_HI 20480
#define OB_LO 25600

template <int KCHUNKS, bool RELU, int OMODE, int AGGP>
__global__ __launch_bounds__(256, 3)
void gemm_mma_kernel(const u16* __restrict__ Ahi, const u16* __restrict__ Alo,
                     const u16* __restrict__ A2hi, const u16* __restrict__ A2lo,
                     const u16* __restrict__ Whi, const u16* __restrict__ Wlo,
                     const float* __restrict__ bias,
                     u16* __restrict__ Chi, u16* __restrict__ Clo,
                     const float* __restrict__ W4v, float* __restrict__ outp)
{
    extern __shared__ char smem[];
    const uint32_t sb = (uint32_t)__cvta_generic_to_shared(smem);
    const int tid  = threadIdx.x;
    const int lane = tid & 31;
    const int wid  = tid >> 5;
    const int wm   = (wid & 3) * 32;
    const int wn   = (wid >> 2) * 32;
    const int rowBase = blockIdx.x * BM;
    const int colBase = blockIdx.y * 64;
    const int KTOT = KCHUNKS * 32;

    float acc[2][4][4];
#pragma unroll
    for (int mi = 0; mi < 2; mi++)
#pragma unroll
        for (int ni = 0; ni < 4; ni++)
#pragma unroll
            for (int j = 0; j < 4; j++) acc[mi][ni][j] = 0.0f;

    const int aRow = wm + (lane & 15);
    const int aColSel = (lane >> 4) * 8;
    const int bRow = wn + lane;

    auto load_chunk = [&](int c, int s) {
        uint32_t base = sb + (uint32_t)s * STG;
        const u16* pah = (c < 8) ? Ahi : A2hi;
        const u16* pal = (c < 8) ? Alo : A2lo;
        int ko = (c & 7) * 32;
        int k0 = c * 32;
        bool needALo = !(AGGP < 3 && c >= 8);
        bool needWLo = !(AGGP == 1 && c >= 8);
#pragma unroll
        for (int i = 0; i < 2; i++) {
            int f   = tid + i * 256;
            int row = f >> 2;
            int c8  = (f & 3) * 8;
            uint32_t so = (uint32_t)(row * 80 + c8 * 2);
            CP16(base + OA_HI + so, pah + (size_t)(rowBase + row) * 256 + ko + c8);
            if (needALo)
                CP16(base + OA_LO + so, pal + (size_t)(rowBase + row) * 256 + ko + c8);
        }
        {
            int row = tid >> 2;
            int c8  = (tid & 3) * 8;
            uint32_t so = (uint32_t)(row * 80 + c8 * 2);
            CP16(base + OB_HI + so, Whi + (size_t)(colBase + row) * KTOT + k0 + c8);
            if (needWLo)
                CP16(base + OB_LO + so, Wlo + (size_t)(colBase + row) * KTOT + k0 + c8);
        }
    };

    load_chunk(0, 0);
    CPCOMMIT();

#pragma unroll 1
    for (int c = 0; c < KCHUNKS; ++c) {
        const int s = c & 1;
        CPWAIT0();
        __syncthreads();
        if (c + 1 < KCHUNKS) { load_chunk(c + 1, s ^ 1); CPCOMMIT(); }

        const uint32_t stgBase = sb + (uint32_t)s * STG;
        const bool doALo = !(AGGP < 3 && c >= 8);
        const bool doWLo = !(AGGP == 1 && c >= 8);
#pragma unroll
        for (int kk = 0; kk < 32; kk += 16) {
            uint32_t ah[2][4], al[2][4];
#pragma unroll
            for (int mi = 0; mi < 2; mi++) {
                uint32_t ao = (uint32_t)(((aRow + mi * 16) * KS + kk + aColSel) * 2);
                ldsm_x4(ah[mi][0], ah[mi][1], ah[mi][2], ah[mi][3],
                        stgBase + OA_HI + ao);
                if (doALo)
                    ldsm_x4(al[mi][0], al[mi][1], al[mi][2], al[mi][3],
                            stgBase + OA_LO + ao);
            }
            uint32_t b[4][2];
            // W_hi with a_hi (and a_lo when enabled)
            {
                uint32_t r0, r1, r2, r3;
                uint32_t addr = stgBase + OB_HI + (uint32_t)((bRow * KS + kk) * 2);
                ldsm_x4(r0, r1, r2, r3, addr);
                b[0][0] = r0; b[1][0] = r1; b[2][0] = r2; b[3][0] = r3;
                addr += 16;
                ldsm_x4(r0, r1, r2, r3, addr);
                b[0][1] = r0; b[1][1] = r1; b[2][1] = r2; b[3][1] = r3;
            }
#pragma unroll
            for (int mi = 0; mi < 2; mi++)
#pragma unroll
                for (int ni = 0; ni < 4; ni++)
                    mma_f16(acc[mi][ni], ah[mi], b[ni]);
            if (doALo) {
#pragma unroll
                for (int mi = 0; mi < 2; mi++)
#pragma unroll
                    for (int ni = 0; ni < 4; ni++)
                        mma_f16(acc[mi][ni], al[mi], b[ni]);
            }
            // W_lo with a_hi
            if (doWLo) {
                uint32_t r0, r1, r2, r3;
                uint32_t addr = stgBase + OB_LO + (uint32_t)((bRow * KS + kk) * 2);
                ldsm_x4(r0, r1, r2, r3, addr);
                b[0][0] = r0; b[1][0] = r1; b[2][0] = r2; b[3][0] = r3;
                addr += 16;
                ldsm_x4(r0, r1, r2, r3, addr);
                b[0][1] = r0; b[1][1] = r1; b[2][1] = r2; b[3][1] = r3;
#pragma unroll
                for (int mi = 0; mi < 2; mi++)
#pragma unroll
                    for (int ni = 0; ni < 4; ni++)
                        mma_f16(acc[mi][ni], ah[mi], b[ni]);
            }
        }
        __syncthreads();
    }

    // ---- epilogue ----
#pragma unroll
    for (int mi = 0; mi < 2; mi++) {
        int row0 = rowBase + wm + mi * 16 + (lane >> 2);
        int row1 = row0 + 8;
        float p00 = 0.f, p01 = 0.f, p10 = 0.f, p11 = 0.f;
#pragma unroll
        for (int ni = 0; ni < 4; ni++) {
            int col = colBase + wn + ni * 8 + (lane & 3) * 2;
            float bx = __ldg(bias + col), by = __ldg(bias + col + 1);
            float2 o0 = make_float2(acc[mi][ni][0] + bx, acc[mi][ni][1] + by);
            float2 o1 = make_float2(acc[mi][ni][2] + bx, acc[mi][ni][3] + by);
            if (RELU) {
                o0.x = fmaxf(o0.x, 0.f); o0.y = fmaxf(o0.y, 0.f);
                o1.x = fmaxf(o1.x, 0.f); o1.y = fmaxf(o1.y, 0.f);
            }
            if (OMODE == 0) {
                float hx = __half2float(__float2half_rn(o0.x));
                float hy = __half2float(__float2half_rn(o0.y));
                *(uint32_t*)(Chi + (size_t)row0 * 256 + col) = pack_f16x2(o0.x, o0.y);
                *(uint32_t*)(Clo + (size_t)row0 * 256 + col) =
                    pack_f16x2(o0.x - hx, o0.y - hy);
                hx = __half2float(__float2half_rn(o1.x));
                hy = __half2float(__float2half_rn(o1.y));
                *(uint32_t*)(Chi + (size_t)row1 * 256 + col) = pack_f16x2(o1.x, o1.y);
                *(uint32_t*)(Clo + (size_t)row1 * 256 + col) =
                    pack_f16x2(o1.x - hx, o1.y - hy);
            } else {
                float wa = __ldg(W4v + col),       wb = __ldg(W4v + col + 1);
                float wc = __ldg(W4v + 256 + col), wd = __ldg(W4v + 256 + col + 1);
                p00 = fmaf(o0.x, wa, fmaf(o0.y, wb, p00));
                p01 = fmaf(o0.x, wc, fmaf(o0.y, wd, p01));
                p10 = fmaf(o1.x, wa, fmaf(o1.y, wb, p10));
                p11 = fmaf(o1.x, wc, fmaf(o1.y, wd, p11));
            }
        }
        if (OMODE == 1) {
            p00 += __shfl_xor_sync(0xFFFFFFFFu, p00, 1);
            p00 += __shfl_xor_sync(0xFFFFFFFFu, p00, 2);
            p01 += __shfl_xor_sync(0xFFFFFFFFu, p01, 1);
            p01 += __shfl_xor_sync(0xFFFFFFFFu, p01, 2);
            p10 += __shfl_xor_sync(0xFFFFFFFFu, p10, 1);
            p10 += __shfl_xor_sync(0xFFFFFFFFu, p10, 2);
            p11 += __shfl_xor_sync(0xFFFFFFFFu, p11, 1);
            p11 += __shfl_xor_sync(0xFFFFFFFFu, p11, 2);
            if ((lane & 3) == 0) {
                if (row0 < N_NODES) {
                    atomicAdd(outp + (size_t)row0 * 2,     p00);
                    atomicAdd(outp + (size_t)row0 * 2 + 1, p01);
                }
                if (row1 < N_NODES) {
                    atomicAdd(outp + (size_t)row1 * 2,     p10);
                    atomicAdd(outp + (size_t)row1 * 2 + 1, p11);
                }
            }
        }
    }
}

// ---------------------------------------------------------------------------
// CSR build
// ---------------------------------------------------------------------------
__global__ void zero_cnt_kernel() {
    int i = blockIdx.x * blockDim.x + threadIdx.x;
    if (i < N_NODES) { g_degi[i] = 0; g_cnt[i] = 0; }
}

__global__ void hist_kernel(const int* __restrict__ src, const int* __restrict__ dst) {
    int e = blockIdx.x * blockDim.x + threadIdx.x;
    if (e < E_EDGES) {
        atomicAdd(&g_degi[src[e]], 1);
        atomicAdd(&g_cnt[dst[e]], 1);
    }
}

// fused: dis computation + per-block partial sums of g_cnt
__global__ void partial_dis_kernel() {
    __shared__ int sh[256];
    int i = blockIdx.x * 256 + threadIdx.x;
    if (i < N_NODES) {
        int d = g_degi[i];
        g_dis[i] = (d > 0) ? rsqrtf((float)d) : 0.0f;
    }
    sh[threadIdx.x] = (i < N_NODES) ? g_cnt[i] : 0;
    __syncthreads();
#pragma unroll
    for (int o = 128; o > 0; o >>= 1) {
        if (threadIdx.x < o) sh[threadIdx.x] += sh[threadIdx.x + o];
        __syncthreads();
    }
    if (threadIdx.x == 0) g_bsum[blockIdx.x] = sh[0];
}

__global__ void scan_blocks_kernel() {
    __shared__ int sh[256];
    int tid = threadIdx.x;
    int v = (tid < NBLK) ? g_bsum[tid] : 0;
    sh[tid] = v;
    __syncthreads();
#pragma unroll
    for (int o = 1; o < 256; o <<= 1) {
        int t = (tid >= o) ? sh[tid - o] : 0;
        __syncthreads();
        sh[tid] += t;
        __syncthreads();
    }
    g_boff[tid] = sh[tid] - v;
}

__global__ void apply_kernel() {
    __shared__ int sh[256];
    int tid = threadIdx.x;
    int i = blockIdx.x * 256 + tid;
    int v = (i < N_NODES) ? g_cnt[i] : 0;
    sh[tid] = v;
    __syncthreads();
#pragma unroll
    for (int o = 1; o < 256; o <<= 1) {
        int t = (tid >= o) ? sh[tid - o] : 0;
        __syncthreads();
        sh[tid] += t;
        __syncthreads();
    }
    if (i < N_NODES) {
        int excl = sh[tid] - v + g_boff[blockIdx.x];
        g_rowstart[i] = excl;
        g_cursor[i]   = excl;
    }
}

__global__ void fill_kernel(const int* __restrict__ src, const int* __restrict__ dst) {
    int e = blockIdx.x * blockDim.x + threadIdx.x;
    if (e < E_EDGES) {
        int s = src[e], d = dst[e];
        int pos = atomicAdd(&g_cursor[d], 1);
        g_csr_src[pos] = s;
        g_csr_w[pos]   = -g_dis[s] * g_dis[d];
    }
}

// ---------------------------------------------------------------------------
// Gather (hi-only input AND hi-only output)
// ---------------------------------------------------------------------------
__global__ __launch_bounds__(256)
void gather_kernel(const u16* __restrict__ hi, u16* __restrict__ outhi)
{
    int node = (blockIdx.x * blockDim.x + threadIdx.x) >> 5;
    int lane = threadIdx.x & 31;
    if (node >= N_NODES) return;

    float a[8] = {0.f, 0.f, 0.f, 0.f, 0.f, 0.f, 0.f, 0.f};

    int p   = g_rowstart[node];
    int end = p + g_cnt[node];

#pragma unroll 1
    for (; p + 3 < end; p += 4) {
        int   s0 = __ldg(&g_csr_src[p]);
        int   s1 = __ldg(&g_csr_src[p + 1]);
        int   s2 = __ldg(&g_csr_src[p + 2]);
        int   s3 = __ldg(&g_csr_src[p + 3]);
        float w0 = __ldg(&g_csr_w[p]);
        float w1 = __ldg(&g_csr_w[p + 1]);
        float w2 = __ldg(&g_csr_w[p + 2]);
        float w3 = __ldg(&g_csr_w[p + 3]);
        uint4 h0 = *(const uint4*)(hi + (size_t)s0 * 256 + lane * 8);
        uint4 h1 = *(const uint4*)(hi + (size_t)s1 * 256 + lane * 8);
        uint4 h2 = *(const uint4*)(hi + (size_t)s2 * 256 + lane * 8);
        uint4 h3 = *(const uint4*)(hi + (size_t)s3 * 256 + lane * 8);
#pragma unroll
        for (int q = 0; q < 4; q++) {
            float2 f0 = f16x2_to_f2((&h0.x)[q]);
            float2 f1 = f16x2_to_f2((&h1.x)[q]);
            float2 f2 = f16x2_to_f2((&h2.x)[q]);
            float2 f3 = f16x2_to_f2((&h3.x)[q]);
            a[q*2]   = fmaf(w0, f0.x, a[q*2]);
            a[q*2+1] = fmaf(w0, f0.y, a[q*2+1]);
            a[q*2]   = fmaf(w1, f1.x, a[q*2]);
            a[q*2+1] = fmaf(w1, f1.y, a[q*2+1]);
            a[q*2]   = fmaf(w2, f2.x, a[q*2]);
            a[q*2+1] = fmaf(w2, f2.y, a[q*2+1]);
            a[q*2]   = fmaf(w3, f3.x, a[q*2]);
            a[q*2+1] = fmaf(w3, f3.y, a[q*2+1]);
        }
    }
#pragma unroll 1
    for (; p < end; ++p) {
        int   s0 = __ldg(&g_csr_src[p]);
        float w0 = __ldg(&g_csr_w[p]);
        uint4 h0 = *(const uint4*)(hi + (size_t)s0 * 256 + lane * 8);
#pragma unroll
        for (int q = 0; q < 4; q++) {
            float2 f0 = f16x2_to_f2((&h0.x)[q]);
            a[q*2]   = fmaf(w0, f0.x, a[q*2]);
            a[q*2+1] = fmaf(w0, f0.y, a[q*2+1]);
        }
    }

    uint4 hh;
#pragma unroll
    for (int q = 0; q < 4; q++)
        (&hh.x)[q] = pack_f16x2(a[q*2], a[q*2+1]);
    __stcs((uint4*)(outhi + (size_t)node * 256 + lane * 8), hh);
}

// out[i] = b4[i&1]
__global__ void init_out_kernel(float* __restrict__ out,
                                const float* __restrict__ b4)
{
    int i = blockIdx.x * blockDim.x + threadIdx.x;
    if (i < N_NODES * 2) out[i] = __ldg(b4 + (i & 1));
}

// ---------------------------------------------------------------------------
// Launch sequence (single stream — capture-safe)
// ---------------------------------------------------------------------------
extern "C" void kernel_launch(void* const* d_in, const int* in_sizes, int n_in,
                              void* d_out, int out_size)
{
    const float* x    = (const float*)d_in[0];
    const int*   ei   = (const int*)  d_in[1];
    const float* W1   = (const float*)d_in[2];
    const float* b1   = (const float*)d_in[3];
    const float* W2   = (const float*)d_in[4];
    const float* b2   = (const float*)d_in[5];
    const float* W3   = (const float*)d_in[6];
    const float* b3   = (const float*)d_in[7];
    const float* W4   = (const float*)d_in[8];
    const float* b4   = (const float*)d_in[9];
    const float* T10  = (const float*)d_in[10];
    const float* T11  = (const float*)d_in[11];
    const float* cb1  = (const float*)d_in[12];
    const float* T20  = (const float*)d_in[13];
    const float* T21  = (const float*)d_in[14];
    const float* cb2  = (const float*)d_in[15];
    float* out = (float*)d_out;

    const int* src = ei;
    const int* dst = ei + E_EDGES;

    u16 *xhi, *xlo, *h1hi, *h1lo, *h2hi, *h2lo, *aghi;
    u16 *o1hi, *o1lo, *o2hi, *o2lo, *whi, *wlo;
    u16 *wc1hi, *wc1lo, *wc2hi, *wc2lo;
    cudaGetSymbolAddress((void**)&xhi, g_xhi);
    cudaGetSymbolAddress((void**)&xlo, g_xlo);
    cudaGetSymbolAddress((void**)&h1hi, g_h1hi);
    cudaGetSymbolAddress((void**)&h1lo, g_h1lo);
    cudaGetSymbolAddress((void**)&h2hi, g_h2hi);
    cudaGetSymbolAddress((void**)&h2lo, g_h2lo);
    cudaGetSymbolAddress((void**)&aghi, g_aghi);
    cudaGetSymbolAddress((void**)&o1hi, g_o1hi);
    cudaGetSymbolAddress((void**)&o1lo, g_o1lo);
    cudaGetSymbolAddress((void**)&o2hi, g_o2hi);
    cudaGetSymbolAddress((void**)&o2lo, g_o2lo);
    cudaGetSymbolAddress((void**)&whi, g_whi);
    cudaGetSymbolAddress((void**)&wlo, g_wlo);
    cudaGetSymbolAddress((void**)&wc1hi, g_wc1hi);
    cudaGetSymbolAddress((void**)&wc1lo, g_wc1lo);
    cudaGetSymbolAddress((void**)&wc2hi, g_wc2hi);
    cudaGetSymbolAddress((void**)&wc2lo, g_wc2lo);

    const int SMEMSZ = 2 * STG;   // 61440

    cudaFuncSetAttribute(gemm_mma_kernel<8,  true,  0, 3>,
                         cudaFuncAttributeMaxDynamicSharedMemorySize, SMEMSZ);
    cudaFuncSetAttribute(gemm_mma_kernel<16, false, 0, 1>,
                         cudaFuncAttributeMaxDynamicSharedMemorySize, SMEMSZ);
    cudaFuncSetAttribute(gemm_mma_kernel<8,  true,  1, 3>,
                         cudaFuncAttributeMaxDynamicSharedMemorySize, SMEMSZ);

    dim3 ggrid(MPAD / BM, 4);    // (391, 4)
    const int gthr = (N_NODES * 32 + 255) / 256;
    const int wblk = (WSZ / 4 + 255) / 256;

    // --- input/weight splits + MLP GEMMs ---
    split_kernel<<<(N_NODES * HDIM / 4 + 255) / 256, 256>>>(x, xhi, xlo,
                                                            N_NODES * HDIM / 4);
    split_all_w_kernel<<<dim3(wblk, 7), 256>>>(W1, W2, W3, T10, T11, T20, T21);
    gemm_mma_kernel<8, true, 0, 3><<<ggrid, 256, SMEMSZ>>>(
        xhi, xlo, nullptr, nullptr, whi + 0 * WSZ, wlo + 0 * WSZ, b1,
        h1hi, h1lo, nullptr, nullptr);
    gemm_mma_kernel<8, true, 0, 3><<<ggrid, 256, SMEMSZ>>>(
        h1hi, h1lo, nullptr, nullptr, whi + 1 * WSZ, wlo + 1 * WSZ, b2,
        h2hi, h2lo, nullptr, nullptr);

    // --- CSR build ---
    zero_cnt_kernel<<<(N_NODES + 255) / 256, 256>>>();
    hist_kernel<<<(E_EDGES + 255) / 256, 256>>>(src, dst);
    partial_dis_kernel<<<NBLK, 256>>>();
    scan_blocks_kernel<<<1, 256>>>();
    apply_kernel<<<NBLK, 256>>>();
    fill_kernel<<<(E_EDGES + 255) / 256, 256>>>(src, dst);

    // --- conv 1: agg = S h2 (hi-only) ; out1 = [h2, agg] @ [T10;T11]^T + cb1 ---
    gather_kernel<<<gthr, 256>>>(h2hi, aghi);
    gemm_mma_kernel<16, false, 0, 1><<<ggrid, 256, SMEMSZ>>>(
        h2hi, h2lo, aghi, nullptr, wc1hi, wc1lo, cb1,
        o1hi, o1lo, nullptr, nullptr);

    // --- conv 2: agg = S out1 (hi-only) ; out2 = [out1, agg] @ [T20;T21]^T + cb2 ---
    gather_kernel<<<gthr, 256>>>(o1hi, aghi);
    gemm_mma_kernel<16, false, 0, 1><<<ggrid, 256, SMEMSZ>>>(
        o1hi, o1lo, aghi, nullptr, wc2hi, wc2lo, cb2,
        o2hi, o2lo, nullptr, nullptr);

    // --- fused: out = relu(out2@W3^T + b3) @ W4^T + b4 ---
    init_out_kernel<<<(N_NODES * 2 + 255) / 256, 256>>>(out, b4);
    gemm_mma_kernel<8, true, 1, 3><<<ggrid, 256, SMEMSZ>>>(
        o2hi, o2lo, nullptr, nullptr, whi + 2 * WSZ, wlo + 2 * WSZ, b3,
        nullptr, nullptr, W4, out);
}

// round 15
// speedup vs baseline: 1.3315x; 1.0506x over previous
#include <cuda_runtime.h>
#include <cuda_fp16.h>
#include <cstdint>

#define N_NODES 50000
#define MPAD    50048
#define E_EDGES 1600000
#define HDIM    256
#define NBLK    196
#define WSZ     (HDIM * HDIM)

typedef unsigned short u16;

// ---------------------------------------------------------------------------
// Static device scratch
// ---------------------------------------------------------------------------
__device__ int   g_degi[N_NODES];
__device__ int   g_cnt[N_NODES];
__device__ int   g_rowstart[N_NODES];
__device__ int   g_cursor[N_NODES];
__device__ float g_dis[N_NODES];
__device__ int   g_csr_src[E_EDGES];
__device__ float g_csr_w[E_EDGES];
__device__ int   g_bsum[256];
__device__ int   g_boff[256];

// fp16 activation pairs
__device__ u16 g_xhi[(size_t)MPAD * HDIM];
__device__ u16 g_xlo[(size_t)MPAD * HDIM];
__device__ u16 g_h1hi[(size_t)MPAD * HDIM];
__device__ u16 g_h1lo[(size_t)MPAD * HDIM];
__device__ u16 g_h2hi[(size_t)MPAD * HDIM];
__device__ u16 g_h2lo[(size_t)MPAD * HDIM];
__device__ u16 g_aghi[(size_t)MPAD * HDIM];
__device__ u16 g_o1hi[(size_t)MPAD * HDIM];
__device__ u16 g_o1lo[(size_t)MPAD * HDIM];
__device__ u16 g_o2hi[(size_t)MPAD * HDIM];

// fp16 hi/lo weights: W1,W2,W3 (256 cols) + concat conv weights (512 cols)
__device__ u16 g_whi[3 * WSZ];
__device__ u16 g_wlo[3 * WSZ];
__device__ u16 g_wc1hi[HDIM * 512];
__device__ u16 g_wc1lo[HDIM * 512];
__device__ u16 g_wc2hi[HDIM * 512];
__device__ u16 g_wc2lo[HDIM * 512];

// ---------------------------------------------------------------------------
// helpers
// ---------------------------------------------------------------------------
__device__ __forceinline__ uint32_t pack_f16x2(float lo, float hi) {
    __half2 h = __floats2half2_rn(lo, hi);
    return *reinterpret_cast<uint32_t*>(&h);
}

__device__ __forceinline__ float2 f16x2_to_f2(uint32_t u) {
    __half2 h = *reinterpret_cast<__half2*>(&u);
    return __half22float2(h);
}

__device__ __forceinline__ void ldsm_x4(uint32_t& r0, uint32_t& r1,
                                        uint32_t& r2, uint32_t& r3, uint32_t addr) {
    asm volatile("ldmatrix.sync.aligned.m8n8.x4.shared.b16 {%0,%1,%2,%3}, [%4];"
                 : "=r"(r0), "=r"(r1), "=r"(r2), "=r"(r3) : "r"(addr));
}

__device__ __forceinline__ void mma_f16(float c[4], const uint32_t a[4],
                                        const uint32_t b[2]) {
    asm volatile(
        "mma.sync.aligned.m16n8k16.row.col.f32.f16.f16.f32 "
        "{%0,%1,%2,%3}, {%4,%5,%6,%7}, {%8,%9}, {%0,%1,%2,%3};"
        : "+f"(c[0]), "+f"(c[1]), "+f"(c[2]), "+f"(c[3])
        : "r"(a[0]), "r"(a[1]), "r"(a[2]), "r"(a[3]), "r"(b[0]), "r"(b[1]));
}

#define CP16(sm, gp) \
    asm volatile("cp.async.cg.shared.global [%0], [%1], 16;" :: "r"(sm), "l"(gp))
#define CPCOMMIT() asm volatile("cp.async.commit_group;")
#define CPWAIT0()  asm volatile("cp.async.wait_group 0;")

// ---------------------------------------------------------------------------
// splits
// ---------------------------------------------------------------------------
__global__ void split_kernel(const float* __restrict__ in, u16* __restrict__ hi,
                             u16* __restrict__ lo, int n4)
{
    int i = blockIdx.x * blockDim.x + threadIdx.x;
    if (i >= n4) return;
    float4 v = ((const float4*)in)[i];
    float hx = __half2float(__float2half_rn(v.x));
    float hy = __half2float(__float2half_rn(v.y));
    float hz = __half2float(__float2half_rn(v.z));
    float hw = __half2float(__float2half_rn(v.w));
    uint2 h = make_uint2(pack_f16x2(v.x, v.y), pack_f16x2(v.z, v.w));
    uint2 l = make_uint2(pack_f16x2(v.x - hx, v.y - hy),
                         pack_f16x2(v.z - hz, v.w - hw));
    ((uint2*)hi)[i] = h;
    ((uint2*)lo)[i] = l;
}

// One launch splits all 7 weight matrices. blockIdx.y selects the matrix:
// 0..2 -> W1,W2,W3 (contiguous 256-col), 3..6 -> T10,T11,T20,T21 (512-col concat).
__global__ void split_all_w_kernel(const float* __restrict__ W1,
                                   const float* __restrict__ W2,
                                   const float* __restrict__ W3,
                                   const float* __restrict__ T10,
                                   const float* __restrict__ T11,
                                   const float* __restrict__ T20,
                                   const float* __restrict__ T21)
{
    int i = blockIdx.x * blockDim.x + threadIdx.x;
    if (i >= WSZ / 4) return;
    int w = blockIdx.y;
    const float* src = (w == 0) ? W1 : (w == 1) ? W2 : (w == 2) ? W3 :
                       (w == 3) ? T10 : (w == 4) ? T11 : (w == 5) ? T20 : T21;
    float4 v = ((const float4*)src)[i];
    float hx = __half2float(__float2half_rn(v.x));
    float hy = __half2float(__float2half_rn(v.y));
    float hz = __half2float(__float2half_rn(v.z));
    float hw = __half2float(__float2half_rn(v.w));
    uint2 h = make_uint2(pack_f16x2(v.x, v.y), pack_f16x2(v.z, v.w));
    uint2 l = make_uint2(pack_f16x2(v.x - hx, v.y - hy),
                         pack_f16x2(v.z - hz, v.w - hw));
    if (w < 3) {
        ((uint2*)(g_whi + (size_t)w * WSZ))[i] = h;
        ((uint2*)(g_wlo + (size_t)w * WSZ))[i] = l;
    } else {
        int row = i >> 6;
        int col = (i & 63) * 4;
        int colofs = ((w - 3) & 1) * 256;
        u16* dhi = (w < 5) ? g_wc1hi : g_wc2hi;
        u16* dlo = (w < 5) ? g_wc1lo : g_wc2lo;
        size_t o = (size_t)row * 512 + colofs + col;
        *(uint2*)(dhi + o) = h;
        *(uint2*)(dlo + o) = l;
    }
}

// ---------------------------------------------------------------------------
// GEMM: C[MPAD, colBase:+64] = A @ (Whi+Wlo)[colBase:+64]^T
// BASEP = passes for chunks < 8 (3 = exact split, 2 = a_hi only: for operands
// with no lo stream). AGGP = passes for chunks >= 8 (conv agg half; 1 =
// a_hi*W_hi only — that operand carries ~2^-12 gather noise already).
// OMODE 0: write fp16 output (hi always; lo only if OUTLO).
// OMODE 1: fused head — relu(acc+b3) . W4 partials, atomicAdd into out.
// Tile 128x64x32, 256 thr, warp tile 32x32, 3 CTAs/SM, 2-stage cp.async.
// ---------------------------------------------------------------------------
#define BM   128
#define KS   40
#define STG  30720
#define OA_HI 0
#define OA_LO 10240
#define OB_HI 20480
#define OB_LO 25600

template <int KCHUNKS, int BASEP, int AGGP, bool RELU, int OMODE, bool OUTLO>
__global__ __launch_bounds__(256, 3)
void gemm_mma_kernel(const u16* __restrict__ Ahi, const u16* __restrict__ Alo,
                     const u16* __restrict__ A2hi,
                     const u16* __restrict__ Whi, const u16* __restrict__ Wlo,
                     const float* __restrict__ bias,
                     u16* __restrict__ Chi, u16* __restrict__ Clo,
                     const float* __restrict__ W4v, float* __restrict__ outp)
{
    extern __shared__ char smem[];
    const uint32_t sb = (uint32_t)__cvta_generic_to_shared(smem);
    const int tid  = threadIdx.x;
    const int lane = tid & 31;
    const int wid  = tid >> 5;
    const int wm   = (wid & 3) * 32;
    const int wn   = (wid >> 2) * 32;
    const int rowBase = blockIdx.x * BM;
    const int colBase = blockIdx.y * 64;
    const int KTOT = KCHUNKS * 32;

    float acc[2][4][4];
#pragma unroll
    for (int mi = 0; mi < 2; mi++)
#pragma unroll
        for (int ni = 0; ni < 4; ni++)
#pragma unroll
            for (int j = 0; j < 4; j++) acc[mi][ni][j] = 0.0f;

    const int aRow = wm + (lane & 15);
    const int aColSel = (lane >> 4) * 8;
    const int bRow = wn + lane;

    auto load_chunk = [&](int c, int s) {
        uint32_t base = sb + (uint32_t)s * STG;
        const u16* pah = (c < 8) ? Ahi : A2hi;
        int ko = (c & 7) * 32;
        int k0 = c * 32;
        bool needALo = (c < 8) ? (BASEP == 3) : (AGGP == 3);
        bool needWLo = (c < 8) ? true : (AGGP >= 2);
#pragma unroll
        for (int i = 0; i < 2; i++) {
            int f   = tid + i * 256;
            int row = f >> 2;
            int c8  = (f & 3) * 8;
            uint32_t so = (uint32_t)(row * 80 + c8 * 2);
            CP16(base + OA_HI + so, pah + (size_t)(rowBase + row) * 256 + ko + c8);
            if (needALo)
                CP16(base + OA_LO + so, Alo + (size_t)(rowBase + row) * 256 + ko + c8);
        }
        {
            int row = tid >> 2;
            int c8  = (tid & 3) * 8;
            uint32_t so = (uint32_t)(row * 80 + c8 * 2);
            CP16(base + OB_HI + so, Whi + (size_t)(colBase + row) * KTOT + k0 + c8);
            if (needWLo)
                CP16(base + OB_LO + so, Wlo + (size_t)(colBase + row) * KTOT + k0 + c8);
        }
    };

    load_chunk(0, 0);
    CPCOMMIT();

#pragma unroll 1
    for (int c = 0; c < KCHUNKS; ++c) {
        const int s = c & 1;
        CPWAIT0();
        __syncthreads();
        if (c + 1 < KCHUNKS) { load_chunk(c + 1, s ^ 1); CPCOMMIT(); }

        const uint32_t stgBase = sb + (uint32_t)s * STG;
        const bool doALo = (c < 8) ? (BASEP == 3) : (AGGP == 3);
        const bool doWLo = (c < 8) ? true : (AGGP >= 2);
#pragma unroll
        for (int kk = 0; kk < 32; kk += 16) {
            uint32_t ah[2][4], al[2][4];
#pragma unroll
            for (int mi = 0; mi < 2; mi++) {
                uint32_t ao = (uint32_t)(((aRow + mi * 16) * KS + kk + aColSel) * 2);
                ldsm_x4(ah[mi][0], ah[mi][1], ah[mi][2], ah[mi][3],
                        stgBase + OA_HI + ao);
                if (doALo)
                    ldsm_x4(al[mi][0], al[mi][1], al[mi][2], al[mi][3],
                            stgBase + OA_LO + ao);
            }
            uint32_t b[4][2];
            // W_hi with a_hi (and a_lo when enabled)
            {
                uint32_t r0, r1, r2, r3;
                uint32_t addr = stgBase + OB_HI + (uint32_t)((bRow * KS + kk) * 2);
                ldsm_x4(r0, r1, r2, r3, addr);
                b[0][0] = r0; b[1][0] = r1; b[2][0] = r2; b[3][0] = r3;
                addr += 16;
                ldsm_x4(r0, r1, r2, r3, addr);
                b[0][1] = r0; b[1][1] = r1; b[2][1] = r2; b[3][1] = r3;
            }
#pragma unroll
            for (int mi = 0; mi < 2; mi++)
#pragma unroll
                for (int ni = 0; ni < 4; ni++)
                    mma_f16(acc[mi][ni], ah[mi], b[ni]);
            if (doALo) {
#pragma unroll
                for (int mi = 0; mi < 2; mi++)
#pragma unroll
                    for (int ni = 0; ni < 4; ni++)
                        mma_f16(acc[mi][ni], al[mi], b[ni]);
            }
            // W_lo with a_hi
            if (doWLo) {
                uint32_t r0, r1, r2, r3;
                uint32_t addr = stgBase + OB_LO + (uint32_t)((bRow * KS + kk) * 2);
                ldsm_x4(r0, r1, r2, r3, addr);
                b[0][0] = r0; b[1][0] = r1; b[2][0] = r2; b[3][0] = r3;
                addr += 16;
                ldsm_x4(r0, r1, r2, r3, addr);
                b[0][1] = r0; b[1][1] = r1; b[2][1] = r2; b[3][1] = r3;
#pragma unroll
                for (int mi = 0; mi < 2; mi++)
#pragma unroll
                    for (int ni = 0; ni < 4; ni++)
                        mma_f16(acc[mi][ni], ah[mi], b[ni]);
            }
        }
        __syncthreads();
    }

    // ---- epilogue ----
#pragma unroll
    for (int mi = 0; mi < 2; mi++) {
        int row0 = rowBase + wm + mi * 16 + (lane >> 2);
        int row1 = row0 + 8;
        float p00 = 0.f, p01 = 0.f, p10 = 0.f, p11 = 0.f;
#pragma unroll
        for (int ni = 0; ni < 4; ni++) {
            int col = colBase + wn + ni * 8 + (lane & 3) * 2;
            float bx = __ldg(bias + col), by = __ldg(bias + col + 1);
            float2 o0 = make_float2(acc[mi][ni][0] + bx, acc[mi][ni][1] + by);
            float2 o1 = make_float2(acc[mi][ni][2] + bx, acc[mi][ni][3] + by);
            if (RELU) {
                o0.x = fmaxf(o0.x, 0.f); o0.y = fmaxf(o0.y, 0.f);
                o1.x = fmaxf(o1.x, 0.f); o1.y = fmaxf(o1.y, 0.f);
            }
            if (OMODE == 0) {
                *(uint32_t*)(Chi + (size_t)row0 * 256 + col) = pack_f16x2(o0.x, o0.y);
                *(uint32_t*)(Chi + (size_t)row1 * 256 + col) = pack_f16x2(o1.x, o1.y);
                if (OUTLO) {
                    float hx = __half2float(__float2half_rn(o0.x));
                    float hy = __half2float(__float2half_rn(o0.y));
                    *(uint32_t*)(Clo + (size_t)row0 * 256 + col) =
                        pack_f16x2(o0.x - hx, o0.y - hy);
                    hx = __half2float(__float2half_rn(o1.x));
                    hy = __half2float(__float2half_rn(o1.y));
                    *(uint32_t*)(Clo + (size_t)row1 * 256 + col) =
                        pack_f16x2(o1.x - hx, o1.y - hy);
                }
            } else {
                float wa = __ldg(W4v + col),       wb = __ldg(W4v + col + 1);
                float wc = __ldg(W4v + 256 + col), wd = __ldg(W4v + 256 + col + 1);
                p00 = fmaf(o0.x, wa, fmaf(o0.y, wb, p00));
                p01 = fmaf(o0.x, wc, fmaf(o0.y, wd, p01));
                p10 = fmaf(o1.x, wa, fmaf(o1.y, wb, p10));
                p11 = fmaf(o1.x, wc, fmaf(o1.y, wd, p11));
            }
        }
        if (OMODE == 1) {
            p00 += __shfl_xor_sync(0xFFFFFFFFu, p00, 1);
            p00 += __shfl_xor_sync(0xFFFFFFFFu, p00, 2);
            p01 += __shfl_xor_sync(0xFFFFFFFFu, p01, 1);
            p01 += __shfl_xor_sync(0xFFFFFFFFu, p01, 2);
            p10 += __shfl_xor_sync(0xFFFFFFFFu, p10, 1);
            p10 += __shfl_xor_sync(0xFFFFFFFFu, p10, 2);
            p11 += __shfl_xor_sync(0xFFFFFFFFu, p11, 1);
            p11 += __shfl_xor_sync(0xFFFFFFFFu, p11, 2);
            if ((lane & 3) == 0) {
                if (row0 < N_NODES) {
                    atomicAdd(outp + (size_t)row0 * 2,     p00);
                    atomicAdd(outp + (size_t)row0 * 2 + 1, p01);
                }
                if (row1 < N_NODES) {
                    atomicAdd(outp + (size_t)row1 * 2,     p10);
                    atomicAdd(outp + (size_t)row1 * 2 + 1, p11);
                }
            }
        }
    }
}

// ---------------------------------------------------------------------------
// CSR build
// ---------------------------------------------------------------------------
__global__ void zero_cnt_kernel() {
    int i = blockIdx.x * blockDim.x + threadIdx.x;
    if (i < N_NODES) { g_degi[i] = 0; g_cnt[i] = 0; }
}

__global__ void hist_kernel(const int* __restrict__ src, const int* __restrict__ dst) {
    int e = blockIdx.x * blockDim.x + threadIdx.x;
    if (e < E_EDGES) {
        atomicAdd(&g_degi[src[e]], 1);
        atomicAdd(&g_cnt[dst[e]], 1);
    }
}

__global__ void partial_dis_kernel() {
    __shared__ int sh[256];
    int i = blockIdx.x * 256 + threadIdx.x;
    if (i < N_NODES) {
        int d = g_degi[i];
        g_dis[i] = (d > 0) ? rsqrtf((float)d) : 0.0f;
    }
    sh[threadIdx.x] = (i < N_NODES) ? g_cnt[i] : 0;
    __syncthreads();
#pragma unroll
    for (int o = 128; o > 0; o >>= 1) {
        if (threadIdx.x < o) sh[threadIdx.x] += sh[threadIdx.x + o];
        __syncthreads();
    }
    if (threadIdx.x == 0) g_bsum[blockIdx.x] = sh[0];
}

__global__ void scan_blocks_kernel() {
    __shared__ int sh[256];
    int tid = threadIdx.x;
    int v = (tid < NBLK) ? g_bsum[tid] : 0;
    sh[tid] = v;
    __syncthreads();
#pragma unroll
    for (int o = 1; o < 256; o <<= 1) {
        int t = (tid >= o) ? sh[tid - o] : 0;
        __syncthreads();
        sh[tid] += t;
        __syncthreads();
    }
    g_boff[tid] = sh[tid] - v;
}

__global__ void apply_kernel() {
    __shared__ int sh[256];
    int tid = threadIdx.x;
    int i = blockIdx.x * 256 + tid;
    int v = (i < N_NODES) ? g_cnt[i] : 0;
    sh[tid] = v;
    __syncthreads();
#pragma unroll
    for (int o = 1; o < 256; o <<= 1) {
        int t = (tid >= o) ? sh[tid - o] : 0;
        __syncthreads();
        sh[tid] += t;
        __syncthreads();
    }
    if (i < N_NODES) {
        int excl = sh[tid] - v + g_boff[blockIdx.x];
        g_rowstart[i] = excl;
        g_cursor[i]   = excl;
    }
}

__global__ void fill_kernel(const int* __restrict__ src, const int* __restrict__ dst) {
    int e = blockIdx.x * blockDim.x + threadIdx.x;
    if (e < E_EDGES) {
        int s = src[e], d = dst[e];
        int pos = atomicAdd(&g_cursor[d], 1);
        g_csr_src[pos] = s;
        g_csr_w[pos]   = -g_dis[s] * g_dis[d];
    }
}

// ---------------------------------------------------------------------------
// Gather (hi-only input AND hi-only output)
// ---------------------------------------------------------------------------
__global__ __launch_bounds__(256)
void gather_kernel(const u16* __restrict__ hi, u16* __restrict__ outhi)
{
    int node = (blockIdx.x * blockDim.x + threadIdx.x) >> 5;
    int lane = threadIdx.x & 31;
    if (node >= N_NODES) return;

    float a[8] = {0.f, 0.f, 0.f, 0.f, 0.f, 0.f, 0.f, 0.f};

    int p   = g_rowstart[node];
    int end = p + g_cnt[node];

#pragma unroll 1
    for (; p + 3 < end; p += 4) {
        int   s0 = __ldg(&g_csr_src[p]);
        int   s1 = __ldg(&g_csr_src[p + 1]);
        int   s2 = __ldg(&g_csr_src[p + 2]);
        int   s3 = __ldg(&g_csr_src[p + 3]);
        float w0 = __ldg(&g_csr_w[p]);
        float w1 = __ldg(&g_csr_w[p + 1]);
        float w2 = __ldg(&g_csr_w[p + 2]);
        float w3 = __ldg(&g_csr_w[p + 3]);
        uint4 h0 = *(const uint4*)(hi + (size_t)s0 * 256 + lane * 8);
        uint4 h1 = *(const uint4*)(hi + (size_t)s1 * 256 + lane * 8);
        uint4 h2 = *(const uint4*)(hi + (size_t)s2 * 256 + lane * 8);
        uint4 h3 = *(const uint4*)(hi + (size_t)s3 * 256 + lane * 8);
#pragma unroll
        for (int q = 0; q < 4; q++) {
            float2 f0 = f16x2_to_f2((&h0.x)[q]);
            float2 f1 = f16x2_to_f2((&h1.x)[q]);
            float2 f2 = f16x2_to_f2((&h2.x)[q]);
            float2 f3 = f16x2_to_f2((&h3.x)[q]);
            a[q*2]   = fmaf(w0, f0.x, a[q*2]);
            a[q*2+1] = fmaf(w0, f0.y, a[q*2+1]);
            a[q*2]   = fmaf(w1, f1.x, a[q*2]);
            a[q*2+1] = fmaf(w1, f1.y, a[q*2+1]);
            a[q*2]   = fmaf(w2, f2.x, a[q*2]);
            a[q*2+1] = fmaf(w2, f2.y, a[q*2+1]);
            a[q*2]   = fmaf(w3, f3.x, a[q*2]);
            a[q*2+1] = fmaf(w3, f3.y, a[q*2+1]);
        }
    }
#pragma unroll 1
    for (; p < end; ++p) {
        int   s0 = __ldg(&g_csr_src[p]);
        float w0 = __ldg(&g_csr_w[p]);
        uint4 h0 = *(const uint4*)(hi + (size_t)s0 * 256 + lane * 8);
#pragma unroll
        for (int q = 0; q < 4; q++) {
            float2 f0 = f16x2_to_f2((&h0.x)[q]);
            a[q*2]   = fmaf(w0, f0.x, a[q*2]);
            a[q*2+1] = fmaf(w0, f0.y, a[q*2+1]);
        }
    }

    uint4 hh;
#pragma unroll
    for (int q = 0; q < 4; q++)
        (&hh.x)[q] = pack_f16x2(a[q*2], a[q*2+1]);
    __stcs((uint4*)(outhi + (size_t)node * 256 + lane * 8), hh);
}

// out[i] = b4[i&1]
__global__ void init_out_kernel(float* __restrict__ out,
                                const float* __restrict__ b4)
{
    int i = blockIdx.x * blockDim.x + threadIdx.x;
    if (i < N_NODES * 2) out[i] = __ldg(b4 + (i & 1));
}

// ---------------------------------------------------------------------------
// Launch sequence (single stream — capture-safe)
// ---------------------------------------------------------------------------
extern "C" void kernel_launch(void* const* d_in, const int* in_sizes, int n_in,
                              void* d_out, int out_size)
{
    const float* x    = (const float*)d_in[0];
    const int*   ei   = (const int*)  d_in[1];
    const float* W1   = (const float*)d_in[2];
    const float* b1   = (const float*)d_in[3];
    const float* W2   = (const float*)d_in[4];
    const float* b2   = (const float*)d_in[5];
    const float* W3   = (const float*)d_in[6];
    const float* b3   = (const float*)d_in[7];
    const float* W4   = (const float*)d_in[8];
    const float* b4   = (const float*)d_in[9];
    const float* T10  = (const float*)d_in[10];
    const float* T11  = (const float*)d_in[11];
    const float* cb1  = (const float*)d_in[12];
    const float* T20  = (const float*)d_in[13];
    const float* T21  = (const float*)d_in[14];
    const float* cb2  = (const float*)d_in[15];
    float* out = (float*)d_out;

    const int* src = ei;
    const int* dst = ei + E_EDGES;

    u16 *xhi, *xlo, *h1hi, *h1lo, *h2hi, *h2lo, *aghi;
    u16 *o1hi, *o1lo, *o2hi, *whi, *wlo;
    u16 *wc1hi, *wc1lo, *wc2hi, *wc2lo;
    cudaGetSymbolAddress((void**)&xhi, g_xhi);
    cudaGetSymbolAddress((void**)&xlo, g_xlo);
    cudaGetSymbolAddress((void**)&h1hi, g_h1hi);
    cudaGetSymbolAddress((void**)&h1lo, g_h1lo);
    cudaGetSymbolAddress((void**)&h2hi, g_h2hi);
    cudaGetSymbolAddress((void**)&h2lo, g_h2lo);
    cudaGetSymbolAddress((void**)&aghi, g_aghi);
    cudaGetSymbolAddress((void**)&o1hi, g_o1hi);
    cudaGetSymbolAddress((void**)&o1lo, g_o1lo);
    cudaGetSymbolAddress((void**)&o2hi, g_o2hi);
    cudaGetSymbolAddress((void**)&whi, g_whi);
    cudaGetSymbolAddress((void**)&wlo, g_wlo);
    cudaGetSymbolAddress((void**)&wc1hi, g_wc1hi);
    cudaGetSymbolAddress((void**)&wc1lo, g_wc1lo);
    cudaGetSymbolAddress((void**)&wc2hi, g_wc2hi);
    cudaGetSymbolAddress((void**)&wc2lo, g_wc2lo);

    const int SMEMSZ = 2 * STG;   // 61440

    cudaFuncSetAttribute(gemm_mma_kernel<8,  3, 3, true,  0, true>,
                         cudaFuncAttributeMaxDynamicSharedMemorySize, SMEMSZ);
    cudaFuncSetAttribute(gemm_mma_kernel<16, 3, 1, false, 0, true>,
                         cudaFuncAttributeMaxDynamicSharedMemorySize, SMEMSZ);
    cudaFuncSetAttribute(gemm_mma_kernel<16, 3, 1, false, 0, false>,
                         cudaFuncAttributeMaxDynamicSharedMemorySize, SMEMSZ);
    cudaFuncSetAttribute(gemm_mma_kernel<8,  2, 3, true,  1, false>,
                         cudaFuncAttributeMaxDynamicSharedMemorySize, SMEMSZ);

    dim3 ggrid(MPAD / BM, 4);    // (391, 4)
    const int gthr = (N_NODES * 32 + 255) / 256;
    const int wblk = (WSZ / 4 + 255) / 256;

    // --- input/weight splits + MLP GEMMs ---
    split_kernel<<<(N_NODES * HDIM / 4 + 255) / 256, 256>>>(x, xhi, xlo,
                                                            N_NODES * HDIM / 4);
    split_all_w_kernel<<<dim3(wblk, 7), 256>>>(W1, W2, W3, T10, T11, T20, T21);
    gemm_mma_kernel<8, 3, 3, true, 0, true><<<ggrid, 256, SMEMSZ>>>(
        xhi, xlo, nullptr, whi + 0 * WSZ, wlo + 0 * WSZ, b1,
        h1hi, h1lo, nullptr, nullptr);
    gemm_mma_kernel<8, 3, 3, true, 0, true><<<ggrid, 256, SMEMSZ>>>(
        h1hi, h1lo, nullptr, whi + 1 * WSZ, wlo + 1 * WSZ, b2,
        h2hi, h2lo, nullptr, nullptr);

    // --- CSR build ---
    zero_cnt_kernel<<<(N_NODES + 255) / 256, 256>>>();
    hist_kernel<<<(E_EDGES + 255) / 256, 256>>>(src, dst);
    partial_dis_kernel<<<NBLK, 256>>>();
    scan_blocks_kernel<<<1, 256>>>();
    apply_kernel<<<NBLK, 256>>>();
    fill_kernel<<<(E_EDGES + 255) / 256, 256>>>(src, dst);

    // --- conv 1: agg = S h2 (hi-only) ; out1 = [h2, agg] @ [T10;T11]^T + cb1 ---
    gather_kernel<<<gthr, 256>>>(h2hi, aghi);
    gemm_mma_kernel<16, 3, 1, false, 0, true><<<ggrid, 256, SMEMSZ>>>(
        h2hi, h2lo, aghi, wc1hi, wc1lo, cb1,
        o1hi, o1lo, nullptr, nullptr);

    // --- conv 2: agg = S out1 (hi-only) ; out2 (hi only) ---
    gather_kernel<<<gthr, 256>>>(o1hi, aghi);
    gemm_mma_kernel<16, 3, 1, false, 0, false><<<ggrid, 256, SMEMSZ>>>(
        o1hi, o1lo, aghi, wc2hi, wc2lo, cb2,
        o2hi, nullptr, nullptr, nullptr);

    // --- fused: out = relu(out2@W3^T + b3) @ W4^T + b4 (2-pass A: hi only) ---
    init_out_kernel<<<(N_NODES * 2 + 255) / 256, 256>>>(out, b4);
    gemm_mma_kernel<8, 2, 3, true, 1, false><<<ggrid, 256, SMEMSZ>>>(
        o2hi, nullptr, nullptr, whi + 2 * WSZ, wlo + 2 * WSZ, b3,
        nullptr, nullptr, W4, out);
}

// round 16
// speedup vs baseline: 1.3880x; 1.0424x over previous
#include <cuda_runtime.h>
#include <cuda_fp16.h>
#include <cstdint>

#define N_NODES 50000
#define MPAD    50048
#define E_EDGES 1600000
#define HDIM    256
#define NBLK    196
#define WSZ     (HDIM * HDIM)

typedef unsigned short u16;

// ---------------------------------------------------------------------------
// Static device scratch
// ---------------------------------------------------------------------------
__device__ int   g_degi[N_NODES];
__device__ int   g_cnt[N_NODES];
__device__ int   g_rowstart[N_NODES];
__device__ int   g_cursor[N_NODES];
__device__ float g_dis[N_NODES];
__device__ int   g_csr_src[E_EDGES];
__device__ float g_csr_w[E_EDGES];
__device__ int   g_bsum[256];
__device__ int   g_boff[256];

// fp16 activations
__device__ u16 g_xhi[(size_t)MPAD * HDIM];
__device__ u16 g_xlo[(size_t)MPAD * HDIM];
__device__ u16 g_h1hi[(size_t)MPAD * HDIM];
__device__ u16 g_h2hi[(size_t)MPAD * HDIM];
__device__ u16 g_h2lo[(size_t)MPAD * HDIM];
__device__ u16 g_aghi[(size_t)MPAD * HDIM];
__device__ u16 g_o1hi[(size_t)MPAD * HDIM];
__device__ u16 g_o1lo[(size_t)MPAD * HDIM];
__device__ u16 g_o2hi[(size_t)MPAD * HDIM];

// fp16 hi/lo weights: W1,W2,W3 (256 cols) + concat conv weights (512 cols)
__device__ u16 g_whi[3 * WSZ];
__device__ u16 g_wlo[3 * WSZ];
__device__ u16 g_wc1hi[HDIM * 512];
__device__ u16 g_wc1lo[HDIM * 512];
__device__ u16 g_wc2hi[HDIM * 512];
__device__ u16 g_wc2lo[HDIM * 512];

// ---------------------------------------------------------------------------
// helpers
// ---------------------------------------------------------------------------
__device__ __forceinline__ uint32_t pack_f16x2(float lo, float hi) {
    __half2 h = __floats2half2_rn(lo, hi);
    return *reinterpret_cast<uint32_t*>(&h);
}

__device__ __forceinline__ float2 f16x2_to_f2(uint32_t u) {
    __half2 h = *reinterpret_cast<__half2*>(&u);
    return __half22float2(h);
}

__device__ __forceinline__ void ldsm_x4(uint32_t& r0, uint32_t& r1,
                                        uint32_t& r2, uint32_t& r3, uint32_t addr) {
    asm volatile("ldmatrix.sync.aligned.m8n8.x4.shared.b16 {%0,%1,%2,%3}, [%4];"
                 : "=r"(r0), "=r"(r1), "=r"(r2), "=r"(r3) : "r"(addr));
}

__device__ __forceinline__ void mma_f16(float c[4], const uint32_t a[4],
                                        const uint32_t b[2]) {
    asm volatile(
        "mma.sync.aligned.m16n8k16.row.col.f32.f16.f16.f32 "
        "{%0,%1,%2,%3}, {%4,%5,%6,%7}, {%8,%9}, {%0,%1,%2,%3};"
        : "+f"(c[0]), "+f"(c[1]), "+f"(c[2]), "+f"(c[3])
        : "r"(a[0]), "r"(a[1]), "r"(a[2]), "r"(a[3]), "r"(b[0]), "r"(b[1]));
}

#define CP16(sm, gp) \
    asm volatile("cp.async.cg.shared.global [%0], [%1], 16;" :: "r"(sm), "l"(gp))
#define CPCOMMIT() asm volatile("cp.async.commit_group;")
#define CPWAIT0()  asm volatile("cp.async.wait_group 0;")

// ---------------------------------------------------------------------------
// splits
// ---------------------------------------------------------------------------
__global__ void split_kernel(const float* __restrict__ in, u16* __restrict__ hi,
                             u16* __restrict__ lo, int n4)
{
    int i = blockIdx.x * blockDim.x + threadIdx.x;
    if (i >= n4) return;
    float4 v = ((const float4*)in)[i];
    float hx = __half2float(__float2half_rn(v.x));
    float hy = __half2float(__float2half_rn(v.y));
    float hz = __half2float(__float2half_rn(v.z));
    float hw = __half2float(__float2half_rn(v.w));
    uint2 h = make_uint2(pack_f16x2(v.x, v.y), pack_f16x2(v.z, v.w));
    uint2 l = make_uint2(pack_f16x2(v.x - hx, v.y - hy),
                         pack_f16x2(v.z - hz, v.w - hw));
    ((uint2*)hi)[i] = h;
    ((uint2*)lo)[i] = l;
}

// One launch splits all 7 weight matrices. blockIdx.y selects the matrix:
// 0..2 -> W1,W2,W3 (contiguous 256-col), 3..6 -> T10,T11,T20,T21 (512-col concat).
__global__ void split_all_w_kernel(const float* __restrict__ W1,
                                   const float* __restrict__ W2,
                                   const float* __restrict__ W3,
                                   const float* __restrict__ T10,
                                   const float* __restrict__ T11,
                                   const float* __restrict__ T20,
                                   const float* __restrict__ T21)
{
    int i = blockIdx.x * blockDim.x + threadIdx.x;
    if (i >= WSZ / 4) return;
    int w = blockIdx.y;
    const float* src = (w == 0) ? W1 : (w == 1) ? W2 : (w == 2) ? W3 :
                       (w == 3) ? T10 : (w == 4) ? T11 : (w == 5) ? T20 : T21;
    float4 v = ((const float4*)src)[i];
    float hx = __half2float(__float2half_rn(v.x));
    float hy = __half2float(__float2half_rn(v.y));
    float hz = __half2float(__float2half_rn(v.z));
    float hw = __half2float(__float2half_rn(v.w));
    uint2 h = make_uint2(pack_f16x2(v.x, v.y), pack_f16x2(v.z, v.w));
    uint2 l = make_uint2(pack_f16x2(v.x - hx, v.y - hy),
                         pack_f16x2(v.z - hz, v.w - hw));
    if (w < 3) {
        ((uint2*)(g_whi + (size_t)w * WSZ))[i] = h;
        ((uint2*)(g_wlo + (size_t)w * WSZ))[i] = l;
    } else {
        int row = i >> 6;
        int col = (i & 63) * 4;
        int colofs = ((w - 3) & 1) * 256;
        u16* dhi = (w < 5) ? g_wc1hi : g_wc2hi;
        u16* dlo = (w < 5) ? g_wc1lo : g_wc2lo;
        size_t o = (size_t)row * 512 + colofs + col;
        *(uint2*)(dhi + o) = h;
        *(uint2*)(dlo + o) = l;
    }
}

// ---------------------------------------------------------------------------
// GEMM: C[MPAD, colBase:+64] = A @ (Whi+Wlo)[colBase:+64]^T
// BASEP: passes for chunks < 8 (3 = exact split; 2 = a_hi*(W_hi+W_lo), for
// operands with no lo stream). AGGP: passes for chunks >= 8 (conv agg half;
// 1 = a_hi*W_hi only — that operand already carries ~2^-12 gather noise).
// OMODE 0: write fp16 output (hi always; lo only if OUTLO).
// OMODE 1: fused head — relu(acc+b3) . W4 partials, atomicAdd into out.
// Tile 128x64x32, 256 thr, warp tile 32x32, 3 CTAs/SM, 2-stage cp.async.
// ---------------------------------------------------------------------------
#define BM   128
#define KS   40
#define STG  30720
#define OA_HI 0
#define OA_LO 10240
#define OB_HI 20480
#define OB_LO 25600

template <int KCHUNKS, int BASEP, int AGGP, bool RELU, int OMODE, bool OUTLO>
__global__ __launch_bounds__(256, 3)
void gemm_mma_kernel(const u16* __restrict__ Ahi, const u16* __restrict__ Alo,
                     const u16* __restrict__ A2hi,
                     const u16* __restrict__ Whi, const u16* __restrict__ Wlo,
                     const float* __restrict__ bias,
                     u16* __restrict__ Chi, u16* __restrict__ Clo,
                     const float* __restrict__ W4v, float* __restrict__ outp)
{
    extern __shared__ char smem[];
    const uint32_t sb = (uint32_t)__cvta_generic_to_shared(smem);
    const int tid  = threadIdx.x;
    const int lane = tid & 31;
    const int wid  = tid >> 5;
    const int wm   = (wid & 3) * 32;
    const int wn   = (wid >> 2) * 32;
    const int rowBase = blockIdx.x * BM;
    const int colBase = blockIdx.y * 64;
    const int KTOT = KCHUNKS * 32;

    float acc[2][4][4];
#pragma unroll
    for (int mi = 0; mi < 2; mi++)
#pragma unroll
        for (int ni = 0; ni < 4; ni++)
#pragma unroll
            for (int j = 0; j < 4; j++) acc[mi][ni][j] = 0.0f;

    const int aRow = wm + (lane & 15);
    const int aColSel = (lane >> 4) * 8;
    const int bRow = wn + lane;

    auto load_chunk = [&](int c, int s) {
        uint32_t base = sb + (uint32_t)s * STG;
        const u16* pah = (c < 8) ? Ahi : A2hi;
        int ko = (c & 7) * 32;
        int k0 = c * 32;
        bool needALo = (c < 8) ? (BASEP == 3) : (AGGP == 3);
        bool needWLo = (c < 8) ? true : (AGGP >= 2);
#pragma unroll
        for (int i = 0; i < 2; i++) {
            int f   = tid + i * 256;
            int row = f >> 2;
            int c8  = (f & 3) * 8;
            uint32_t so = (uint32_t)(row * 80 + c8 * 2);
            CP16(base + OA_HI + so, pah + (size_t)(rowBase + row) * 256 + ko + c8);
            if (needALo)
                CP16(base + OA_LO + so, Alo + (size_t)(rowBase + row) * 256 + ko + c8);
        }
        {
            int row = tid >> 2;
            int c8  = (tid & 3) * 8;
            uint32_t so = (uint32_t)(row * 80 + c8 * 2);
            CP16(base + OB_HI + so, Whi + (size_t)(colBase + row) * KTOT + k0 + c8);
            if (needWLo)
                CP16(base + OB_LO + so, Wlo + (size_t)(colBase + row) * KTOT + k0 + c8);
        }
    };

    load_chunk(0, 0);
    CPCOMMIT();

#pragma unroll 1
    for (int c = 0; c < KCHUNKS; ++c) {
        const int s = c & 1;
        CPWAIT0();
        __syncthreads();
        if (c + 1 < KCHUNKS) { load_chunk(c + 1, s ^ 1); CPCOMMIT(); }

        const uint32_t stgBase = sb + (uint32_t)s * STG;
        const bool doALo = (c < 8) ? (BASEP == 3) : (AGGP == 3);
        const bool doWLo = (c < 8) ? true : (AGGP >= 2);
#pragma unroll
        for (int kk = 0; kk < 32; kk += 16) {
            uint32_t ah[2][4], al[2][4];
#pragma unroll
            for (int mi = 0; mi < 2; mi++) {
                uint32_t ao = (uint32_t)(((aRow + mi * 16) * KS + kk + aColSel) * 2);
                ldsm_x4(ah[mi][0], ah[mi][1], ah[mi][2], ah[mi][3],
                        stgBase + OA_HI + ao);
                if (doALo)
                    ldsm_x4(al[mi][0], al[mi][1], al[mi][2], al[mi][3],
                            stgBase + OA_LO + ao);
            }
            uint32_t b[4][2];
            // W_hi with a_hi (and a_lo when enabled)
            {
                uint32_t r0, r1, r2, r3;
                uint32_t addr = stgBase + OB_HI + (uint32_t)((bRow * KS + kk) * 2);
                ldsm_x4(r0, r1, r2, r3, addr);
                b[0][0] = r0; b[1][0] = r1; b[2][0] = r2; b[3][0] = r3;
                addr += 16;
                ldsm_x4(r0, r1, r2, r3, addr);
                b[0][1] = r0; b[1][1] = r1; b[2][1] = r2; b[3][1] = r3;
            }
#pragma unroll
            for (int mi = 0; mi < 2; mi++)
#pragma unroll
                for (int ni = 0; ni < 4; ni++)
                    mma_f16(acc[mi][ni], ah[mi], b[ni]);
            if (doALo) {
#pragma unroll
                for (int mi = 0; mi < 2; mi++)
#pragma unroll
                    for (int ni = 0; ni < 4; ni++)
                        mma_f16(acc[mi][ni], al[mi], b[ni]);
            }
            // W_lo with a_hi
            if (doWLo) {
                uint32_t r0, r1, r2, r3;
                uint32_t addr = stgBase + OB_LO + (uint32_t)((bRow * KS + kk) * 2);
                ldsm_x4(r0, r1, r2, r3, addr);
                b[0][0] = r0; b[1][0] = r1; b[2][0] = r2; b[3][0] = r3;
                addr += 16;
                ldsm_x4(r0, r1, r2, r3, addr);
                b[0][1] = r0; b[1][1] = r1; b[2][1] = r2; b[3][1] = r3;
#pragma unroll
                for (int mi = 0; mi < 2; mi++)
#pragma unroll
                    for (int ni = 0; ni < 4; ni++)
                        mma_f16(acc[mi][ni], ah[mi], b[ni]);
            }
        }
        __syncthreads();
    }

    // ---- epilogue ----
#pragma unroll
    for (int mi = 0; mi < 2; mi++) {
        int row0 = rowBase + wm + mi * 16 + (lane >> 2);
        int row1 = row0 + 8;
        float p00 = 0.f, p01 = 0.f, p10 = 0.f, p11 = 0.f;
#pragma unroll
        for (int ni = 0; ni < 4; ni++) {
            int col = colBase + wn + ni * 8 + (lane & 3) * 2;
            float bx = __ldg(bias + col), by = __ldg(bias + col + 1);
            float2 o0 = make_float2(acc[mi][ni][0] + bx, acc[mi][ni][1] + by);
            float2 o1 = make_float2(acc[mi][ni][2] + bx, acc[mi][ni][3] + by);
            if (RELU) {
                o0.x = fmaxf(o0.x, 0.f); o0.y = fmaxf(o0.y, 0.f);
                o1.x = fmaxf(o1.x, 0.f); o1.y = fmaxf(o1.y, 0.f);
            }
            if (OMODE == 0) {
                *(uint32_t*)(Chi + (size_t)row0 * 256 + col) = pack_f16x2(o0.x, o0.y);
                *(uint32_t*)(Chi + (size_t)row1 * 256 + col) = pack_f16x2(o1.x, o1.y);
                if (OUTLO) {
                    float hx = __half2float(__float2half_rn(o0.x));
                    float hy = __half2float(__float2half_rn(o0.y));
                    *(uint32_t*)(Clo + (size_t)row0 * 256 + col) =
                        pack_f16x2(o0.x - hx, o0.y - hy);
                    hx = __half2float(__float2half_rn(o1.x));
                    hy = __half2float(__float2half_rn(o1.y));
                    *(uint32_t*)(Clo + (size_t)row1 * 256 + col) =
                        pack_f16x2(o1.x - hx, o1.y - hy);
                }
            } else {
                float wa = __ldg(W4v + col),       wb = __ldg(W4v + col + 1);
                float wc = __ldg(W4v + 256 + col), wd = __ldg(W4v + 256 + col + 1);
                p00 = fmaf(o0.x, wa, fmaf(o0.y, wb, p00));
                p01 = fmaf(o0.x, wc, fmaf(o0.y, wd, p01));
                p10 = fmaf(o1.x, wa, fmaf(o1.y, wb, p10));
                p11 = fmaf(o1.x, wc, fmaf(o1.y, wd, p11));
            }
        }
        if (OMODE == 1) {
            p00 += __shfl_xor_sync(0xFFFFFFFFu, p00, 1);
            p00 += __shfl_xor_sync(0xFFFFFFFFu, p00, 2);
            p01 += __shfl_xor_sync(0xFFFFFFFFu, p01, 1);
            p01 += __shfl_xor_sync(0xFFFFFFFFu, p01, 2);
            p10 += __shfl_xor_sync(0xFFFFFFFFu, p10, 1);
            p10 += __shfl_xor_sync(0xFFFFFFFFu, p10, 2);
            p11 += __shfl_xor_sync(0xFFFFFFFFu, p11, 1);
            p11 += __shfl_xor_sync(0xFFFFFFFFu, p11, 2);
            if ((lane & 3) == 0) {
                if (row0 < N_NODES) {
                    atomicAdd(outp + (size_t)row0 * 2,     p00);
                    atomicAdd(outp + (size_t)row0 * 2 + 1, p01);
                }
                if (row1 < N_NODES) {
                    atomicAdd(outp + (size_t)row1 * 2,     p10);
                    atomicAdd(outp + (size_t)row1 * 2 + 1, p11);
                }
            }
        }
    }
}

// ---------------------------------------------------------------------------
// CSR build
// ---------------------------------------------------------------------------
__global__ void zero_cnt_kernel() {
    int i = blockIdx.x * blockDim.x + threadIdx.x;
    if (i < N_NODES) { g_degi[i] = 0; g_cnt[i] = 0; }
}

__global__ void hist_kernel(const int* __restrict__ src, const int* __restrict__ dst) {
    int e = blockIdx.x * blockDim.x + threadIdx.x;
    if (e < E_EDGES) {
        atomicAdd(&g_degi[src[e]], 1);
        atomicAdd(&g_cnt[dst[e]], 1);
    }
}

__global__ void partial_dis_kernel() {
    __shared__ int sh[256];
    int i = blockIdx.x * 256 + threadIdx.x;
    if (i < N_NODES) {
        int d = g_degi[i];
        g_dis[i] = (d > 0) ? rsqrtf((float)d) : 0.0f;
    }
    sh[threadIdx.x] = (i < N_NODES) ? g_cnt[i] : 0;
    __syncthreads();
#pragma unroll
    for (int o = 128; o > 0; o >>= 1) {
        if (threadIdx.x < o) sh[threadIdx.x] += sh[threadIdx.x + o];
        __syncthreads();
    }
    if (threadIdx.x == 0) g_bsum[blockIdx.x] = sh[0];
}

__global__ void scan_blocks_kernel() {
    __shared__ int sh[256];
    int tid = threadIdx.x;
    int v = (tid < NBLK) ? g_bsum[tid] : 0;
    sh[tid] = v;
    __syncthreads();
#pragma unroll
    for (int o = 1; o < 256; o <<= 1) {
        int t = (tid >= o) ? sh[tid - o] : 0;
        __syncthreads();
        sh[tid] += t;
        __syncthreads();
    }
    g_boff[tid] = sh[tid] - v;
}

__global__ void apply_kernel() {
    __shared__ int sh[256];
    int tid = threadIdx.x;
    int i = blockIdx.x * 256 + tid;
    int v = (i < N_NODES) ? g_cnt[i] : 0;
    sh[tid] = v;
    __syncthreads();
#pragma unroll
    for (int o = 1; o < 256; o <<= 1) {
        int t = (tid >= o) ? sh[tid - o] : 0;
        __syncthreads();
        sh[tid] += t;
        __syncthreads();
    }
    if (i < N_NODES) {
        int excl = sh[tid] - v + g_boff[blockIdx.x];
        g_rowstart[i] = excl;
        g_cursor[i]   = excl;
    }
}

__global__ void fill_kernel(const int* __restrict__ src, const int* __restrict__ dst) {
    int e = blockIdx.x * blockDim.x + threadIdx.x;
    if (e < E_EDGES) {
        int s = src[e], d = dst[e];
        int pos = atomicAdd(&g_cursor[d], 1);
        g_csr_src[pos] = s;
        g_csr_w[pos]   = -g_dis[s] * g_dis[d];
    }
}

// ---------------------------------------------------------------------------
// Gather (hi-only input AND hi-only output)
// ---------------------------------------------------------------------------
__global__ __launch_bounds__(256)
void gather_kernel(const u16* __restrict__ hi, u16* __restrict__ outhi)
{
    int node = (blockIdx.x * blockDim.x + threadIdx.x) >> 5;
    int lane = threadIdx.x & 31;
    if (node >= N_NODES) return;

    float a[8] = {0.f, 0.f, 0.f, 0.f, 0.f, 0.f, 0.f, 0.f};

    int p   = g_rowstart[node];
    int end = p + g_cnt[node];

#pragma unroll 1
    for (; p + 3 < end; p += 4) {
        int   s0 = __ldg(&g_csr_src[p]);
        int   s1 = __ldg(&g_csr_src[p + 1]);
        int   s2 = __ldg(&g_csr_src[p + 2]);
        int   s3 = __ldg(&g_csr_src[p + 3]);
        float w0 = __ldg(&g_csr_w[p]);
        float w1 = __ldg(&g_csr_w[p + 1]);
        float w2 = __ldg(&g_csr_w[p + 2]);
        float w3 = __ldg(&g_csr_w[p + 3]);
        uint4 h0 = *(const uint4*)(hi + (size_t)s0 * 256 + lane * 8);
        uint4 h1 = *(const uint4*)(hi + (size_t)s1 * 256 + lane * 8);
        uint4 h2 = *(const uint4*)(hi + (size_t)s2 * 256 + lane * 8);
        uint4 h3 = *(const uint4*)(hi + (size_t)s3 * 256 + lane * 8);
#pragma unroll
        for (int q = 0; q < 4; q++) {
            float2 f0 = f16x2_to_f2((&h0.x)[q]);
            float2 f1 = f16x2_to_f2((&h1.x)[q]);
            float2 f2 = f16x2_to_f2((&h2.x)[q]);
            float2 f3 = f16x2_to_f2((&h3.x)[q]);
            a[q*2]   = fmaf(w0, f0.x, a[q*2]);
            a[q*2+1] = fmaf(w0, f0.y, a[q*2+1]);
            a[q*2]   = fmaf(w1, f1.x, a[q*2]);
            a[q*2+1] = fmaf(w1, f1.y, a[q*2+1]);
            a[q*2]   = fmaf(w2, f2.x, a[q*2]);
            a[q*2+1] = fmaf(w2, f2.y, a[q*2+1]);
            a[q*2]   = fmaf(w3, f3.x, a[q*2]);
            a[q*2+1] = fmaf(w3, f3.y, a[q*2+1]);
        }
    }
#pragma unroll 1
    for (; p < end; ++p) {
        int   s0 = __ldg(&g_csr_src[p]);
        float w0 = __ldg(&g_csr_w[p]);
        uint4 h0 = *(const uint4*)(hi + (size_t)s0 * 256 + lane * 8);
#pragma unroll
        for (int q = 0; q < 4; q++) {
            float2 f0 = f16x2_to_f2((&h0.x)[q]);
            a[q*2]   = fmaf(w0, f0.x, a[q*2]);
            a[q*2+1] = fmaf(w0, f0.y, a[q*2+1]);
        }
    }

    uint4 hh;
#pragma unroll
    for (int q = 0; q < 4; q++)
        (&hh.x)[q] = pack_f16x2(a[q*2], a[q*2+1]);
    __stcs((uint4*)(outhi + (size_t)node * 256 + lane * 8), hh);
}

// out[i] = b4[i&1]
__global__ void init_out_kernel(float* __restrict__ out,
                                const float* __restrict__ b4)
{
    int i = blockIdx.x * blockDim.x + threadIdx.x;
    if (i < N_NODES * 2) out[i] = __ldg(b4 + (i & 1));
}

// ---------------------------------------------------------------------------
// Launch sequence (single stream — capture-safe)
// ---------------------------------------------------------------------------
extern "C" void kernel_launch(void* const* d_in, const int* in_sizes, int n_in,
                              void* d_out, int out_size)
{
    const float* x    = (const float*)d_in[0];
    const int*   ei   = (const int*)  d_in[1];
    const float* W1   = (const float*)d_in[2];
    const float* b1   = (const float*)d_in[3];
    const float* W2   = (const float*)d_in[4];
    const float* b2   = (const float*)d_in[5];
    const float* W3   = (const float*)d_in[6];
    const float* b3   = (const float*)d_in[7];
    const float* W4   = (const float*)d_in[8];
    const float* b4   = (const float*)d_in[9];
    const float* T10  = (const float*)d_in[10];
    const float* T11  = (const float*)d_in[11];
    const float* cb1  = (const float*)d_in[12];
    const float* T20  = (const float*)d_in[13];
    const float* T21  = (const float*)d_in[14];
    const float* cb2  = (const float*)d_in[15];
    float* out = (float*)d_out;

    const int* src = ei;
    const int* dst = ei + E_EDGES;

    u16 *xhi, *xlo, *h1hi, *h2hi, *h2lo, *aghi;
    u16 *o1hi, *o1lo, *o2hi, *whi, *wlo;
    u16 *wc1hi, *wc1lo, *wc2hi, *wc2lo;
    cudaGetSymbolAddress((void**)&xhi, g_xhi);
    cudaGetSymbolAddress((void**)&xlo, g_xlo);
    cudaGetSymbolAddress((void**)&h1hi, g_h1hi);
    cudaGetSymbolAddress((void**)&h2hi, g_h2hi);
    cudaGetSymbolAddress((void**)&h2lo, g_h2lo);
    cudaGetSymbolAddress((void**)&aghi, g_aghi);
    cudaGetSymbolAddress((void**)&o1hi, g_o1hi);
    cudaGetSymbolAddress((void**)&o1lo, g_o1lo);
    cudaGetSymbolAddress((void**)&o2hi, g_o2hi);
    cudaGetSymbolAddress((void**)&whi, g_whi);
    cudaGetSymbolAddress((void**)&wlo, g_wlo);
    cudaGetSymbolAddress((void**)&wc1hi, g_wc1hi);
    cudaGetSymbolAddress((void**)&wc1lo, g_wc1lo);
    cudaGetSymbolAddress((void**)&wc2hi, g_wc2hi);
    cudaGetSymbolAddress((void**)&wc2lo, g_wc2lo);

    const int SMEMSZ = 2 * STG;   // 61440

    cudaFuncSetAttribute(gemm_mma_kernel<8,  3, 3, true,  0, false>,
                         cudaFuncAttributeMaxDynamicSharedMemorySize, SMEMSZ);
    cudaFuncSetAttribute(gemm_mma_kernel<8,  2, 3, true,  0, true>,
                         cudaFuncAttributeMaxDynamicSharedMemorySize, SMEMSZ);
    cudaFuncSetAttribute(gemm_mma_kernel<16, 3, 1, false, 0, true>,
                         cudaFuncAttributeMaxDynamicSharedMemorySize, SMEMSZ);
    cudaFuncSetAttribute(gemm_mma_kernel<16, 3, 1, false, 0, false>,
                         cudaFuncAttributeMaxDynamicSharedMemorySize, SMEMSZ);
    cudaFuncSetAttribute(gemm_mma_kernel<8,  2, 3, true,  1, false>,
                         cudaFuncAttributeMaxDynamicSharedMemorySize, SMEMSZ);

    dim3 ggrid(MPAD / BM, 4);    // (391, 4)
    const int gthr = (N_NODES * 32 + 255) / 256;
    const int wblk = (WSZ / 4 + 255) / 256;

    // --- input/weight splits + MLP GEMMs ---
    split_kernel<<<(N_NODES * HDIM / 4 + 255) / 256, 256>>>(x, xhi, xlo,
                                                            N_NODES * HDIM / 4);
    split_all_w_kernel<<<dim3(wblk, 7), 256>>>(W1, W2, W3, T10, T11, T20, T21);
    // h1 = relu(x@W1+b1): exact 3-pass; hi-only output
    gemm_mma_kernel<8, 3, 3, true, 0, false><<<ggrid, 256, SMEMSZ>>>(
        xhi, xlo, nullptr, whi + 0 * WSZ, wlo + 0 * WSZ, b1,
        h1hi, nullptr, nullptr, nullptr);
    // h2 = relu(h1@W2+b2): 2-pass on A (h1 hi only); exact hi/lo output
    gemm_mma_kernel<8, 2, 3, true, 0, true><<<ggrid, 256, SMEMSZ>>>(
        h1hi, nullptr, nullptr, whi + 1 * WSZ, wlo + 1 * WSZ, b2,
        h2hi, h2lo, nullptr, nullptr);

    // --- CSR build ---
    zero_cnt_kernel<<<(N_NODES + 255) / 256, 256>>>();
    hist_kernel<<<(E_EDGES + 255) / 256, 256>>>(src, dst);
    partial_dis_kernel<<<NBLK, 256>>>();
    scan_blocks_kernel<<<1, 256>>>();
    apply_kernel<<<NBLK, 256>>>();
    fill_kernel<<<(E_EDGES + 255) / 256, 256>>>(src, dst);

    // --- conv 1: agg = S h2 (hi-only) ; out1 = [h2, agg] @ [T10;T11]^T + cb1 ---
    gather_kernel<<<gthr, 256>>>(h2hi, aghi);
    gemm_mma_kernel<16, 3, 1, false, 0, true><<<ggrid, 256, SMEMSZ>>>(
        h2hi, h2lo, aghi, wc1hi, wc1lo, cb1,
        o1hi, o1lo, nullptr, nullptr);

    // --- conv 2: agg = S out1 (hi-only) ; out2 (hi only) ---
    gather_kernel<<<gthr, 256>>>(o1hi, aghi);
    gemm_mma_kernel<16, 3, 1, false, 0, false><<<ggrid, 256, SMEMSZ>>>(
        o1hi, o1lo, aghi, wc2hi, wc2lo, cb2,
        o2hi, nullptr, nullptr, nullptr);

    // --- fused: out = relu(out2@W3^T + b3) @ W4^T + b4 (2-pass A: hi only) ---
    init_out_kernel<<<(N_NODES * 2 + 255) / 256, 256>>>(out, b4);
    gemm_mma_kernel<8, 2, 3, true, 1, false><<<ggrid, 256, SMEMSZ>>>(
        o2hi, nullptr, nullptr, whi + 2 * WSZ, wlo + 2 * WSZ, b3,
        nullptr, nullptr, W4, out);
}

// round 17
// speedup vs baseline: 1.4756x; 1.0631x over previous
#include <cuda_runtime.h>
#include <cuda_fp16.h>
#include <cstdint>

#define N_NODES 50000
#define MPAD    50048
#define E_EDGES 1600000
#define HDIM    256
#define NBLK    196
#define WSZ     (HDIM * HDIM)

typedef unsigned short u16;

// ---------------------------------------------------------------------------
// Static device scratch
// ---------------------------------------------------------------------------
__device__ int   g_degi[N_NODES];
__device__ int   g_cnt[N_NODES];
__device__ int   g_rowstart[N_NODES];
__device__ int   g_cursor[N_NODES];
__device__ float g_dis[N_NODES];
__device__ int   g_csr_src[E_EDGES];
__device__ float g_csr_w[E_EDGES];
__device__ int   g_bsum[256];
__device__ int   g_boff[256];

// fp16 activations
__device__ u16 g_xhi[(size_t)MPAD * HDIM];
__device__ u16 g_xlo[(size_t)MPAD * HDIM];
__device__ u16 g_h1hi[(size_t)MPAD * HDIM];
__device__ u16 g_h2hi[(size_t)MPAD * HDIM];
__device__ u16 g_h2lo[(size_t)MPAD * HDIM];
__device__ u16 g_aghi[(size_t)MPAD * HDIM];
__device__ u16 g_o1hi[(size_t)MPAD * HDIM];
__device__ u16 g_o2hi[(size_t)MPAD * HDIM];

// fp16 hi/lo weights: W1,W2,W3 (256 cols) + concat conv weights (512 cols)
__device__ u16 g_whi[3 * WSZ];
__device__ u16 g_wlo[3 * WSZ];
__device__ u16 g_wc1hi[HDIM * 512];
__device__ u16 g_wc1lo[HDIM * 512];
__device__ u16 g_wc2hi[HDIM * 512];
__device__ u16 g_wc2lo[HDIM * 512];

// ---------------------------------------------------------------------------
// helpers
// ---------------------------------------------------------------------------
__device__ __forceinline__ uint32_t pack_f16x2(float lo, float hi) {
    __half2 h = __floats2half2_rn(lo, hi);
    return *reinterpret_cast<uint32_t*>(&h);
}

__device__ __forceinline__ float2 f16x2_to_f2(uint32_t u) {
    __half2 h = *reinterpret_cast<__half2*>(&u);
    return __half22float2(h);
}

__device__ __forceinline__ void ldsm_x4(uint32_t& r0, uint32_t& r1,
                                        uint32_t& r2, uint32_t& r3, uint32_t addr) {
    asm volatile("ldmatrix.sync.aligned.m8n8.x4.shared.b16 {%0,%1,%2,%3}, [%4];"
                 : "=r"(r0), "=r"(r1), "=r"(r2), "=r"(r3) : "r"(addr));
}

__device__ __forceinline__ void mma_f16(float c[4], const uint32_t a[4],
                                        const uint32_t b[2]) {
    asm volatile(
        "mma.sync.aligned.m16n8k16.row.col.f32.f16.f16.f32 "
        "{%0,%1,%2,%3}, {%4,%5,%6,%7}, {%8,%9}, {%0,%1,%2,%3};"
        : "+f"(c[0]), "+f"(c[1]), "+f"(c[2]), "+f"(c[3])
        : "r"(a[0]), "r"(a[1]), "r"(a[2]), "r"(a[3]), "r"(b[0]), "r"(b[1]));
}

#define CP16(sm, gp) \
    asm volatile("cp.async.cg.shared.global [%0], [%1], 16;" :: "r"(sm), "l"(gp))
#define CPCOMMIT() asm volatile("cp.async.commit_group;")
#define CPWAIT0()  asm volatile("cp.async.wait_group 0;")

// ---------------------------------------------------------------------------
// splits
// ---------------------------------------------------------------------------
__global__ void split_kernel(const float* __restrict__ in, u16* __restrict__ hi,
                             u16* __restrict__ lo, int n4)
{
    int i = blockIdx.x * blockDim.x + threadIdx.x;
    if (i >= n4) return;
    float4 v = ((const float4*)in)[i];
    float hx = __half2float(__float2half_rn(v.x));
    float hy = __half2float(__float2half_rn(v.y));
    float hz = __half2float(__float2half_rn(v.z));
    float hw = __half2float(__float2half_rn(v.w));
    uint2 h = make_uint2(pack_f16x2(v.x, v.y), pack_f16x2(v.z, v.w));
    uint2 l = make_uint2(pack_f16x2(v.x - hx, v.y - hy),
                         pack_f16x2(v.z - hz, v.w - hw));
    ((uint2*)hi)[i] = h;
    ((uint2*)lo)[i] = l;
}

// One launch splits all 7 weight matrices. blockIdx.y selects the matrix:
// 0..2 -> W1,W2,W3 (contiguous 256-col), 3..6 -> T10,T11,T20,T21 (512-col concat).
__global__ void split_all_w_kernel(const float* __restrict__ W1,
                                   const float* __restrict__ W2,
                                   const float* __restrict__ W3,
                                   const float* __restrict__ T10,
                                   const float* __restrict__ T11,
                                   const float* __restrict__ T20,
                                   const float* __restrict__ T21)
{
    int i = blockIdx.x * blockDim.x + threadIdx.x;
    if (i >= WSZ / 4) return;
    int w = blockIdx.y;
    const float* src = (w == 0) ? W1 : (w == 1) ? W2 : (w == 2) ? W3 :
                       (w == 3) ? T10 : (w == 4) ? T11 : (w == 5) ? T20 : T21;
    float4 v = ((const float4*)src)[i];
    float hx = __half2float(__float2half_rn(v.x));
    float hy = __half2float(__float2half_rn(v.y));
    float hz = __half2float(__float2half_rn(v.z));
    float hw = __half2float(__float2half_rn(v.w));
    uint2 h = make_uint2(pack_f16x2(v.x, v.y), pack_f16x2(v.z, v.w));
    uint2 l = make_uint2(pack_f16x2(v.x - hx, v.y - hy),
                         pack_f16x2(v.z - hz, v.w - hw));
    if (w < 3) {
        ((uint2*)(g_whi + (size_t)w * WSZ))[i] = h;
        ((uint2*)(g_wlo + (size_t)w * WSZ))[i] = l;
    } else {
        int row = i >> 6;
        int col = (i & 63) * 4;
        int colofs = ((w - 3) & 1) * 256;
        u16* dhi = (w < 5) ? g_wc1hi : g_wc2hi;
        u16* dlo = (w < 5) ? g_wc1lo : g_wc2lo;
        size_t o = (size_t)row * 512 + colofs + col;
        *(uint2*)(dhi + o) = h;
        *(uint2*)(dlo + o) = l;
    }
}

// ---------------------------------------------------------------------------
// GEMM: C[MPAD, colBase:+64] = A @ (Whi+Wlo)[colBase:+64]^T
// BASEP: passes for chunks < 8 (3 = exact split; 2 = a_hi*(W_hi+W_lo), for
// operands with no lo stream). AGGP: passes for chunks >= 8 (conv agg half;
// 1 = a_hi*W_hi only — that operand already carries ~2^-12 gather noise).
// OMODE 0: write fp16 output (hi always; lo only if OUTLO).
// OMODE 1: fused head — relu(acc+b3) . W4 partials, atomicAdd into out.
// Tile 128x64x32, 256 thr, warp tile 32x32, 3 CTAs/SM, 2-stage cp.async.
// ---------------------------------------------------------------------------
#define BM   128
#define KS   40
#define STG  30720
#define OA_HI 0
#define OA_LO 10240
#define OB_HI 20480
#define OB_LO 25600

template <int KCHUNKS, int BASEP, int AGGP, bool RELU, int OMODE, bool OUTLO>
__global__ __launch_bounds__(256, 3)
void gemm_mma_kernel(const u16* __restrict__ Ahi, const u16* __restrict__ Alo,
                     const u16* __restrict__ A2hi,
                     const u16* __restrict__ Whi, const u16* __restrict__ Wlo,
                     const float* __restrict__ bias,
                     u16* __restrict__ Chi, u16* __restrict__ Clo,
                     const float* __restrict__ W4v, float* __restrict__ outp)
{
    extern __shared__ char smem[];
    const uint32_t sb = (uint32_t)__cvta_generic_to_shared(smem);
    const int tid  = threadIdx.x;
    const int lane = tid & 31;
    const int wid  = tid >> 5;
    const int wm   = (wid & 3) * 32;
    const int wn   = (wid >> 2) * 32;
    const int rowBase = blockIdx.x * BM;
    const int colBase = blockIdx.y * 64;
    const int KTOT = KCHUNKS * 32;

    float acc[2][4][4];
#pragma unroll
    for (int mi = 0; mi < 2; mi++)
#pragma unroll
        for (int ni = 0; ni < 4; ni++)
#pragma unroll
            for (int j = 0; j < 4; j++) acc[mi][ni][j] = 0.0f;

    const int aRow = wm + (lane & 15);
    const int aColSel = (lane >> 4) * 8;
    const int bRow = wn + lane;

    auto load_chunk = [&](int c, int s) {
        uint32_t base = sb + (uint32_t)s * STG;
        const u16* pah = (c < 8) ? Ahi : A2hi;
        int ko = (c & 7) * 32;
        int k0 = c * 32;
        bool needALo = (c < 8) ? (BASEP == 3) : (AGGP == 3);
        bool needWLo = (c < 8) ? true : (AGGP >= 2);
#pragma unroll
        for (int i = 0; i < 2; i++) {
            int f   = tid + i * 256;
            int row = f >> 2;
            int c8  = (f & 3) * 8;
            uint32_t so = (uint32_t)(row * 80 + c8 * 2);
            CP16(base + OA_HI + so, pah + (size_t)(rowBase + row) * 256 + ko + c8);
            if (needALo)
                CP16(base + OA_LO + so, Alo + (size_t)(rowBase + row) * 256 + ko + c8);
        }
        {
            int row = tid >> 2;
            int c8  = (tid & 3) * 8;
            uint32_t so = (uint32_t)(row * 80 + c8 * 2);
            CP16(base + OB_HI + so, Whi + (size_t)(colBase + row) * KTOT + k0 + c8);
            if (needWLo)
                CP16(base + OB_LO + so, Wlo + (size_t)(colBase + row) * KTOT + k0 + c8);
        }
    };

    load_chunk(0, 0);
    CPCOMMIT();

#pragma unroll 1
    for (int c = 0; c < KCHUNKS; ++c) {
        const int s = c & 1;
        CPWAIT0();
        __syncthreads();
        if (c + 1 < KCHUNKS) { load_chunk(c + 1, s ^ 1); CPCOMMIT(); }

        const uint32_t stgBase = sb + (uint32_t)s * STG;
        const bool doALo = (c < 8) ? (BASEP == 3) : (AGGP == 3);
        const bool doWLo = (c < 8) ? true : (AGGP >= 2);
#pragma unroll
        for (int kk = 0; kk < 32; kk += 16) {
            uint32_t ah[2][4], al[2][4];
#pragma unroll
            for (int mi = 0; mi < 2; mi++) {
                uint32_t ao = (uint32_t)(((aRow + mi * 16) * KS + kk + aColSel) * 2);
                ldsm_x4(ah[mi][0], ah[mi][1], ah[mi][2], ah[mi][3],
                        stgBase + OA_HI + ao);
                if (doALo)
                    ldsm_x4(al[mi][0], al[mi][1], al[mi][2], al[mi][3],
                            stgBase + OA_LO + ao);
            }
            uint32_t b[4][2];
            // W_hi with a_hi (and a_lo when enabled)
            {
                uint32_t r0, r1, r2, r3;
                uint32_t addr = stgBase + OB_HI + (uint32_t)((bRow * KS + kk) * 2);
                ldsm_x4(r0, r1, r2, r3, addr);
                b[0][0] = r0; b[1][0] = r1; b[2][0] = r2; b[3][0] = r3;
                addr += 16;
                ldsm_x4(r0, r1, r2, r3, addr);
                b[0][1] = r0; b[1][1] = r1; b[2][1] = r2; b[3][1] = r3;
            }
#pragma unroll
            for (int mi = 0; mi < 2; mi++)
#pragma unroll
                for (int ni = 0; ni < 4; ni++)
                    mma_f16(acc[mi][ni], ah[mi], b[ni]);
            if (doALo) {
#pragma unroll
                for (int mi = 0; mi < 2; mi++)
#pragma unroll
                    for (int ni = 0; ni < 4; ni++)
                        mma_f16(acc[mi][ni], al[mi], b[ni]);
            }
            // W_lo with a_hi
            if (doWLo) {
                uint32_t r0, r1, r2, r3;
                uint32_t addr = stgBase + OB_LO + (uint32_t)((bRow * KS + kk) * 2);
                ldsm_x4(r0, r1, r2, r3, addr);
                b[0][0] = r0; b[1][0] = r1; b[2][0] = r2; b[3][0] = r3;
                addr += 16;
                ldsm_x4(r0, r1, r2, r3, addr);
                b[0][1] = r0; b[1][1] = r1; b[2][1] = r2; b[3][1] = r3;
#pragma unroll
                for (int mi = 0; mi < 2; mi++)
#pragma unroll
                    for (int ni = 0; ni < 4; ni++)
                        mma_f16(acc[mi][ni], ah[mi], b[ni]);
            }
        }
        __syncthreads();
    }

    // ---- epilogue ----
#pragma unroll
    for (int mi = 0; mi < 2; mi++) {
        int row0 = rowBase + wm + mi * 16 + (lane >> 2);
        int row1 = row0 + 8;
        float p00 = 0.f, p01 = 0.f, p10 = 0.f, p11 = 0.f;
#pragma unroll
        for (int ni = 0; ni < 4; ni++) {
            int col = colBase + wn + ni * 8 + (lane & 3) * 2;
            float bx = __ldg(bias + col), by = __ldg(bias + col + 1);
            float2 o0 = make_float2(acc[mi][ni][0] + bx, acc[mi][ni][1] + by);
            float2 o1 = make_float2(acc[mi][ni][2] + bx, acc[mi][ni][3] + by);
            if (RELU) {
                o0.x = fmaxf(o0.x, 0.f); o0.y = fmaxf(o0.y, 0.f);
                o1.x = fmaxf(o1.x, 0.f); o1.y = fmaxf(o1.y, 0.f);
            }
            if (OMODE == 0) {
                *(uint32_t*)(Chi + (size_t)row0 * 256 + col) = pack_f16x2(o0.x, o0.y);
                *(uint32_t*)(Chi + (size_t)row1 * 256 + col) = pack_f16x2(o1.x, o1.y);
                if (OUTLO) {
                    float hx = __half2float(__float2half_rn(o0.x));
                    float hy = __half2float(__float2half_rn(o0.y));
                    *(uint32_t*)(Clo + (size_t)row0 * 256 + col) =
                        pack_f16x2(o0.x - hx, o0.y - hy);
                    hx = __half2float(__float2half_rn(o1.x));
                    hy = __half2float(__float2half_rn(o1.y));
                    *(uint32_t*)(Clo + (size_t)row1 * 256 + col) =
                        pack_f16x2(o1.x - hx, o1.y - hy);
                }
            } else {
                float wa = __ldg(W4v + col),       wb = __ldg(W4v + col + 1);
                float wc = __ldg(W4v + 256 + col), wd = __ldg(W4v + 256 + col + 1);
                p00 = fmaf(o0.x, wa, fmaf(o0.y, wb, p00));
                p01 = fmaf(o0.x, wc, fmaf(o0.y, wd, p01));
                p10 = fmaf(o1.x, wa, fmaf(o1.y, wb, p10));
                p11 = fmaf(o1.x, wc, fmaf(o1.y, wd, p11));
            }
        }
        if (OMODE == 1) {
            p00 += __shfl_xor_sync(0xFFFFFFFFu, p00, 1);
            p00 += __shfl_xor_sync(0xFFFFFFFFu, p00, 2);
            p01 += __shfl_xor_sync(0xFFFFFFFFu, p01, 1);
            p01 += __shfl_xor_sync(0xFFFFFFFFu, p01, 2);
            p10 += __shfl_xor_sync(0xFFFFFFFFu, p10, 1);
            p10 += __shfl_xor_sync(0xFFFFFFFFu, p10, 2);
            p11 += __shfl_xor_sync(0xFFFFFFFFu, p11, 1);
            p11 += __shfl_xor_sync(0xFFFFFFFFu, p11, 2);
            if ((lane & 3) == 0) {
                if (row0 < N_NODES) {
                    atomicAdd(outp + (size_t)row0 * 2,     p00);
                    atomicAdd(outp + (size_t)row0 * 2 + 1, p01);
                }
                if (row1 < N_NODES) {
                    atomicAdd(outp + (size_t)row1 * 2,     p10);
                    atomicAdd(outp + (size_t)row1 * 2 + 1, p11);
                }
            }
        }
    }
}

// ---------------------------------------------------------------------------
// CSR build
// ---------------------------------------------------------------------------
__global__ void zero_cnt_kernel() {
    int i = blockIdx.x * blockDim.x + threadIdx.x;
    if (i < N_NODES) { g_degi[i] = 0; g_cnt[i] = 0; }
}

__global__ void hist_kernel(const int* __restrict__ src, const int* __restrict__ dst) {
    int e = blockIdx.x * blockDim.x + threadIdx.x;
    if (e < E_EDGES) {
        atomicAdd(&g_degi[src[e]], 1);
        atomicAdd(&g_cnt[dst[e]], 1);
    }
}

__global__ void partial_dis_kernel() {
    __shared__ int sh[256];
    int i = blockIdx.x * 256 + threadIdx.x;
    if (i < N_NODES) {
        int d = g_degi[i];
        g_dis[i] = (d > 0) ? rsqrtf((float)d) : 0.0f;
    }
    sh[threadIdx.x] = (i < N_NODES) ? g_cnt[i] : 0;
    __syncthreads();
#pragma unroll
    for (int o = 128; o > 0; o >>= 1) {
        if (threadIdx.x < o) sh[threadIdx.x] += sh[threadIdx.x + o];
        __syncthreads();
    }
    if (threadIdx.x == 0) g_bsum[blockIdx.x] = sh[0];
}

__global__ void scan_blocks_kernel() {
    __shared__ int sh[256];
    int tid = threadIdx.x;
    int v = (tid < NBLK) ? g_bsum[tid] : 0;
    sh[tid] = v;
    __syncthreads();
#pragma unroll
    for (int o = 1; o < 256; o <<= 1) {
        int t = (tid >= o) ? sh[tid - o] : 0;
        __syncthreads();
        sh[tid] += t;
        __syncthreads();
    }
    g_boff[tid] = sh[tid] - v;
}

__global__ void apply_kernel() {
    __shared__ int sh[256];
    int tid = threadIdx.x;
    int i = blockIdx.x * 256 + tid;
    int v = (i < N_NODES) ? g_cnt[i] : 0;
    sh[tid] = v;
    __syncthreads();
#pragma unroll
    for (int o = 1; o < 256; o <<= 1) {
        int t = (tid >= o) ? sh[tid - o] : 0;
        __syncthreads();
        sh[tid] += t;
        __syncthreads();
    }
    if (i < N_NODES) {
        int excl = sh[tid] - v + g_boff[blockIdx.x];
        g_rowstart[i] = excl;
        g_cursor[i]   = excl;
    }
}

__global__ void fill_kernel(const int* __restrict__ src, const int* __restrict__ dst) {
    int e = blockIdx.x * blockDim.x + threadIdx.x;
    if (e < E_EDGES) {
        int s = src[e], d = dst[e];
        int pos = atomicAdd(&g_cursor[d], 1);
        g_csr_src[pos] = s;
        g_csr_w[pos]   = -g_dis[s] * g_dis[d];
    }
}

// ---------------------------------------------------------------------------
// Gather (hi-only input AND hi-only output)
// ---------------------------------------------------------------------------
__global__ __launch_bounds__(256)
void gather_kernel(const u16* __restrict__ hi, u16* __restrict__ outhi)
{
    int node = (blockIdx.x * blockDim.x + threadIdx.x) >> 5;
    int lane = threadIdx.x & 31;
    if (node >= N_NODES) return;

    float a[8] = {0.f, 0.f, 0.f, 0.f, 0.f, 0.f, 0.f, 0.f};

    int p   = g_rowstart[node];
    int end = p + g_cnt[node];

#pragma unroll 1
    for (; p + 3 < end; p += 4) {
        int   s0 = __ldg(&g_csr_src[p]);
        int   s1 = __ldg(&g_csr_src[p + 1]);
        int   s2 = __ldg(&g_csr_src[p + 2]);
        int   s3 = __ldg(&g_csr_src[p + 3]);
        float w0 = __ldg(&g_csr_w[p]);
        float w1 = __ldg(&g_csr_w[p + 1]);
        float w2 = __ldg(&g_csr_w[p + 2]);
        float w3 = __ldg(&g_csr_w[p + 3]);
        uint4 h0 = *(const uint4*)(hi + (size_t)s0 * 256 + lane * 8);
        uint4 h1 = *(const uint4*)(hi + (size_t)s1 * 256 + lane * 8);
        uint4 h2 = *(const uint4*)(hi + (size_t)s2 * 256 + lane * 8);
        uint4 h3 = *(const uint4*)(hi + (size_t)s3 * 256 + lane * 8);
#pragma unroll
        for (int q = 0; q < 4; q++) {
            float2 f0 = f16x2_to_f2((&h0.x)[q]);
            float2 f1 = f16x2_to_f2((&h1.x)[q]);
            float2 f2 = f16x2_to_f2((&h2.x)[q]);
            float2 f3 = f16x2_to_f2((&h3.x)[q]);
            a[q*2]   = fmaf(w0, f0.x, a[q*2]);
            a[q*2+1] = fmaf(w0, f0.y, a[q*2+1]);
            a[q*2]   = fmaf(w1, f1.x, a[q*2]);
            a[q*2+1] = fmaf(w1, f1.y, a[q*2+1]);
            a[q*2]   = fmaf(w2, f2.x, a[q*2]);
            a[q*2+1] = fmaf(w2, f2.y, a[q*2+1]);
            a[q*2]   = fmaf(w3, f3.x, a[q*2]);
            a[q*2+1] = fmaf(w3, f3.y, a[q*2+1]);
        }
    }
#pragma unroll 1
    for (; p < end; ++p) {
        int   s0 = __ldg(&g_csr_src[p]);
        float w0 = __ldg(&g_csr_w[p]);
        uint4 h0 = *(const uint4*)(hi + (size_t)s0 * 256 + lane * 8);
#pragma unroll
        for (int q = 0; q < 4; q++) {
            float2 f0 = f16x2_to_f2((&h0.x)[q]);
            a[q*2]   = fmaf(w0, f0.x, a[q*2]);
            a[q*2+1] = fmaf(w0, f0.y, a[q*2+1]);
        }
    }

    uint4 hh;
#pragma unroll
    for (int q = 0; q < 4; q++)
        (&hh.x)[q] = pack_f16x2(a[q*2], a[q*2+1]);
    __stcs((uint4*)(outhi + (size_t)node * 256 + lane * 8), hh);
}

// out[i] = b4[i&1]
__global__ void init_out_kernel(float* __restrict__ out,
                                const float* __restrict__ b4)
{
    int i = blockIdx.x * blockDim.x + threadIdx.x;
    if (i < N_NODES * 2) out[i] = __ldg(b4 + (i & 1));
}

// ---------------------------------------------------------------------------
// Launch sequence (single stream — capture-safe)
// ---------------------------------------------------------------------------
extern "C" void kernel_launch(void* const* d_in, const int* in_sizes, int n_in,
                              void* d_out, int out_size)
{
    const float* x    = (const float*)d_in[0];
    const int*   ei   = (const int*)  d_in[1];
    const float* W1   = (const float*)d_in[2];
    const float* b1   = (const float*)d_in[3];
    const float* W2   = (const float*)d_in[4];
    const float* b2   = (const float*)d_in[5];
    const float* W3   = (const float*)d_in[6];
    const float* b3   = (const float*)d_in[7];
    const float* W4   = (const float*)d_in[8];
    const float* b4   = (const float*)d_in[9];
    const float* T10  = (const float*)d_in[10];
    const float* T11  = (const float*)d_in[11];
    const float* cb1  = (const float*)d_in[12];
    const float* T20  = (const float*)d_in[13];
    const float* T21  = (const float*)d_in[14];
    const float* cb2  = (const float*)d_in[15];
    float* out = (float*)d_out;

    const int* src = ei;
    const int* dst = ei + E_EDGES;

    u16 *xhi, *xlo, *h1hi, *h2hi, *h2lo, *aghi;
    u16 *o1hi, *o2hi, *whi, *wlo;
    u16 *wc1hi, *wc1lo, *wc2hi, *wc2lo;
    cudaGetSymbolAddress((void**)&xhi, g_xhi);
    cudaGetSymbolAddress((void**)&xlo, g_xlo);
    cudaGetSymbolAddress((void**)&h1hi, g_h1hi);
    cudaGetSymbolAddress((void**)&h2hi, g_h2hi);
    cudaGetSymbolAddress((void**)&h2lo, g_h2lo);
    cudaGetSymbolAddress((void**)&aghi, g_aghi);
    cudaGetSymbolAddress((void**)&o1hi, g_o1hi);
    cudaGetSymbolAddress((void**)&o2hi, g_o2hi);
    cudaGetSymbolAddress((void**)&whi, g_whi);
    cudaGetSymbolAddress((void**)&wlo, g_wlo);
    cudaGetSymbolAddress((void**)&wc1hi, g_wc1hi);
    cudaGetSymbolAddress((void**)&wc1lo, g_wc1lo);
    cudaGetSymbolAddress((void**)&wc2hi, g_wc2hi);
    cudaGetSymbolAddress((void**)&wc2lo, g_wc2lo);

    const int SMEMSZ = 2 * STG;   // 61440

    cudaFuncSetAttribute(gemm_mma_kernel<8,  3, 3, true,  0, false>,
                         cudaFuncAttributeMaxDynamicSharedMemorySize, SMEMSZ);
    cudaFuncSetAttribute(gemm_mma_kernel<8,  2, 3, true,  0, true>,
                         cudaFuncAttributeMaxDynamicSharedMemorySize, SMEMSZ);
    cudaFuncSetAttribute(gemm_mma_kernel<16, 3, 1, false, 0, false>,
                         cudaFuncAttributeMaxDynamicSharedMemorySize, SMEMSZ);
    cudaFuncSetAttribute(gemm_mma_kernel<16, 2, 1, false, 0, false>,
                         cudaFuncAttributeMaxDynamicSharedMemorySize, SMEMSZ);
    cudaFuncSetAttribute(gemm_mma_kernel<8,  2, 3, true,  1, false>,
                         cudaFuncAttributeMaxDynamicSharedMemorySize, SMEMSZ);

    dim3 ggrid(MPAD / BM, 4);    // (391, 4)
    const int gthr = (N_NODES * 32 + 255) / 256;
    const int wblk = (WSZ / 4 + 255) / 256;

    // --- input/weight splits + MLP GEMMs ---
    split_kernel<<<(N_NODES * HDIM / 4 + 255) / 256, 256>>>(x, xhi, xlo,
                                                            N_NODES * HDIM / 4);
    split_all_w_kernel<<<dim3(wblk, 7), 256>>>(W1, W2, W3, T10, T11, T20, T21);
    // h1 = relu(x@W1+b1): exact 3-pass; hi-only output
    gemm_mma_kernel<8, 3, 3, true, 0, false><<<ggrid, 256, SMEMSZ>>>(
        xhi, xlo, nullptr, whi + 0 * WSZ, wlo + 0 * WSZ, b1,
        h1hi, nullptr, nullptr, nullptr);
    // h2 = relu(h1@W2+b2): 2-pass on A (h1 hi only); exact hi/lo output
    gemm_mma_kernel<8, 2, 3, true, 0, true><<<ggrid, 256, SMEMSZ>>>(
        h1hi, nullptr, nullptr, whi + 1 * WSZ, wlo + 1 * WSZ, b2,
        h2hi, h2lo, nullptr, nullptr);

    // --- CSR build ---
    zero_cnt_kernel<<<(N_NODES + 255) / 256, 256>>>();
    hist_kernel<<<(E_EDGES + 255) / 256, 256>>>(src, dst);
    partial_dis_kernel<<<NBLK, 256>>>();
    scan_blocks_kernel<<<1, 256>>>();
    apply_kernel<<<NBLK, 256>>>();
    fill_kernel<<<(E_EDGES + 255) / 256, 256>>>(src, dst);

    // --- conv 1: agg = S h2 (hi-only) ; out1 (hi only) ---
    gather_kernel<<<gthr, 256>>>(h2hi, aghi);
    gemm_mma_kernel<16, 3, 1, false, 0, false><<<ggrid, 256, SMEMSZ>>>(
        h2hi, h2lo, aghi, wc1hi, wc1lo, cb1,
        o1hi, nullptr, nullptr, nullptr);

    // --- conv 2: agg = S out1 (hi-only) ; out2 (hi only); base 2-pass ---
    gather_kernel<<<gthr, 256>>>(o1hi, aghi);
    gemm_mma_kernel<16, 2, 1, false, 0, false><<<ggrid, 256, SMEMSZ>>>(
        o1hi, nullptr, aghi, wc2hi, wc2lo, cb2,
        o2hi, nullptr, nullptr, nullptr);

    // --- fused: out = relu(out2@W3^T + b3) @ W4^T + b4 (2-pass A: hi only) ---
    init_out_kernel<<<(N_NODES * 2 + 255) / 256, 256>>>(out, b4);
    gemm_mma_kernel<8, 2, 3, true, 1, false><<<ggrid, 256, SMEMSZ>>>(
        o2hi, nullptr, nullptr, whi + 2 * WSZ, wlo + 2 * WSZ, b3,
        nullptr, nullptr, W4, out);
}